// round 1
// baseline (speedup 1.0000x reference)
#include <cuda_runtime.h>
#include <math.h>

// Problem dims
#define B_   8
#define S_   2048
#define D_   768
#define H_   3072
#define NT_  (B_ * S_)         // 16384 tokens
#define EPS_ 1e-5f

// ---------------------------------------------------------------------------
// Scratch (device globals — no allocation allowed in kernel_launch)
// ---------------------------------------------------------------------------
__device__ float g_h [NT_ * D_];                 // LN1 output
__device__ float g_q [NT_ * D_];
__device__ float g_k [NT_ * D_];
__device__ float g_v [NT_ * D_];
__device__ float g_sc[(size_t)B_ * S_ * S_];     // attention scores / probs
__device__ float g_y [NT_ * D_];                 // attn @ V
__device__ float g_x1[NT_ * D_];                 // x + attn_out
__device__ float g_h2[NT_ * D_];                 // LN2 output
__device__ float g_m [NT_ * H_];                 // GELU(fc) activations

// ---------------------------------------------------------------------------
// LayerNorm: one block (256 threads) per row of 768
// ---------------------------------------------------------------------------
__global__ void __launch_bounds__(256)
ln_kernel(const float* __restrict__ x, const float* __restrict__ g,
          const float* __restrict__ b, float* __restrict__ out)
{
    long row = blockIdx.x;
    const float* xr = x + row * D_;
    float* orow = out + row * D_;
    int t = threadIdx.x;

    float vals[3];
    float s = 0.f, s2 = 0.f;
#pragma unroll
    for (int i = 0; i < 3; i++) {
        float v = xr[t + i * 256];
        vals[i] = v;
        s += v;
        s2 += v * v;
    }
#pragma unroll
    for (int o = 16; o > 0; o >>= 1) {
        s  += __shfl_xor_sync(0xffffffffu, s,  o);
        s2 += __shfl_xor_sync(0xffffffffu, s2, o);
    }
    __shared__ float sm[8], sm2[8], stat[2];
    int w = t >> 5, l = t & 31;
    if (l == 0) { sm[w] = s; sm2[w] = s2; }
    __syncthreads();
    if (t == 0) {
        float a = 0.f, c = 0.f;
#pragma unroll
        for (int i = 0; i < 8; i++) { a += sm[i]; c += sm2[i]; }
        float mu  = a / (float)D_;
        float var = c / (float)D_ - mu * mu;
        stat[0] = mu;
        stat[1] = rsqrtf(var + EPS_);
    }
    __syncthreads();
    float mu = stat[0], rstd = stat[1];
#pragma unroll
    for (int i = 0; i < 3; i++) {
        int idx = t + i * 256;
        orow[idx] = (vals[i] - mu) * rstd * g[idx] + b[idx];
    }
}

// ---------------------------------------------------------------------------
// Row softmax over 2048 keys, with pre-scale (1/sqrt(D)) applied
// ---------------------------------------------------------------------------
__global__ void __launch_bounds__(256)
softmax_kernel(float* __restrict__ sc, float scale)
{
    long row = blockIdx.x;
    float* p = sc + row * (long)S_;
    int t = threadIdx.x;

    float vals[8];
    float mx = -1e30f;
#pragma unroll
    for (int i = 0; i < 8; i++) {
        float v = p[t + i * 256];
        vals[i] = v;
        mx = fmaxf(mx, v);
    }
#pragma unroll
    for (int o = 16; o > 0; o >>= 1)
        mx = fmaxf(mx, __shfl_xor_sync(0xffffffffu, mx, o));
    __shared__ float sm[8], stat[1];
    int w = t >> 5, l = t & 31;
    if (l == 0) sm[w] = mx;
    __syncthreads();
    if (t == 0) {
        float m = sm[0];
#pragma unroll
        for (int i = 1; i < 8; i++) m = fmaxf(m, sm[i]);
        stat[0] = m;
    }
    __syncthreads();
    float rowmax = stat[0];

    float sum = 0.f;
#pragma unroll
    for (int i = 0; i < 8; i++) {
        float e = __expf((vals[i] - rowmax) * scale);
        vals[i] = e;
        sum += e;
    }
#pragma unroll
    for (int o = 16; o > 0; o >>= 1)
        sum += __shfl_xor_sync(0xffffffffu, sum, o);
    if (l == 0) sm[w] = sum;
    __syncthreads();
    if (t == 0) {
        float a = 0.f;
#pragma unroll
        for (int i = 0; i < 8; i++) a += sm[i];
        stat[0] = 1.f / a;
    }
    __syncthreads();
    float inv = stat[0];
#pragma unroll
    for (int i = 0; i < 8; i++)
        p[t + i * 256] = vals[i] * inv;
}

// ---------------------------------------------------------------------------
// Generic tiled SGEMM:  C = A * B (+ bias) (+ GELU) (+ residual)
//   BT=false: B is [K,N] row-major (NN).  BT=true: B is [N,K] row-major (NT).
//   Batched via blockIdx.z with element strides sA/sB/sC (C and res share sC).
//   BM=BN=128, BK=8, 256 threads, 8x8 per-thread tile.
// ---------------------------------------------------------------------------
template <bool BT, int GELU>
__global__ void __launch_bounds__(256)
gemm_kernel(const float* __restrict__ A, const float* __restrict__ Bm,
            const float* __restrict__ bias, const float* __restrict__ res,
            float* __restrict__ C, int M, int N, int K,
            long sA, long sB, long sC)
{
    constexpr int BM = 128, BN = 128, BK = 8;
    __shared__ float As[BK][BM];
    __shared__ float Bs[BK][BN];

    int bx = blockIdx.x, by = blockIdx.y, bz = blockIdx.z;

    A += (long)bz * sA + (long)by * BM * K;
    if (BT) Bm += (long)bz * sB + (long)bx * BN * K;
    else    Bm += (long)bz * sB + bx * BN;
    C += (long)bz * sC + (long)by * BM * N + bx * BN;
    if (res) res += (long)bz * sC + (long)by * BM * N + bx * BN;

    int tid = threadIdx.x;
    int tx = tid & 15, ty = tid >> 4;

    int arow = tid >> 1;           // 0..127
    int acol = (tid & 1) * 4;      // 0 or 4
    int bk_nn = tid >> 5;          // 0..7   (NN B load)
    int bn_nn = (tid & 31) * 4;    // 0..124

    float acc[8][8];
#pragma unroll
    for (int i = 0; i < 8; i++)
#pragma unroll
        for (int j = 0; j < 8; j++) acc[i][j] = 0.f;

    for (int k0 = 0; k0 < K; k0 += BK) {
        float4 av = *(const float4*)(A + (long)arow * K + k0 + acol);
        As[acol + 0][arow] = av.x;
        As[acol + 1][arow] = av.y;
        As[acol + 2][arow] = av.z;
        As[acol + 3][arow] = av.w;
        if (BT) {
            float4 bv = *(const float4*)(Bm + (long)arow * K + k0 + acol);
            Bs[acol + 0][arow] = bv.x;
            Bs[acol + 1][arow] = bv.y;
            Bs[acol + 2][arow] = bv.z;
            Bs[acol + 3][arow] = bv.w;
        } else {
            float4 bv = *(const float4*)(Bm + (long)(k0 + bk_nn) * N + bn_nn);
            *(float4*)&Bs[bk_nn][bn_nn] = bv;
        }
        __syncthreads();
#pragma unroll
        for (int kk = 0; kk < BK; kk++) {
            float a[8], b[8];
#pragma unroll
            for (int i = 0; i < 8; i++) a[i] = As[kk][ty * 8 + i];
#pragma unroll
            for (int j = 0; j < 8; j++) b[j] = Bs[kk][tx * 8 + j];
#pragma unroll
            for (int i = 0; i < 8; i++)
#pragma unroll
                for (int j = 0; j < 8; j++)
                    acc[i][j] += a[i] * b[j];
        }
        __syncthreads();
    }

#pragma unroll
    for (int i = 0; i < 8; i++) {
        int r = ty * 8 + i;
#pragma unroll
        for (int j = 0; j < 8; j++) {
            int c = tx * 8 + j;
            float v = acc[i][j];
            if (bias) v += bias[bx * BN + c];
            if (GELU) v = 0.5f * v * (1.f + erff(v * 0.70710678118654752f));
            if (res)  v += res[(long)r * N + c];
            C[(long)r * N + c] = v;
        }
    }
}

// ---------------------------------------------------------------------------
// Launch: full transformer block
// ---------------------------------------------------------------------------
extern "C" void kernel_launch(void* const* d_in, const int* in_sizes, int n_in,
                              void* d_out, int out_size)
{
    const float* x     = (const float*)d_in[0];
    const float* ln1g  = (const float*)d_in[1];
    const float* ln1b  = (const float*)d_in[2];
    const float* ln2g  = (const float*)d_in[3];
    const float* ln2b  = (const float*)d_in[4];
    const float* Wq    = (const float*)d_in[5];
    const float* bq    = (const float*)d_in[6];
    const float* Wk    = (const float*)d_in[7];
    const float* bk    = (const float*)d_in[8];
    const float* Wv    = (const float*)d_in[9];
    const float* bv    = (const float*)d_in[10];
    const float* Wo    = (const float*)d_in[11];
    const float* bo    = (const float*)d_in[12];
    const float* Wfc   = (const float*)d_in[13];
    const float* bfc   = (const float*)d_in[14];
    const float* Wproj = (const float*)d_in[15];
    const float* bproj = (const float*)d_in[16];
    float* out = (float*)d_out;

    float *h, *q, *k, *v, *sc, *y, *x1, *h2, *m;
    cudaGetSymbolAddress((void**)&h,  g_h);
    cudaGetSymbolAddress((void**)&q,  g_q);
    cudaGetSymbolAddress((void**)&k,  g_k);
    cudaGetSymbolAddress((void**)&v,  g_v);
    cudaGetSymbolAddress((void**)&sc, g_sc);
    cudaGetSymbolAddress((void**)&y,  g_y);
    cudaGetSymbolAddress((void**)&x1, g_x1);
    cudaGetSymbolAddress((void**)&h2, g_h2);
    cudaGetSymbolAddress((void**)&m,  g_m);

    const long sQ = (long)S_ * D_;   // per-batch stride of q/k/v/y
    const long sS = (long)S_ * S_;   // per-batch stride of scores

    // 1) LN1
    ln_kernel<<<NT_, 256>>>(x, ln1g, ln1b, h);

    // 2) QKV projections [16384,768] x [768,768]
    dim3 gD(D_ / 128, NT_ / 128, 1);
    gemm_kernel<false, 0><<<gD, 256>>>(h, Wq, bq, nullptr, q, NT_, D_, D_, 0, 0, 0);
    gemm_kernel<false, 0><<<gD, 256>>>(h, Wk, bk, nullptr, k, NT_, D_, D_, 0, 0, 0);
    gemm_kernel<false, 0><<<gD, 256>>>(h, Wv, bv, nullptr, v, NT_, D_, D_, 0, 0, 0);

    // 3) scores = q @ k^T (batched NT), scale applied in softmax
    dim3 gS(S_ / 128, S_ / 128, B_);
    gemm_kernel<true, 0><<<gS, 256>>>(q, k, nullptr, nullptr, sc, S_, S_, D_, sQ, sQ, sS);

    // 4) softmax over keys with 1/sqrt(D)
    softmax_kernel<<<B_ * S_, 256>>>(sc, 1.0f / sqrtf((float)D_));

    // 5) y = attn @ v (batched NN)
    dim3 gA(D_ / 128, S_ / 128, B_);
    gemm_kernel<false, 0><<<gA, 256>>>(sc, v, nullptr, nullptr, y, S_, D_, S_, sS, sQ, sQ);

    // 6) x1 = x + y @ Wo + bo
    gemm_kernel<false, 0><<<gD, 256>>>(y, Wo, bo, x, x1, NT_, D_, D_, 0, 0, 0);

    // 7) LN2
    ln_kernel<<<NT_, 256>>>(x1, ln2g, ln2b, h2);

    // 8) m = GELU(h2 @ Wfc + bfc)
    dim3 gH(H_ / 128, NT_ / 128, 1);
    gemm_kernel<false, 1><<<gH, 256>>>(h2, Wfc, bfc, nullptr, m, NT_, H_, D_, 0, 0, 0);

    // 9) out = x1 + m @ Wproj + bproj
    gemm_kernel<false, 0><<<gD, 256>>>(m, Wproj, bproj, x1, out, NT_, D_, H_, 0, 0, 0);
}

// round 4
// speedup vs baseline: 2.4043x; 2.4043x over previous
#include <cuda_runtime.h>
#include <cuda_bf16.h>
#include <math.h>
#include <stdint.h>

// Problem dims
#define B_   8
#define S_   2048
#define D_   768
#define H_   3072
#define NT_  (B_ * S_)         // 16384 tokens
#define EPS_ 1e-5f

// ---------------------------------------------------------------------------
// Scratch (device globals — no allocation allowed)
// ---------------------------------------------------------------------------
__device__ unsigned short g_h_hi [NT_ * D_],  g_h_lo [NT_ * D_];
__device__ unsigned short g_q_hi [NT_ * D_],  g_q_lo [NT_ * D_];
__device__ unsigned short g_k_hi [NT_ * D_],  g_k_lo [NT_ * D_];
__device__ unsigned short g_vt_hi[NT_ * D_],  g_vt_lo[NT_ * D_];   // [D, B*S]
__device__ float          g_sc[(size_t)B_ * S_ * S_];
__device__ unsigned short g_p_hi[(size_t)B_ * S_ * S_], g_p_lo[(size_t)B_ * S_ * S_];
__device__ unsigned short g_y_hi [NT_ * D_],  g_y_lo [NT_ * D_];
__device__ float          g_x1[NT_ * D_];
__device__ unsigned short g_h2_hi[NT_ * D_],  g_h2_lo[NT_ * D_];
__device__ unsigned short g_m_hi [(size_t)NT_ * H_], g_m_lo [(size_t)NT_ * H_];
// transposed-split weights  [N,K]
__device__ unsigned short g_wqt_hi[D_ * D_], g_wqt_lo[D_ * D_];
__device__ unsigned short g_wkt_hi[D_ * D_], g_wkt_lo[D_ * D_];
__device__ unsigned short g_wvt_hi[D_ * D_], g_wvt_lo[D_ * D_];
__device__ unsigned short g_wot_hi[D_ * D_], g_wot_lo[D_ * D_];
__device__ unsigned short g_wfct_hi[H_ * D_], g_wfct_lo[H_ * D_];
__device__ unsigned short g_wprojt_hi[D_ * H_], g_wprojt_lo[D_ * H_];

// ---------------------------------------------------------------------------
// PTX helpers (baseline ISA only: cp.async / ldmatrix / mma.sync — compute_100 OK)
// ---------------------------------------------------------------------------
__device__ __forceinline__ void cp16(uint32_t dst, const void* src) {
    asm volatile("cp.async.cg.shared.global [%0], [%1], 16;" :: "r"(dst), "l"(src));
}
__device__ __forceinline__ void cp_commit() { asm volatile("cp.async.commit_group;" ::: "memory"); }
__device__ __forceinline__ void cp_wait0()  { asm volatile("cp.async.wait_group 0;"  ::: "memory"); }
__device__ __forceinline__ void cp_wait1()  { asm volatile("cp.async.wait_group 1;"  ::: "memory"); }

__device__ __forceinline__ void ldm4(uint32_t (&r)[4], uint32_t addr) {
    asm volatile("ldmatrix.sync.aligned.m8n8.x4.shared.b16 {%0,%1,%2,%3}, [%4];"
                 : "=r"(r[0]), "=r"(r[1]), "=r"(r[2]), "=r"(r[3]) : "r"(addr));
}
__device__ __forceinline__ void ldm2(uint32_t (&r)[2], uint32_t addr) {
    asm volatile("ldmatrix.sync.aligned.m8n8.x2.shared.b16 {%0,%1}, [%2];"
                 : "=r"(r[0]), "=r"(r[1]) : "r"(addr));
}
__device__ __forceinline__ void mma16816(float (&c)[4], const uint32_t (&a)[4],
                                         const uint32_t (&b)[2]) {
    asm volatile("mma.sync.aligned.m16n8k16.row.col.f32.bf16.bf16.f32 "
                 "{%0,%1,%2,%3}, {%4,%5,%6,%7}, {%8,%9}, {%0,%1,%2,%3};"
                 : "+f"(c[0]), "+f"(c[1]), "+f"(c[2]), "+f"(c[3])
                 : "r"(a[0]), "r"(a[1]), "r"(a[2]), "r"(a[3]), "r"(b[0]), "r"(b[1]));
}

__device__ __forceinline__ void split2(float v, __nv_bfloat16& h, __nv_bfloat16& l) {
    h = __float2bfloat16(v);
    l = __float2bfloat16(v - __bfloat162float(h));
}
__device__ __forceinline__ uint32_t pack2(__nv_bfloat16 a, __nv_bfloat16 b) {
    return ((uint32_t)__bfloat16_as_ushort(b) << 16) | __bfloat16_as_ushort(a);
}

// ---------------------------------------------------------------------------
// Tensor-core GEMM: C[M,N] = sum_k A[M,K]*B[N,K]  (A,B pre-split bf16 hi/lo)
// tile 128x128, BK=32, 2-stage cp.async, mma.m16n8k16, 3-pass hi/lo
// SMEM: pitch 80B per 32-elem row (stride 5*16B -> ldmatrix conflict-free)
// BIASM: 0 none, 1 col bias, 2 row bias
// ---------------------------------------------------------------------------
#define PITCH  80
#define ATILE  (128 * PITCH)                 // 10240 B per operand-half tile
#define STAGEB (4 * ATILE)                   // AH AL BH BL
#define SMEM_GEMM (2 * STAGEB)               // 81920 B

__device__ __forceinline__ void load_tile(uint32_t dst, const __nv_bfloat16* g,
                                          long ld, int k0) {
    int tid = threadIdx.x;
#pragma unroll
    for (int i = 0; i < 2; i++) {
        int idx = tid + i * 256;             // 0..511
        int row = idx >> 2, ch = idx & 3;
        cp16(dst + row * PITCH + ch * 16, g + (long)row * ld + k0 + ch * 8);
    }
}

template <int BIASM, int DOGELU, int DORES, int SPLIT>
__global__ void __launch_bounds__(256, 1)
gemm_mma(const __nv_bfloat16* __restrict__ Ahi, const __nv_bfloat16* __restrict__ Alo,
         long ldA, long sA,
         const __nv_bfloat16* __restrict__ Bhi, const __nv_bfloat16* __restrict__ Blo,
         long ldB, long sB,
         float* __restrict__ Cf, __nv_bfloat16* __restrict__ Chi, __nv_bfloat16* __restrict__ Clo,
         long ldC, long sC,
         const float* __restrict__ bias, const float* __restrict__ res, int K)
{
    extern __shared__ char smem[];
    uint32_t sb = (uint32_t)__cvta_generic_to_shared(smem);
    int tid = threadIdx.x, lane = tid & 31, wid = tid >> 5;
    int wm = wid & 3, wn = wid >> 2;                  // 4 x 2 warp grid
    long row0 = (long)blockIdx.y * 128, col0 = (long)blockIdx.x * 128;
    int bz = blockIdx.z;

    const __nv_bfloat16* gAh = Ahi + (long)bz * sA + row0 * ldA;
    const __nv_bfloat16* gAl = Alo + (long)bz * sA + row0 * ldA;
    const __nv_bfloat16* gBh = Bhi + (long)bz * sB + col0 * ldB;
    const __nv_bfloat16* gBl = Blo + (long)bz * sB + col0 * ldB;

    float acc[2][8][4];
#pragma unroll
    for (int t = 0; t < 2; t++)
#pragma unroll
        for (int j = 0; j < 8; j++)
#pragma unroll
            for (int e = 0; e < 4; e++) acc[t][j][e] = 0.f;

    // ldmatrix lane addressing (stage-invariant parts)
    int a_row = wm * 32 + (lane & 15);                // + t*16
    int a_ch  = (lane >> 4) * 8;                      // + kk   (element col)
    int b_row = wn * 64 + (lane & 7);                 // + j*8
    int b_ch  = ((lane >> 3) & 1) * 8;                // + kk

    // prologue: stage 0
    load_tile(sb + 0 * ATILE, gAh, ldA, 0);
    load_tile(sb + 1 * ATILE, gAl, ldA, 0);
    load_tile(sb + 2 * ATILE, gBh, ldB, 0);
    load_tile(sb + 3 * ATILE, gBl, ldB, 0);
    cp_commit();

    int NC = K >> 5;
    for (int c = 0; c < NC; c++) {
        if (c + 1 < NC) {
            uint32_t so = sb + ((c + 1) & 1) * STAGEB;
            int k0 = (c + 1) * 32;
            load_tile(so + 0 * ATILE, gAh, ldA, k0);
            load_tile(so + 1 * ATILE, gAl, ldA, k0);
            load_tile(so + 2 * ATILE, gBh, ldB, k0);
            load_tile(so + 3 * ATILE, gBl, ldB, k0);
            cp_commit();
            cp_wait1();
        } else {
            cp_wait0();
        }
        __syncthreads();

        uint32_t s0 = sb + (c & 1) * STAGEB;
#pragma unroll
        for (int kk = 0; kk < 32; kk += 16) {
            uint32_t ah[2][4], al[2][4];
#pragma unroll
            for (int t = 0; t < 2; t++) {
                uint32_t ad = s0 + (a_row + t * 16) * PITCH + (a_ch + kk) * 2;
                ldm4(ah[t], ad);
                ldm4(al[t], ad + ATILE);
            }
            uint32_t bh[8][2], bl[8][2];
#pragma unroll
            for (int j = 0; j < 8; j++) {
                uint32_t bd = s0 + 2 * ATILE + (b_row + j * 8) * PITCH + (b_ch + kk) * 2;
                ldm2(bh[j], bd);
                ldm2(bl[j], bd + ATILE);
            }
#pragma unroll
            for (int t = 0; t < 2; t++)
#pragma unroll
                for (int j = 0; j < 8; j++) {
                    mma16816(acc[t][j], ah[t], bh[j]);
                    mma16816(acc[t][j], ah[t], bl[j]);
                    mma16816(acc[t][j], al[t], bh[j]);
                }
        }
        __syncthreads();
    }

    // epilogue: straight from registers, fused ops
#pragma unroll
    for (int t = 0; t < 2; t++)
#pragma unroll
        for (int j = 0; j < 8; j++) {
#pragma unroll
            for (int half = 0; half < 2; half++) {
                long r  = row0 + wm * 32 + t * 16 + (lane >> 2) + half * 8;
                long cc = col0 + wn * 64 + j * 8 + (lane & 3) * 2;
                float v0 = acc[t][j][half * 2 + 0];
                float v1 = acc[t][j][half * 2 + 1];
                if (BIASM == 1) { v0 += bias[cc]; v1 += bias[cc + 1]; }
                if (BIASM == 2) { float bb = bias[r]; v0 += bb; v1 += bb; }
                if (DOGELU) {
                    v0 = 0.5f * v0 * (1.f + erff(v0 * 0.70710678118654752f));
                    v1 = 0.5f * v1 * (1.f + erff(v1 * 0.70710678118654752f));
                }
                long off = (long)bz * sC + r * ldC + cc;
                if (DORES) { v0 += res[off]; v1 += res[off + 1]; }
                if (SPLIT) {
                    __nv_bfloat16 h0, l0, h1, l1;
                    split2(v0, h0, l0); split2(v1, h1, l1);
                    *reinterpret_cast<uint32_t*>(Chi + off) = pack2(h0, h1);
                    *reinterpret_cast<uint32_t*>(Clo + off) = pack2(l0, l1);
                } else {
                    Cf[off] = v0; Cf[off + 1] = v1;
                }
            }
        }
}

// ---------------------------------------------------------------------------
// Transpose + split:  W[K,N] fp32  ->  out[N,K] bf16 hi/lo
// ---------------------------------------------------------------------------
__global__ void __launch_bounds__(256)
tsplit_kernel(const float* __restrict__ W, __nv_bfloat16* __restrict__ hi,
              __nv_bfloat16* __restrict__ lo, int K, int N)
{
    __shared__ float t[32][33];
    int n0 = blockIdx.x * 32, k0 = blockIdx.y * 32;
    int tx = threadIdx.x & 31, ty = threadIdx.x >> 5;  // 32x8
#pragma unroll
    for (int i = 0; i < 32; i += 8)
        t[ty + i][tx] = W[(long)(k0 + ty + i) * N + n0 + tx];
    __syncthreads();
#pragma unroll
    for (int i = 0; i < 32; i += 8) {
        float v = t[tx][ty + i];
        long o = (long)(n0 + ty + i) * K + k0 + tx;
        __nv_bfloat16 h, l; split2(v, h, l);
        hi[o] = h; lo[o] = l;
    }
}

// ---------------------------------------------------------------------------
// LayerNorm -> split bf16 output
// ---------------------------------------------------------------------------
__global__ void __launch_bounds__(256)
ln_kernel(const float* __restrict__ x, const float* __restrict__ g,
          const float* __restrict__ b, __nv_bfloat16* __restrict__ ohi,
          __nv_bfloat16* __restrict__ olo)
{
    long row = blockIdx.x;
    const float* xr = x + row * D_;
    int t = threadIdx.x;
    float vals[3];
    float s = 0.f, s2 = 0.f;
#pragma unroll
    for (int i = 0; i < 3; i++) {
        float v = xr[t + i * 256];
        vals[i] = v; s += v; s2 += v * v;
    }
#pragma unroll
    for (int o = 16; o > 0; o >>= 1) {
        s  += __shfl_xor_sync(0xffffffffu, s,  o);
        s2 += __shfl_xor_sync(0xffffffffu, s2, o);
    }
    __shared__ float sm[8], sm2[8], stat[2];
    int w = t >> 5, l = t & 31;
    if (l == 0) { sm[w] = s; sm2[w] = s2; }
    __syncthreads();
    if (t == 0) {
        float a = 0.f, c = 0.f;
#pragma unroll
        for (int i = 0; i < 8; i++) { a += sm[i]; c += sm2[i]; }
        float mu = a / (float)D_;
        stat[0] = mu;
        stat[1] = rsqrtf(c / (float)D_ - mu * mu + EPS_);
    }
    __syncthreads();
    float mu = stat[0], rstd = stat[1];
#pragma unroll
    for (int i = 0; i < 3; i++) {
        int idx = t + i * 256;
        float v = (vals[i] - mu) * rstd * g[idx] + b[idx];
        __nv_bfloat16 h, lo2; split2(v, h, lo2);
        ohi[row * D_ + idx] = h; olo[row * D_ + idx] = lo2;
    }
}

// ---------------------------------------------------------------------------
// Softmax (with scale) -> split bf16 probs
// ---------------------------------------------------------------------------
__global__ void __launch_bounds__(256)
softmax_kernel(const float* __restrict__ sc, __nv_bfloat16* __restrict__ phi,
               __nv_bfloat16* __restrict__ plo, float scale)
{
    long row = blockIdx.x;
    const float* p = sc + row * (long)S_;
    int t = threadIdx.x;
    float vals[8];
    float mx = -1e30f;
#pragma unroll
    for (int i = 0; i < 8; i++) {
        float v = p[t + i * 256];
        vals[i] = v; mx = fmaxf(mx, v);
    }
#pragma unroll
    for (int o = 16; o > 0; o >>= 1)
        mx = fmaxf(mx, __shfl_xor_sync(0xffffffffu, mx, o));
    __shared__ float sm[8], stat[1];
    int w = t >> 5, l = t & 31;
    if (l == 0) sm[w] = mx;
    __syncthreads();
    if (t == 0) {
        float m2 = sm[0];
#pragma unroll
        for (int i = 1; i < 8; i++) m2 = fmaxf(m2, sm[i]);
        stat[0] = m2;
    }
    __syncthreads();
    float rowmax = stat[0];
    float sum = 0.f;
#pragma unroll
    for (int i = 0; i < 8; i++) {
        float e = __expf((vals[i] - rowmax) * scale);
        vals[i] = e; sum += e;
    }
#pragma unroll
    for (int o = 16; o > 0; o >>= 1)
        sum += __shfl_xor_sync(0xffffffffu, sum, o);
    if (l == 0) sm[w] = sum;
    __syncthreads();
    if (t == 0) {
        float a = 0.f;
#pragma unroll
        for (int i = 0; i < 8; i++) a += sm[i];
        stat[0] = 1.f / a;
    }
    __syncthreads();
    float inv = stat[0];
#pragma unroll
    for (int i = 0; i < 8; i++) {
        float v = vals[i] * inv;
        __nv_bfloat16 h, lo2; split2(v, h, lo2);
        long o2 = row * (long)S_ + t + i * 256;
        phi[o2] = h; plo[o2] = lo2;
    }
}

// ---------------------------------------------------------------------------
// Launch
// ---------------------------------------------------------------------------
extern "C" void kernel_launch(void* const* d_in, const int* in_sizes, int n_in,
                              void* d_out, int out_size)
{
    const float* x     = (const float*)d_in[0];
    const float* ln1g  = (const float*)d_in[1];
    const float* ln1b  = (const float*)d_in[2];
    const float* ln2g  = (const float*)d_in[3];
    const float* ln2b  = (const float*)d_in[4];
    const float* Wq    = (const float*)d_in[5];
    const float* bq    = (const float*)d_in[6];
    const float* Wk    = (const float*)d_in[7];
    const float* bk    = (const float*)d_in[8];
    const float* Wv    = (const float*)d_in[9];
    const float* bv    = (const float*)d_in[10];
    const float* Wo    = (const float*)d_in[11];
    const float* bo    = (const float*)d_in[12];
    const float* Wfc   = (const float*)d_in[13];
    const float* bfc   = (const float*)d_in[14];
    const float* Wproj = (const float*)d_in[15];
    const float* bproj = (const float*)d_in[16];
    float* out = (float*)d_out;

    auto ga = [](const void* sym) { void* p; cudaGetSymbolAddress(&p, sym); return p; };
    __nv_bfloat16 *h_hi = (__nv_bfloat16*)ga(g_h_hi),   *h_lo = (__nv_bfloat16*)ga(g_h_lo);
    __nv_bfloat16 *q_hi = (__nv_bfloat16*)ga(g_q_hi),   *q_lo = (__nv_bfloat16*)ga(g_q_lo);
    __nv_bfloat16 *k_hi = (__nv_bfloat16*)ga(g_k_hi),   *k_lo = (__nv_bfloat16*)ga(g_k_lo);
    __nv_bfloat16 *vt_hi= (__nv_bfloat16*)ga(g_vt_hi),  *vt_lo= (__nv_bfloat16*)ga(g_vt_lo);
    float         *sc   = (float*)ga(g_sc);
    __nv_bfloat16 *p_hi = (__nv_bfloat16*)ga(g_p_hi),   *p_lo = (__nv_bfloat16*)ga(g_p_lo);
    __nv_bfloat16 *y_hi = (__nv_bfloat16*)ga(g_y_hi),   *y_lo = (__nv_bfloat16*)ga(g_y_lo);
    float         *x1   = (float*)ga(g_x1);
    __nv_bfloat16 *h2_hi= (__nv_bfloat16*)ga(g_h2_hi),  *h2_lo= (__nv_bfloat16*)ga(g_h2_lo);
    __nv_bfloat16 *m_hi = (__nv_bfloat16*)ga(g_m_hi),   *m_lo = (__nv_bfloat16*)ga(g_m_lo);
    __nv_bfloat16 *wqt_hi = (__nv_bfloat16*)ga(g_wqt_hi), *wqt_lo = (__nv_bfloat16*)ga(g_wqt_lo);
    __nv_bfloat16 *wkt_hi = (__nv_bfloat16*)ga(g_wkt_hi), *wkt_lo = (__nv_bfloat16*)ga(g_wkt_lo);
    __nv_bfloat16 *wvt_hi = (__nv_bfloat16*)ga(g_wvt_hi), *wvt_lo = (__nv_bfloat16*)ga(g_wvt_lo);
    __nv_bfloat16 *wot_hi = (__nv_bfloat16*)ga(g_wot_hi), *wot_lo = (__nv_bfloat16*)ga(g_wot_lo);
    __nv_bfloat16 *wfct_hi = (__nv_bfloat16*)ga(g_wfct_hi), *wfct_lo = (__nv_bfloat16*)ga(g_wfct_lo);
    __nv_bfloat16 *wpt_hi = (__nv_bfloat16*)ga(g_wprojt_hi), *wpt_lo = (__nv_bfloat16*)ga(g_wprojt_lo);

    cudaFuncSetAttribute(gemm_mma<1,0,0,1>, cudaFuncAttributeMaxDynamicSharedMemorySize, SMEM_GEMM);
    cudaFuncSetAttribute(gemm_mma<2,0,0,1>, cudaFuncAttributeMaxDynamicSharedMemorySize, SMEM_GEMM);
    cudaFuncSetAttribute(gemm_mma<0,0,0,0>, cudaFuncAttributeMaxDynamicSharedMemorySize, SMEM_GEMM);
    cudaFuncSetAttribute(gemm_mma<0,0,0,1>, cudaFuncAttributeMaxDynamicSharedMemorySize, SMEM_GEMM);
    cudaFuncSetAttribute(gemm_mma<1,0,1,0>, cudaFuncAttributeMaxDynamicSharedMemorySize, SMEM_GEMM);
    cudaFuncSetAttribute(gemm_mma<1,1,0,1>, cudaFuncAttributeMaxDynamicSharedMemorySize, SMEM_GEMM);

    const long sQ = (long)S_ * D_;
    const long sS = (long)S_ * S_;

    // weight transpose+split
    tsplit_kernel<<<dim3(24, 24), 256>>>(Wq, wqt_hi, wqt_lo, D_, D_);
    tsplit_kernel<<<dim3(24, 24), 256>>>(Wk, wkt_hi, wkt_lo, D_, D_);
    tsplit_kernel<<<dim3(24, 24), 256>>>(Wv, wvt_hi, wvt_lo, D_, D_);
    tsplit_kernel<<<dim3(24, 24), 256>>>(Wo, wot_hi, wot_lo, D_, D_);
    tsplit_kernel<<<dim3(96, 24), 256>>>(Wfc, wfct_hi, wfct_lo, D_, H_);   // -> [3072,768]
    tsplit_kernel<<<dim3(24, 96), 256>>>(Wproj, wpt_hi, wpt_lo, H_, D_);   // -> [768,3072]

    // LN1
    ln_kernel<<<NT_, 256>>>(x, ln1g, ln1b, h_hi, h_lo);

    // q, k
    gemm_mma<1,0,0,1><<<dim3(6, 128, 1), 256, SMEM_GEMM>>>(
        h_hi, h_lo, D_, 0, wqt_hi, wqt_lo, D_, 0,
        nullptr, q_hi, q_lo, D_, 0, bq, nullptr, D_);
    gemm_mma<1,0,0,1><<<dim3(6, 128, 1), 256, SMEM_GEMM>>>(
        h_hi, h_lo, D_, 0, wkt_hi, wkt_lo, D_, 0,
        nullptr, k_hi, k_lo, D_, 0, bk, nullptr, D_);

    // v^T = Wv^T . h^T   ([768,16384], row bias)
    gemm_mma<2,0,0,1><<<dim3(128, 6, 1), 256, SMEM_GEMM>>>(
        wvt_hi, wvt_lo, D_, 0, h_hi, h_lo, D_, 0,
        nullptr, vt_hi, vt_lo, NT_, 0, bv, nullptr, D_);

    // scores = q . k^T  (batched, fp32 out)
    gemm_mma<0,0,0,0><<<dim3(16, 16, B_), 256, SMEM_GEMM>>>(
        q_hi, q_lo, D_, sQ, k_hi, k_lo, D_, sQ,
        sc, nullptr, nullptr, S_, sS, nullptr, nullptr, D_);

    // softmax (scale inside) -> split probs
    softmax_kernel<<<B_ * S_, 256>>>(sc, p_hi, p_lo, 1.0f / sqrtf((float)D_));

    // y = probs . v   (B rows = vt rows (d), cols = tokens; batch offset bz*S_)
    gemm_mma<0,0,0,1><<<dim3(6, 16, B_), 256, SMEM_GEMM>>>(
        p_hi, p_lo, S_, sS, vt_hi, vt_lo, NT_, S_,
        nullptr, y_hi, y_lo, D_, sQ, nullptr, nullptr, S_);

    // x1 = x + y . Wo + bo
    gemm_mma<1,0,1,0><<<dim3(6, 128, 1), 256, SMEM_GEMM>>>(
        y_hi, y_lo, D_, 0, wot_hi, wot_lo, D_, 0,
        x1, nullptr, nullptr, D_, 0, bo, x, D_);

    // LN2
    ln_kernel<<<NT_, 256>>>(x1, ln2g, ln2b, h2_hi, h2_lo);

    // m = GELU(h2 . Wfc + bfc)
    gemm_mma<1,1,0,1><<<dim3(24, 128, 1), 256, SMEM_GEMM>>>(
        h2_hi, h2_lo, D_, 0, wfct_hi, wfct_lo, D_, 0,
        nullptr, m_hi, m_lo, H_, 0, bfc, nullptr, D_);

    // out = x1 + m . Wproj + bproj
    gemm_mma<1,0,1,0><<<dim3(6, 128, 1), 256, SMEM_GEMM>>>(
        m_hi, m_lo, H_, 0, wpt_hi, wpt_lo, H_, 0,
        out, nullptr, nullptr, D_, 0, bproj, x1, H_);
}

// round 5
// speedup vs baseline: 2.7448x; 1.1416x over previous
#include <cuda_runtime.h>
#include <cuda_bf16.h>
#include <math.h>
#include <stdint.h>

// Problem dims
#define B_   8
#define S_   2048
#define D_   768
#define H_   3072
#define NT_  (B_ * S_)         // 16384 tokens
#define EPS_ 1e-5f

// ---------------------------------------------------------------------------
// Scratch (device globals — no allocation allowed)
// ---------------------------------------------------------------------------
__device__ unsigned short g_h_hi [NT_ * D_],  g_h_lo [NT_ * D_];
__device__ unsigned short g_q_hi [NT_ * D_],  g_q_lo [NT_ * D_];
__device__ unsigned short g_k_hi [NT_ * D_],  g_k_lo [NT_ * D_];
__device__ unsigned short g_vt_hi[NT_ * D_],  g_vt_lo[NT_ * D_];   // [D, B*S]
__device__ float          g_sc[(size_t)B_ * S_ * S_];
__device__ unsigned short g_p_hi[(size_t)B_ * S_ * S_], g_p_lo[(size_t)B_ * S_ * S_];
__device__ unsigned short g_y_hi [NT_ * D_],  g_y_lo [NT_ * D_];
__device__ float          g_x1[NT_ * D_];
__device__ unsigned short g_h2_hi[NT_ * D_],  g_h2_lo[NT_ * D_];
__device__ unsigned short g_m_hi [(size_t)NT_ * H_], g_m_lo [(size_t)NT_ * H_];
// transposed-split weights  [N,K]
__device__ unsigned short g_wqt_hi[D_ * D_], g_wqt_lo[D_ * D_];
__device__ unsigned short g_wkt_hi[D_ * D_], g_wkt_lo[D_ * D_];
__device__ unsigned short g_wvt_hi[D_ * D_], g_wvt_lo[D_ * D_];
__device__ unsigned short g_wot_hi[D_ * D_], g_wot_lo[D_ * D_];
__device__ unsigned short g_wfct_hi[H_ * D_], g_wfct_lo[H_ * D_];
__device__ unsigned short g_wprojt_hi[D_ * H_], g_wprojt_lo[D_ * H_];

// ---------------------------------------------------------------------------
// PTX helpers (baseline ISA: cp.async / ldmatrix / mma.sync)
// ---------------------------------------------------------------------------
__device__ __forceinline__ void cp16(uint32_t dst, const void* src) {
    asm volatile("cp.async.cg.shared.global [%0], [%1], 16;" :: "r"(dst), "l"(src));
}
__device__ __forceinline__ void cp_commit() { asm volatile("cp.async.commit_group;" ::: "memory"); }
__device__ __forceinline__ void cp_wait0()  { asm volatile("cp.async.wait_group 0;"  ::: "memory"); }
__device__ __forceinline__ void cp_wait1()  { asm volatile("cp.async.wait_group 1;"  ::: "memory"); }

__device__ __forceinline__ void ldm4(uint32_t (&r)[4], uint32_t addr) {
    asm volatile("ldmatrix.sync.aligned.m8n8.x4.shared.b16 {%0,%1,%2,%3}, [%4];"
                 : "=r"(r[0]), "=r"(r[1]), "=r"(r[2]), "=r"(r[3]) : "r"(addr));
}
__device__ __forceinline__ void ldm2(uint32_t (&r)[2], uint32_t addr) {
    asm volatile("ldmatrix.sync.aligned.m8n8.x2.shared.b16 {%0,%1}, [%2];"
                 : "=r"(r[0]), "=r"(r[1]) : "r"(addr));
}
__device__ __forceinline__ void mma16816(float (&c)[4], const uint32_t (&a)[4],
                                         const uint32_t (&b)[2]) {
    asm volatile("mma.sync.aligned.m16n8k16.row.col.f32.bf16.bf16.f32 "
                 "{%0,%1,%2,%3}, {%4,%5,%6,%7}, {%8,%9}, {%0,%1,%2,%3};"
                 : "+f"(c[0]), "+f"(c[1]), "+f"(c[2]), "+f"(c[3])
                 : "r"(a[0]), "r"(a[1]), "r"(a[2]), "r"(a[3]), "r"(b[0]), "r"(b[1]));
}

__device__ __forceinline__ void split2(float v, __nv_bfloat16& h, __nv_bfloat16& l) {
    h = __float2bfloat16(v);
    l = __float2bfloat16(v - __bfloat162float(h));
}
__device__ __forceinline__ uint32_t pack2(__nv_bfloat16 a, __nv_bfloat16 b) {
    return ((uint32_t)__bfloat16_as_ushort(b) << 16) | __bfloat16_as_ushort(a);
}

// ---------------------------------------------------------------------------
// Tensor-core GEMM: C[M,N] = sum_k A[M,K]*B[N,K]  (A,B pre-split bf16 hi/lo)
// tile 256x128, BK=32, 512 threads (16 warps, 4x4), warp tile 64x32
// 2-stage cp.async, mma.m16n8k16, 3-pass hi/lo
// SMEM: pitch 80B per 32-elem row (stride 5*16B -> ldmatrix conflict-free)
// BIASM: 0 none, 1 col bias, 2 row bias
// ---------------------------------------------------------------------------
#define PITCH   80
#define ATILEB  (256 * PITCH)                 // 20480
#define BTILEB  (128 * PITCH)                 // 10240
#define STAGEB  (2 * ATILEB + 2 * BTILEB)     // 61440
#define SMEM_GEMM (2 * STAGEB)                // 122880

__device__ __forceinline__ void load_tileA(uint32_t dst, const __nv_bfloat16* g,
                                           long ld, int k0) {
    int tid = threadIdx.x;
#pragma unroll
    for (int i = 0; i < 2; i++) {
        int idx = tid + i * 512;              // 0..1023
        int row = idx >> 2, ch = idx & 3;
        cp16(dst + row * PITCH + ch * 16, g + (long)row * ld + k0 + ch * 8);
    }
}
__device__ __forceinline__ void load_tileB(uint32_t dst, const __nv_bfloat16* g,
                                           long ld, int k0) {
    int idx = threadIdx.x;                    // 0..511
    int row = idx >> 2, ch = idx & 3;
    cp16(dst + row * PITCH + ch * 16, g + (long)row * ld + k0 + ch * 8);
}

template <int BIASM, int DOGELU, int DORES, int SPLIT>
__global__ void __launch_bounds__(512, 1)
gemm_mma(const __nv_bfloat16* __restrict__ Ahi, const __nv_bfloat16* __restrict__ Alo,
         long ldA, long sA,
         const __nv_bfloat16* __restrict__ Bhi, const __nv_bfloat16* __restrict__ Blo,
         long ldB, long sB,
         float* __restrict__ Cf, __nv_bfloat16* __restrict__ Chi, __nv_bfloat16* __restrict__ Clo,
         long ldC, long sC,
         const float* __restrict__ bias, const float* __restrict__ res, int K)
{
    extern __shared__ char smem[];
    uint32_t sb = (uint32_t)__cvta_generic_to_shared(smem);
    int tid = threadIdx.x, lane = tid & 31, wid = tid >> 5;
    int wm = wid & 3, wn = wid >> 2;                  // 4 x 4 warp grid
    long row0 = (long)blockIdx.y * 256, col0 = (long)blockIdx.x * 128;
    int bz = blockIdx.z;

    const __nv_bfloat16* gAh = Ahi + (long)bz * sA + row0 * ldA;
    const __nv_bfloat16* gAl = Alo + (long)bz * sA + row0 * ldA;
    const __nv_bfloat16* gBh = Bhi + (long)bz * sB + col0 * ldB;
    const __nv_bfloat16* gBl = Blo + (long)bz * sB + col0 * ldB;

    float acc[4][4][4];
#pragma unroll
    for (int t = 0; t < 4; t++)
#pragma unroll
        for (int j = 0; j < 4; j++)
#pragma unroll
            for (int e = 0; e < 4; e++) acc[t][j][e] = 0.f;

    // ldmatrix lane addressing (stage-invariant parts)
    int a_row = wm * 64 + (lane & 15);                // + t*16
    int a_ch  = (lane >> 4) * 8;                      // + kk
    int b_row = wn * 32 + (lane & 7);                 // + j*8
    int b_ch  = ((lane >> 3) & 1) * 8;                // + kk

    // prologue: stage 0
    load_tileA(sb + 0,                     gAh, ldA, 0);
    load_tileA(sb + ATILEB,                gAl, ldA, 0);
    load_tileB(sb + 2 * ATILEB,            gBh, ldB, 0);
    load_tileB(sb + 2 * ATILEB + BTILEB,   gBl, ldB, 0);
    cp_commit();

    int NC = K >> 5;
    for (int c = 0; c < NC; c++) {
        if (c + 1 < NC) {
            uint32_t so = sb + ((c + 1) & 1) * STAGEB;
            int k0 = (c + 1) * 32;
            load_tileA(so + 0,                   gAh, ldA, k0);
            load_tileA(so + ATILEB,              gAl, ldA, k0);
            load_tileB(so + 2 * ATILEB,          gBh, ldB, k0);
            load_tileB(so + 2 * ATILEB + BTILEB, gBl, ldB, k0);
            cp_commit();
            cp_wait1();
        } else {
            cp_wait0();
        }
        __syncthreads();

        uint32_t s0 = sb + (c & 1) * STAGEB;
#pragma unroll
        for (int kk = 0; kk < 32; kk += 16) {
            uint32_t ah[4][4], al[4][4];
#pragma unroll
            for (int t = 0; t < 4; t++) {
                uint32_t ad = s0 + (a_row + t * 16) * PITCH + (a_ch + kk) * 2;
                ldm4(ah[t], ad);
                ldm4(al[t], ad + ATILEB);
            }
            uint32_t bh[4][2], bl[4][2];
#pragma unroll
            for (int j = 0; j < 4; j++) {
                uint32_t bd = s0 + 2 * ATILEB + (b_row + j * 8) * PITCH + (b_ch + kk) * 2;
                ldm2(bh[j], bd);
                ldm2(bl[j], bd + BTILEB);
            }
#pragma unroll
            for (int t = 0; t < 4; t++)
#pragma unroll
                for (int j = 0; j < 4; j++) {
                    mma16816(acc[t][j], ah[t], bh[j]);
                    mma16816(acc[t][j], ah[t], bl[j]);
                    mma16816(acc[t][j], al[t], bh[j]);
                }
        }
        if (c + 1 < NC) __syncthreads();
    }

    // epilogue: straight from registers, fused ops
#pragma unroll
    for (int t = 0; t < 4; t++)
#pragma unroll
        for (int j = 0; j < 4; j++) {
#pragma unroll
            for (int half = 0; half < 2; half++) {
                long r  = row0 + wm * 64 + t * 16 + (lane >> 2) + half * 8;
                long cc = col0 + wn * 32 + j * 8 + (lane & 3) * 2;
                float v0 = acc[t][j][half * 2 + 0];
                float v1 = acc[t][j][half * 2 + 1];
                if (BIASM == 1) { v0 += bias[cc]; v1 += bias[cc + 1]; }
                if (BIASM == 2) { float bb = bias[r]; v0 += bb; v1 += bb; }
                if (DOGELU) {
                    v0 = 0.5f * v0 * (1.f + erff(v0 * 0.70710678118654752f));
                    v1 = 0.5f * v1 * (1.f + erff(v1 * 0.70710678118654752f));
                }
                long off = (long)bz * sC + r * ldC + cc;
                if (DORES) {
                    float2 rv = *reinterpret_cast<const float2*>(res + off);
                    v0 += rv.x; v1 += rv.y;
                }
                if (SPLIT) {
                    __nv_bfloat16 h0, l0, h1, l1;
                    split2(v0, h0, l0); split2(v1, h1, l1);
                    *reinterpret_cast<uint32_t*>(Chi + off) = pack2(h0, h1);
                    *reinterpret_cast<uint32_t*>(Clo + off) = pack2(l0, l1);
                } else {
                    *reinterpret_cast<float2*>(Cf + off) = make_float2(v0, v1);
                }
            }
        }
}

// ---------------------------------------------------------------------------
// Transpose + split:  W[K,N] fp32  ->  out[N,K] bf16 hi/lo
// ---------------------------------------------------------------------------
__global__ void __launch_bounds__(256)
tsplit_kernel(const float* __restrict__ W, __nv_bfloat16* __restrict__ hi,
              __nv_bfloat16* __restrict__ lo, int K, int N)
{
    __shared__ float t[32][33];
    int n0 = blockIdx.x * 32, k0 = blockIdx.y * 32;
    int tx = threadIdx.x & 31, ty = threadIdx.x >> 5;  // 32x8
#pragma unroll
    for (int i = 0; i < 32; i += 8)
        t[ty + i][tx] = W[(long)(k0 + ty + i) * N + n0 + tx];
    __syncthreads();
#pragma unroll
    for (int i = 0; i < 32; i += 8) {
        float v = t[tx][ty + i];
        long o = (long)(n0 + ty + i) * K + k0 + tx;
        __nv_bfloat16 h, l; split2(v, h, l);
        hi[o] = h; lo[o] = l;
    }
}

// ---------------------------------------------------------------------------
// LayerNorm -> split bf16 output
// ---------------------------------------------------------------------------
__global__ void __launch_bounds__(256)
ln_kernel(const float* __restrict__ x, const float* __restrict__ g,
          const float* __restrict__ b, __nv_bfloat16* __restrict__ ohi,
          __nv_bfloat16* __restrict__ olo)
{
    long row = blockIdx.x;
    const float* xr = x + row * D_;
    int t = threadIdx.x;
    float vals[3];
    float s = 0.f, s2 = 0.f;
#pragma unroll
    for (int i = 0; i < 3; i++) {
        float v = xr[t + i * 256];
        vals[i] = v; s += v; s2 += v * v;
    }
#pragma unroll
    for (int o = 16; o > 0; o >>= 1) {
        s  += __shfl_xor_sync(0xffffffffu, s,  o);
        s2 += __shfl_xor_sync(0xffffffffu, s2, o);
    }
    __shared__ float sm[8], sm2[8], stat[2];
    int w = t >> 5, l = t & 31;
    if (l == 0) { sm[w] = s; sm2[w] = s2; }
    __syncthreads();
    if (t == 0) {
        float a = 0.f, c = 0.f;
#pragma unroll
        for (int i = 0; i < 8; i++) { a += sm[i]; c += sm2[i]; }
        float mu = a / (float)D_;
        stat[0] = mu;
        stat[1] = rsqrtf(c / (float)D_ - mu * mu + EPS_);
    }
    __syncthreads();
    float mu = stat[0], rstd = stat[1];
#pragma unroll
    for (int i = 0; i < 3; i++) {
        int idx = t + i * 256;
        float v = (vals[i] - mu) * rstd * g[idx] + b[idx];
        __nv_bfloat16 h, lo2; split2(v, h, lo2);
        ohi[row * D_ + idx] = h; olo[row * D_ + idx] = lo2;
    }
}

// ---------------------------------------------------------------------------
// Softmax (with scale) -> split bf16 probs
// ---------------------------------------------------------------------------
__global__ void __launch_bounds__(256)
softmax_kernel(const float* __restrict__ sc, __nv_bfloat16* __restrict__ phi,
               __nv_bfloat16* __restrict__ plo, float scale)
{
    long row = blockIdx.x;
    const float* p = sc + row * (long)S_;
    int t = threadIdx.x;
    float vals[8];
    float mx = -1e30f;
#pragma unroll
    for (int i = 0; i < 8; i++) {
        float v = p[t + i * 256];
        vals[i] = v; mx = fmaxf(mx, v);
    }
#pragma unroll
    for (int o = 16; o > 0; o >>= 1)
        mx = fmaxf(mx, __shfl_xor_sync(0xffffffffu, mx, o));
    __shared__ float sm[8], stat[1];
    int w = t >> 5, l = t & 31;
    if (l == 0) sm[w] = mx;
    __syncthreads();
    if (t == 0) {
        float m2 = sm[0];
#pragma unroll
        for (int i = 1; i < 8; i++) m2 = fmaxf(m2, sm[i]);
        stat[0] = m2;
    }
    __syncthreads();
    float rowmax = stat[0];
    float sum = 0.f;
#pragma unroll
    for (int i = 0; i < 8; i++) {
        float e = __expf((vals[i] - rowmax) * scale);
        vals[i] = e; sum += e;
    }
#pragma unroll
    for (int o = 16; o > 0; o >>= 1)
        sum += __shfl_xor_sync(0xffffffffu, sum, o);
    if (l == 0) sm[w] = sum;
    __syncthreads();
    if (t == 0) {
        float a = 0.f;
#pragma unroll
        for (int i = 0; i < 8; i++) a += sm[i];
        stat[0] = 1.f / a;
    }
    __syncthreads();
    float inv = stat[0];
#pragma unroll
    for (int i = 0; i < 8; i++) {
        float v = vals[i] * inv;
        __nv_bfloat16 h, lo2; split2(v, h, lo2);
        long o2 = row * (long)S_ + t + i * 256;
        phi[o2] = h; plo[o2] = lo2;
    }
}

// ---------------------------------------------------------------------------
// Launch
// ---------------------------------------------------------------------------
extern "C" void kernel_launch(void* const* d_in, const int* in_sizes, int n_in,
                              void* d_out, int out_size)
{
    const float* x     = (const float*)d_in[0];
    const float* ln1g  = (const float*)d_in[1];
    const float* ln1b  = (const float*)d_in[2];
    const float* ln2g  = (const float*)d_in[3];
    const float* ln2b  = (const float*)d_in[4];
    const float* Wq    = (const float*)d_in[5];
    const float* bq    = (const float*)d_in[6];
    const float* Wk    = (const float*)d_in[7];
    const float* bk    = (const float*)d_in[8];
    const float* Wv    = (const float*)d_in[9];
    const float* bv    = (const float*)d_in[10];
    const float* Wo    = (const float*)d_in[11];
    const float* bo    = (const float*)d_in[12];
    const float* Wfc   = (const float*)d_in[13];
    const float* bfc   = (const float*)d_in[14];
    const float* Wproj = (const float*)d_in[15];
    const float* bproj = (const float*)d_in[16];
    float* out = (float*)d_out;

    auto ga = [](const void* sym) { void* p; cudaGetSymbolAddress(&p, sym); return p; };
    __nv_bfloat16 *h_hi = (__nv_bfloat16*)ga(g_h_hi),   *h_lo = (__nv_bfloat16*)ga(g_h_lo);
    __nv_bfloat16 *q_hi = (__nv_bfloat16*)ga(g_q_hi),   *q_lo = (__nv_bfloat16*)ga(g_q_lo);
    __nv_bfloat16 *k_hi = (__nv_bfloat16*)ga(g_k_hi),   *k_lo = (__nv_bfloat16*)ga(g_k_lo);
    __nv_bfloat16 *vt_hi= (__nv_bfloat16*)ga(g_vt_hi),  *vt_lo= (__nv_bfloat16*)ga(g_vt_lo);
    float         *sc   = (float*)ga(g_sc);
    __nv_bfloat16 *p_hi = (__nv_bfloat16*)ga(g_p_hi),   *p_lo = (__nv_bfloat16*)ga(g_p_lo);
    __nv_bfloat16 *y_hi = (__nv_bfloat16*)ga(g_y_hi),   *y_lo = (__nv_bfloat16*)ga(g_y_lo);
    float         *x1   = (float*)ga(g_x1);
    __nv_bfloat16 *h2_hi= (__nv_bfloat16*)ga(g_h2_hi),  *h2_lo= (__nv_bfloat16*)ga(g_h2_lo);
    __nv_bfloat16 *m_hi = (__nv_bfloat16*)ga(g_m_hi),   *m_lo = (__nv_bfloat16*)ga(g_m_lo);
    __nv_bfloat16 *wqt_hi = (__nv_bfloat16*)ga(g_wqt_hi), *wqt_lo = (__nv_bfloat16*)ga(g_wqt_lo);
    __nv_bfloat16 *wkt_hi = (__nv_bfloat16*)ga(g_wkt_hi), *wkt_lo = (__nv_bfloat16*)ga(g_wkt_lo);
    __nv_bfloat16 *wvt_hi = (__nv_bfloat16*)ga(g_wvt_hi), *wvt_lo = (__nv_bfloat16*)ga(g_wvt_lo);
    __nv_bfloat16 *wot_hi = (__nv_bfloat16*)ga(g_wot_hi), *wot_lo = (__nv_bfloat16*)ga(g_wot_lo);
    __nv_bfloat16 *wfct_hi = (__nv_bfloat16*)ga(g_wfct_hi), *wfct_lo = (__nv_bfloat16*)ga(g_wfct_lo);
    __nv_bfloat16 *wpt_hi = (__nv_bfloat16*)ga(g_wprojt_hi), *wpt_lo = (__nv_bfloat16*)ga(g_wprojt_lo);

    cudaFuncSetAttribute(gemm_mma<1,0,0,1>, cudaFuncAttributeMaxDynamicSharedMemorySize, SMEM_GEMM);
    cudaFuncSetAttribute(gemm_mma<2,0,0,1>, cudaFuncAttributeMaxDynamicSharedMemorySize, SMEM_GEMM);
    cudaFuncSetAttribute(gemm_mma<0,0,0,0>, cudaFuncAttributeMaxDynamicSharedMemorySize, SMEM_GEMM);
    cudaFuncSetAttribute(gemm_mma<0,0,0,1>, cudaFuncAttributeMaxDynamicSharedMemorySize, SMEM_GEMM);
    cudaFuncSetAttribute(gemm_mma<1,0,1,0>, cudaFuncAttributeMaxDynamicSharedMemorySize, SMEM_GEMM);
    cudaFuncSetAttribute(gemm_mma<1,1,0,1>, cudaFuncAttributeMaxDynamicSharedMemorySize, SMEM_GEMM);

    const long sQ = (long)S_ * D_;
    const long sS = (long)S_ * S_;

    // 1) LN1
    ln_kernel<<<NT_, 256>>>(x, ln1g, ln1b, h_hi, h_lo);

    // 2-4) weight transpose+split for q/k/v
    tsplit_kernel<<<dim3(24, 24), 256>>>(Wq, wqt_hi, wqt_lo, D_, D_);
    tsplit_kernel<<<dim3(24, 24), 256>>>(Wk, wkt_hi, wkt_lo, D_, D_);
    tsplit_kernel<<<dim3(24, 24), 256>>>(Wv, wvt_hi, wvt_lo, D_, D_);

    // 5) q   6) k   (launch #6 = this GEMM gets profiled by ncu -s 5 -c 1)
    gemm_mma<1,0,0,1><<<dim3(6, 64, 1), 512, SMEM_GEMM>>>(
        h_hi, h_lo, D_, 0, wqt_hi, wqt_lo, D_, 0,
        nullptr, q_hi, q_lo, D_, 0, bq, nullptr, D_);
    gemm_mma<1,0,0,1><<<dim3(6, 64, 1), 512, SMEM_GEMM>>>(
        h_hi, h_lo, D_, 0, wkt_hi, wkt_lo, D_, 0,
        nullptr, k_hi, k_lo, D_, 0, bk, nullptr, D_);

    // 7) v^T = Wv^T . h^T   ([768,16384], row bias)
    gemm_mma<2,0,0,1><<<dim3(128, 3, 1), 512, SMEM_GEMM>>>(
        wvt_hi, wvt_lo, D_, 0, h_hi, h_lo, D_, 0,
        nullptr, vt_hi, vt_lo, NT_, 0, bv, nullptr, D_);

    // 8) scores = q . k^T  (batched, fp32 out)
    gemm_mma<0,0,0,0><<<dim3(16, 8, B_), 512, SMEM_GEMM>>>(
        q_hi, q_lo, D_, sQ, k_hi, k_lo, D_, sQ,
        sc, nullptr, nullptr, S_, sS, nullptr, nullptr, D_);

    // 9) softmax (scale inside) -> split probs
    softmax_kernel<<<B_ * S_, 256>>>(sc, p_hi, p_lo, 1.0f / sqrtf((float)D_));

    // 10) y = probs . v
    gemm_mma<0,0,0,1><<<dim3(6, 8, B_), 512, SMEM_GEMM>>>(
        p_hi, p_lo, S_, sS, vt_hi, vt_lo, NT_, S_,
        nullptr, y_hi, y_lo, D_, sQ, nullptr, nullptr, S_);

    // 11) tsplit Wo   12) x1 = x + y . Wo + bo
    tsplit_kernel<<<dim3(24, 24), 256>>>(Wo, wot_hi, wot_lo, D_, D_);
    gemm_mma<1,0,1,0><<<dim3(6, 64, 1), 512, SMEM_GEMM>>>(
        y_hi, y_lo, D_, 0, wot_hi, wot_lo, D_, 0,
        x1, nullptr, nullptr, D_, 0, bo, x, D_);

    // 13) LN2
    ln_kernel<<<NT_, 256>>>(x1, ln2g, ln2b, h2_hi, h2_lo);

    // 14) tsplit Wfc   15) m = GELU(h2 . Wfc + bfc)
    tsplit_kernel<<<dim3(96, 24), 256>>>(Wfc, wfct_hi, wfct_lo, D_, H_);
    gemm_mma<1,1,0,1><<<dim3(24, 64, 1), 512, SMEM_GEMM>>>(
        h2_hi, h2_lo, D_, 0, wfct_hi, wfct_lo, D_, 0,
        nullptr, m_hi, m_lo, H_, 0, bfc, nullptr, D_);

    // 16) tsplit Wproj   17) out = x1 + m . Wproj + bproj
    tsplit_kernel<<<dim3(24, 96), 256>>>(Wproj, wpt_hi, wpt_lo, H_, D_);
    gemm_mma<1,0,1,0><<<dim3(6, 64, 1), 512, SMEM_GEMM>>>(
        m_hi, m_lo, H_, 0, wpt_hi, wpt_lo, H_, 0,
        out, nullptr, nullptr, D_, 0, bproj, x1, H_);
}

// round 6
// speedup vs baseline: 3.8308x; 1.3957x over previous
#include <cuda_runtime.h>
#include <cuda_fp16.h>
#include <math.h>
#include <stdint.h>

// Problem dims
#define B_   8
#define S_   2048
#define D_   768
#define H_   3072
#define NT_  (B_ * S_)         // 16384 tokens
#define EPS_ 1e-5f

// ---------------------------------------------------------------------------
// Scratch (device globals)
// ---------------------------------------------------------------------------
__device__ unsigned short g_h_hi [NT_ * D_],  g_h_lo [NT_ * D_];   // LN1 out (B-operand: hi/lo)
__device__ unsigned short g_q   [NT_ * D_];                        // A-operand: single fp16
__device__ unsigned short g_k_hi [NT_ * D_],  g_k_lo [NT_ * D_];   // B-operand
__device__ unsigned short g_vt_hi[NT_ * D_],  g_vt_lo[NT_ * D_];   // [D, B*S], B-operand
__device__ float          g_sc[(size_t)B_ * S_ * S_];
__device__ unsigned short g_p  [(size_t)B_ * S_ * S_];             // probs single
__device__ unsigned short g_y  [NT_ * D_];                         // single
__device__ float          g_x1[NT_ * D_];
__device__ unsigned short g_h2 [NT_ * D_];                         // single
__device__ unsigned short g_m  [(size_t)NT_ * H_];                 // single
// transposed-split weights [N,K] fp16 hi/lo
__device__ unsigned short g_wqt_hi[D_ * D_], g_wqt_lo[D_ * D_];
__device__ unsigned short g_wkt_hi[D_ * D_], g_wkt_lo[D_ * D_];
__device__ unsigned short g_wvt_hi[D_ * D_], g_wvt_lo[D_ * D_];
__device__ unsigned short g_wot_hi[D_ * D_], g_wot_lo[D_ * D_];
__device__ unsigned short g_wfct_hi[H_ * D_], g_wfct_lo[H_ * D_];
__device__ unsigned short g_wprojt_hi[D_ * H_], g_wprojt_lo[D_ * H_];

// ---------------------------------------------------------------------------
// PTX helpers
// ---------------------------------------------------------------------------
__device__ __forceinline__ void cp16(uint32_t dst, const void* src) {
    asm volatile("cp.async.cg.shared.global [%0], [%1], 16;" :: "r"(dst), "l"(src));
}
__device__ __forceinline__ void cp_commit() { asm volatile("cp.async.commit_group;" ::: "memory"); }
__device__ __forceinline__ void cp_wait0()  { asm volatile("cp.async.wait_group 0;"  ::: "memory"); }
__device__ __forceinline__ void cp_wait1()  { asm volatile("cp.async.wait_group 1;"  ::: "memory"); }

__device__ __forceinline__ void ldm4(uint32_t (&r)[4], uint32_t addr) {
    asm volatile("ldmatrix.sync.aligned.m8n8.x4.shared.b16 {%0,%1,%2,%3}, [%4];"
                 : "=r"(r[0]), "=r"(r[1]), "=r"(r[2]), "=r"(r[3]) : "r"(addr));
}
__device__ __forceinline__ void ldm2(uint32_t (&r)[2], uint32_t addr) {
    asm volatile("ldmatrix.sync.aligned.m8n8.x2.shared.b16 {%0,%1}, [%2];"
                 : "=r"(r[0]), "=r"(r[1]) : "r"(addr));
}
__device__ __forceinline__ void mma16816(float (&c)[4], const uint32_t (&a)[4],
                                         const uint32_t (&b)[2]) {
    asm volatile("mma.sync.aligned.m16n8k16.row.col.f32.f16.f16.f32 "
                 "{%0,%1,%2,%3}, {%4,%5,%6,%7}, {%8,%9}, {%0,%1,%2,%3};"
                 : "+f"(c[0]), "+f"(c[1]), "+f"(c[2]), "+f"(c[3])
                 : "r"(a[0]), "r"(a[1]), "r"(a[2]), "r"(a[3]), "r"(b[0]), "r"(b[1]));
}

__device__ __forceinline__ void split2h(float v, __half& h, __half& l) {
    h = __float2half(v);
    l = __float2half(v - __half2float(h));
}
__device__ __forceinline__ uint32_t pack2h(__half a, __half b) {
    return ((uint32_t)__half_as_ushort(b) << 16) | __half_as_ushort(a);
}

// ---------------------------------------------------------------------------
// Tensor-core GEMM: C[M,N] = sum_k A[M,K]*B[N,K]
//   A: plain fp16.  B: fp16 hi/lo (2-pass).
// tile 256x128, BK=32, 512 threads (16 warps 4x4), warp tile 64x32
// 3-stage cp.async pipeline.  PITCH=80 B rows -> ldmatrix conflict-free.
// BIASM: 0 none, 1 col, 2 row.  OUTK: 0 fp32, 1 fp16 single, 2 fp16 hi/lo
// ---------------------------------------------------------------------------
#define PITCH   80
#define ATILEB  (256 * PITCH)                 // 20480
#define BTILEB  (128 * PITCH)                 // 10240
#define STAGEB  (ATILEB + 2 * BTILEB)         // 40960
#define SMEM_GEMM (3 * STAGEB)                // 122880

__device__ __forceinline__ void load_tileA(uint32_t dst, const __half* g,
                                           long ld, int k0) {
    int tid = threadIdx.x;
#pragma unroll
    for (int i = 0; i < 2; i++) {
        int idx = tid + i * 512;              // 0..1023
        int row = idx >> 2, ch = idx & 3;
        cp16(dst + row * PITCH + ch * 16, g + (long)row * ld + k0 + ch * 8);
    }
}
__device__ __forceinline__ void load_tileB(uint32_t dst, const __half* g,
                                           long ld, int k0) {
    int idx = threadIdx.x;                    // 0..511
    int row = idx >> 2, ch = idx & 3;
    cp16(dst + row * PITCH + ch * 16, g + (long)row * ld + k0 + ch * 8);
}

template <int BIASM, int DOGELU, int DORES, int OUTK>
__global__ void __launch_bounds__(512, 1)
gemm_mma(const __half* __restrict__ A, long ldA, long sA,
         const __half* __restrict__ Bhi, const __half* __restrict__ Blo,
         long ldB, long sB,
         float* __restrict__ Cf, __half* __restrict__ Chi, __half* __restrict__ Clo,
         long ldC, long sC,
         const float* __restrict__ bias, const float* __restrict__ res, int K)
{
    extern __shared__ char smem[];
    uint32_t sb = (uint32_t)__cvta_generic_to_shared(smem);
    int tid = threadIdx.x, lane = tid & 31, wid = tid >> 5;
    int wm = wid & 3, wn = wid >> 2;                  // 4 x 4 warp grid
    long row0 = (long)blockIdx.y * 256, col0 = (long)blockIdx.x * 128;
    int bz = blockIdx.z;

    const __half* gA  = A   + (long)bz * sA + row0 * ldA;
    const __half* gBh = Bhi + (long)bz * sB + col0 * ldB;
    const __half* gBl = Blo + (long)bz * sB + col0 * ldB;

    float acc[4][4][4];
#pragma unroll
    for (int t = 0; t < 4; t++)
#pragma unroll
        for (int j = 0; j < 4; j++)
#pragma unroll
            for (int e = 0; e < 4; e++) acc[t][j][e] = 0.f;

    int a_row = wm * 64 + (lane & 15);
    int a_ch  = (lane >> 4) * 8;
    int b_row = wn * 32 + (lane & 7);
    int b_ch  = ((lane >> 3) & 1) * 8;

    int NC = K >> 5;
    // prologue: stages 0,1
    {
        load_tileA(sb + 0 * STAGEB,          gA,  ldA, 0);
        load_tileB(sb + 0 * STAGEB + ATILEB,          gBh, ldB, 0);
        load_tileB(sb + 0 * STAGEB + ATILEB + BTILEB, gBl, ldB, 0);
        cp_commit();
        if (NC > 1) {
            load_tileA(sb + 1 * STAGEB,          gA,  ldA, 32);
            load_tileB(sb + 1 * STAGEB + ATILEB,          gBh, ldB, 32);
            load_tileB(sb + 1 * STAGEB + ATILEB + BTILEB, gBl, ldB, 32);
            cp_commit();
        }
    }

    for (int c = 0; c < NC; c++) {
        if (c + 1 < NC) cp_wait1(); else cp_wait0();
        __syncthreads();
        if (c + 2 < NC) {
            uint32_t so = sb + ((c + 2) % 3) * STAGEB;
            int k0 = (c + 2) * 32;
            load_tileA(so,                   gA,  ldA, k0);
            load_tileB(so + ATILEB,          gBh, ldB, k0);
            load_tileB(so + ATILEB + BTILEB, gBl, ldB, k0);
            cp_commit();
        }

        uint32_t s0 = sb + (c % 3) * STAGEB;
#pragma unroll
        for (int kk = 0; kk < 32; kk += 16) {
            uint32_t ah[4][4];
#pragma unroll
            for (int t = 0; t < 4; t++)
                ldm4(ah[t], s0 + (a_row + t * 16) * PITCH + (a_ch + kk) * 2);
            uint32_t bh[4][2], bl[4][2];
#pragma unroll
            for (int j = 0; j < 4; j++) {
                uint32_t bd = s0 + ATILEB + (b_row + j * 8) * PITCH + (b_ch + kk) * 2;
                ldm2(bh[j], bd);
                ldm2(bl[j], bd + BTILEB);
            }
#pragma unroll
            for (int t = 0; t < 4; t++)
#pragma unroll
                for (int j = 0; j < 4; j++) {
                    mma16816(acc[t][j], ah[t], bh[j]);
                    mma16816(acc[t][j], ah[t], bl[j]);
                }
        }
    }

    // epilogue: from registers, fused ops
#pragma unroll
    for (int t = 0; t < 4; t++)
#pragma unroll
        for (int j = 0; j < 4; j++) {
#pragma unroll
            for (int half = 0; half < 2; half++) {
                long r  = row0 + wm * 64 + t * 16 + (lane >> 2) + half * 8;
                long cc = col0 + wn * 32 + j * 8 + (lane & 3) * 2;
                float v0 = acc[t][j][half * 2 + 0];
                float v1 = acc[t][j][half * 2 + 1];
                if (BIASM == 1) { v0 += bias[cc]; v1 += bias[cc + 1]; }
                if (BIASM == 2) { float bb = bias[r]; v0 += bb; v1 += bb; }
                if (DOGELU) {
                    v0 = 0.5f * v0 * (1.f + erff(v0 * 0.70710678118654752f));
                    v1 = 0.5f * v1 * (1.f + erff(v1 * 0.70710678118654752f));
                }
                long off = (long)bz * sC + r * ldC + cc;
                if (DORES) {
                    float2 rv = *reinterpret_cast<const float2*>(res + off);
                    v0 += rv.x; v1 += rv.y;
                }
                if (OUTK == 0) {
                    *reinterpret_cast<float2*>(Cf + off) = make_float2(v0, v1);
                } else if (OUTK == 1) {
                    *reinterpret_cast<uint32_t*>(Chi + off) =
                        pack2h(__float2half(v0), __float2half(v1));
                } else {
                    __half h0, l0, h1, l1;
                    split2h(v0, h0, l0); split2h(v1, h1, l1);
                    *reinterpret_cast<uint32_t*>(Chi + off) = pack2h(h0, h1);
                    *reinterpret_cast<uint32_t*>(Clo + off) = pack2h(l0, l1);
                }
            }
        }
}

// ---------------------------------------------------------------------------
// Transpose + split:  W[K,N] fp32 -> out[N,K] fp16 hi/lo
// ---------------------------------------------------------------------------
__global__ void __launch_bounds__(256)
tsplit_kernel(const float* __restrict__ W, __half* __restrict__ hi,
              __half* __restrict__ lo, int K, int N)
{
    __shared__ float t[32][33];
    int n0 = blockIdx.x * 32, k0 = blockIdx.y * 32;
    int tx = threadIdx.x & 31, ty = threadIdx.x >> 5;
#pragma unroll
    for (int i = 0; i < 32; i += 8)
        t[ty + i][tx] = W[(long)(k0 + ty + i) * N + n0 + tx];
    __syncthreads();
#pragma unroll
    for (int i = 0; i < 32; i += 8) {
        float v = t[tx][ty + i];
        long o = (long)(n0 + ty + i) * K + k0 + tx;
        __half h, l; split2h(v, h, l);
        hi[o] = h; lo[o] = l;
    }
}

// ---------------------------------------------------------------------------
// LayerNorm. HILO=1: write hi+lo, HILO=0: single fp16
// ---------------------------------------------------------------------------
template <int HILO>
__global__ void __launch_bounds__(256)
ln_kernel(const float* __restrict__ x, const float* __restrict__ g,
          const float* __restrict__ b, __half* __restrict__ ohi,
          __half* __restrict__ olo)
{
    long row = blockIdx.x;
    const float* xr = x + row * D_;
    int t = threadIdx.x;
    float vals[3];
    float s = 0.f, s2 = 0.f;
#pragma unroll
    for (int i = 0; i < 3; i++) {
        float v = xr[t + i * 256];
        vals[i] = v; s += v; s2 += v * v;
    }
#pragma unroll
    for (int o = 16; o > 0; o >>= 1) {
        s  += __shfl_xor_sync(0xffffffffu, s,  o);
        s2 += __shfl_xor_sync(0xffffffffu, s2, o);
    }
    __shared__ float sm[8], sm2[8], stat[2];
    int w = t >> 5, l = t & 31;
    if (l == 0) { sm[w] = s; sm2[w] = s2; }
    __syncthreads();
    if (t == 0) {
        float a = 0.f, c = 0.f;
#pragma unroll
        for (int i = 0; i < 8; i++) { a += sm[i]; c += sm2[i]; }
        float mu = a / (float)D_;
        stat[0] = mu;
        stat[1] = rsqrtf(c / (float)D_ - mu * mu + EPS_);
    }
    __syncthreads();
    float mu = stat[0], rstd = stat[1];
#pragma unroll
    for (int i = 0; i < 3; i++) {
        int idx = t + i * 256;
        float v = (vals[i] - mu) * rstd * g[idx] + b[idx];
        if (HILO) {
            __half h, lo2; split2h(v, h, lo2);
            ohi[row * D_ + idx] = h; olo[row * D_ + idx] = lo2;
        } else {
            ohi[row * D_ + idx] = __float2half(v);
        }
    }
}

// ---------------------------------------------------------------------------
// Softmax (with scale) -> single fp16 probs
// ---------------------------------------------------------------------------
__global__ void __launch_bounds__(256)
softmax_kernel(const float* __restrict__ sc, __half* __restrict__ ph, float scale)
{
    long row = blockIdx.x;
    const float* p = sc + row * (long)S_;
    int t = threadIdx.x;
    float vals[8];
    float mx = -1e30f;
#pragma unroll
    for (int i = 0; i < 8; i++) {
        float v = p[t + i * 256];
        vals[i] = v; mx = fmaxf(mx, v);
    }
#pragma unroll
    for (int o = 16; o > 0; o >>= 1)
        mx = fmaxf(mx, __shfl_xor_sync(0xffffffffu, mx, o));
    __shared__ float sm[8], stat[1];
    int w = t >> 5, l = t & 31;
    if (l == 0) sm[w] = mx;
    __syncthreads();
    if (t == 0) {
        float m2 = sm[0];
#pragma unroll
        for (int i = 1; i < 8; i++) m2 = fmaxf(m2, sm[i]);
        stat[0] = m2;
    }
    __syncthreads();
    float rowmax = stat[0];
    float sum = 0.f;
#pragma unroll
    for (int i = 0; i < 8; i++) {
        float e = __expf((vals[i] - rowmax) * scale);
        vals[i] = e; sum += e;
    }
#pragma unroll
    for (int o = 16; o > 0; o >>= 1)
        sum += __shfl_xor_sync(0xffffffffu, sum, o);
    if (l == 0) sm[w] = sum;
    __syncthreads();
    if (t == 0) {
        float a = 0.f;
#pragma unroll
        for (int i = 0; i < 8; i++) a += sm[i];
        stat[0] = 1.f / a;
    }
    __syncthreads();
    float inv = stat[0];
#pragma unroll
    for (int i = 0; i < 8; i++)
        ph[row * (long)S_ + t + i * 256] = __float2half(vals[i] * inv);
}

// ---------------------------------------------------------------------------
// Launch
// ---------------------------------------------------------------------------
extern "C" void kernel_launch(void* const* d_in, const int* in_sizes, int n_in,
                              void* d_out, int out_size)
{
    const float* x     = (const float*)d_in[0];
    const float* ln1g  = (const float*)d_in[1];
    const float* ln1b  = (const float*)d_in[2];
    const float* ln2g  = (const float*)d_in[3];
    const float* ln2b  = (const float*)d_in[4];
    const float* Wq    = (const float*)d_in[5];
    const float* bq    = (const float*)d_in[6];
    const float* Wk    = (const float*)d_in[7];
    const float* bk    = (const float*)d_in[8];
    const float* Wv    = (const float*)d_in[9];
    const float* bv    = (const float*)d_in[10];
    const float* Wo    = (const float*)d_in[11];
    const float* bo    = (const float*)d_in[12];
    const float* Wfc   = (const float*)d_in[13];
    const float* bfc   = (const float*)d_in[14];
    const float* Wproj = (const float*)d_in[15];
    const float* bproj = (const float*)d_in[16];
    float* out = (float*)d_out;

    auto ga = [](const void* sym) { void* p; cudaGetSymbolAddress(&p, sym); return p; };
    __half *h_hi = (__half*)ga(g_h_hi),   *h_lo = (__half*)ga(g_h_lo);
    __half *q    = (__half*)ga(g_q);
    __half *k_hi = (__half*)ga(g_k_hi),   *k_lo = (__half*)ga(g_k_lo);
    __half *vt_hi= (__half*)ga(g_vt_hi),  *vt_lo= (__half*)ga(g_vt_lo);
    float  *sc   = (float*)ga(g_sc);
    __half *p    = (__half*)ga(g_p);
    __half *y    = (__half*)ga(g_y);
    float  *x1   = (float*)ga(g_x1);
    __half *h2   = (__half*)ga(g_h2);
    __half *m    = (__half*)ga(g_m);
    __half *wqt_hi = (__half*)ga(g_wqt_hi), *wqt_lo = (__half*)ga(g_wqt_lo);
    __half *wkt_hi = (__half*)ga(g_wkt_hi), *wkt_lo = (__half*)ga(g_wkt_lo);
    __half *wvt_hi = (__half*)ga(g_wvt_hi), *wvt_lo = (__half*)ga(g_wvt_lo);
    __half *wot_hi = (__half*)ga(g_wot_hi), *wot_lo = (__half*)ga(g_wot_lo);
    __half *wfct_hi = (__half*)ga(g_wfct_hi), *wfct_lo = (__half*)ga(g_wfct_lo);
    __half *wpt_hi = (__half*)ga(g_wprojt_hi), *wpt_lo = (__half*)ga(g_wprojt_lo);

    cudaFuncSetAttribute(gemm_mma<1,0,0,1>, cudaFuncAttributeMaxDynamicSharedMemorySize, SMEM_GEMM);
    cudaFuncSetAttribute(gemm_mma<1,0,0,2>, cudaFuncAttributeMaxDynamicSharedMemorySize, SMEM_GEMM);
    cudaFuncSetAttribute(gemm_mma<2,0,0,2>, cudaFuncAttributeMaxDynamicSharedMemorySize, SMEM_GEMM);
    cudaFuncSetAttribute(gemm_mma<0,0,0,0>, cudaFuncAttributeMaxDynamicSharedMemorySize, SMEM_GEMM);
    cudaFuncSetAttribute(gemm_mma<0,0,0,1>, cudaFuncAttributeMaxDynamicSharedMemorySize, SMEM_GEMM);
    cudaFuncSetAttribute(gemm_mma<1,0,1,0>, cudaFuncAttributeMaxDynamicSharedMemorySize, SMEM_GEMM);
    cudaFuncSetAttribute(gemm_mma<1,1,0,1>, cudaFuncAttributeMaxDynamicSharedMemorySize, SMEM_GEMM);

    const long sQ = (long)S_ * D_;
    const long sS = (long)S_ * S_;

    // LN1 -> h hi/lo
    ln_kernel<1><<<NT_, 256>>>(x, ln1g, ln1b, h_hi, h_lo);

    // weight transpose+split q/k/v
    tsplit_kernel<<<dim3(24, 24), 256>>>(Wq, wqt_hi, wqt_lo, D_, D_);
    tsplit_kernel<<<dim3(24, 24), 256>>>(Wk, wkt_hi, wkt_lo, D_, D_);
    tsplit_kernel<<<dim3(24, 24), 256>>>(Wv, wvt_hi, wvt_lo, D_, D_);

    // q (single out), k (hi/lo out); A = h_hi (fp16 single)
    gemm_mma<1,0,0,1><<<dim3(6, 64, 1), 512, SMEM_GEMM>>>(
        h_hi, D_, 0, wqt_hi, wqt_lo, D_, 0,
        nullptr, q, nullptr, D_, 0, bq, nullptr, D_);
    gemm_mma<1,0,0,2><<<dim3(6, 64, 1), 512, SMEM_GEMM>>>(
        h_hi, D_, 0, wkt_hi, wkt_lo, D_, 0,
        nullptr, k_hi, k_lo, D_, 0, bk, nullptr, D_);

    // v^T = Wv^T . h^T  (A = wvt_hi single, B = h hi/lo, row bias, out hi/lo)
    gemm_mma<2,0,0,2><<<dim3(128, 3, 1), 512, SMEM_GEMM>>>(
        wvt_hi, D_, 0, h_hi, h_lo, D_, 0,
        nullptr, vt_hi, vt_lo, NT_, 0, bv, nullptr, D_);

    // scores = q . k^T (batched, fp32 out)
    gemm_mma<0,0,0,0><<<dim3(16, 8, B_), 512, SMEM_GEMM>>>(
        q, D_, sQ, k_hi, k_lo, D_, sQ,
        sc, nullptr, nullptr, S_, sS, nullptr, nullptr, D_);

    // softmax -> probs single
    softmax_kernel<<<B_ * S_, 256>>>(sc, p, 1.0f / sqrtf((float)D_));

    // y = probs . v  (A = probs single, B = vt hi/lo)
    gemm_mma<0,0,0,1><<<dim3(6, 8, B_), 512, SMEM_GEMM>>>(
        p, S_, sS, vt_hi, vt_lo, NT_, S_,
        nullptr, y, nullptr, D_, sQ, nullptr, nullptr, S_);

    // x1 = x + y . Wo + bo
    tsplit_kernel<<<dim3(24, 24), 256>>>(Wo, wot_hi, wot_lo, D_, D_);
    gemm_mma<1,0,1,0><<<dim3(6, 64, 1), 512, SMEM_GEMM>>>(
        y, D_, 0, wot_hi, wot_lo, D_, 0,
        x1, nullptr, nullptr, D_, 0, bo, x, D_);

    // LN2 -> h2 single
    ln_kernel<0><<<NT_, 256>>>(x1, ln2g, ln2b, h2, nullptr);

    // m = GELU(h2 . Wfc + bfc)  (single out)
    tsplit_kernel<<<dim3(96, 24), 256>>>(Wfc, wfct_hi, wfct_lo, D_, H_);
    gemm_mma<1,1,0,1><<<dim3(24, 64, 1), 512, SMEM_GEMM>>>(
        h2, D_, 0, wfct_hi, wfct_lo, D_, 0,
        nullptr, m, nullptr, H_, 0, bfc, nullptr, D_);

    // out = x1 + m . Wproj + bproj
    tsplit_kernel<<<dim3(24, 96), 256>>>(Wproj, wpt_hi, wpt_lo, H_, D_);
    gemm_mma<1,0,1,0><<<dim3(6, 64, 1), 512, SMEM_GEMM>>>(
        m, H_, 0, wpt_hi, wpt_lo, H_, 0,
        out, nullptr, nullptr, D_, 0, bproj, x1, H_);
}

// round 7
// speedup vs baseline: 5.8651x; 1.5310x over previous
#include <cuda_runtime.h>
#include <cuda_fp16.h>
#include <math.h>
#include <stdint.h>

// Problem dims
#define B_   8
#define S_   2048
#define D_   768
#define H_   3072
#define NT_  (B_ * S_)         // 16384 tokens
#define EPS_ 1e-5f

// ---------------------------------------------------------------------------
// Scratch (device globals) — all activations single fp16
// ---------------------------------------------------------------------------
__device__ unsigned short g_h [NT_ * D_];                 // LN1 out
__device__ unsigned short g_q [NT_ * D_];
__device__ unsigned short g_k [NT_ * D_];
__device__ unsigned short g_vt[NT_ * D_];                 // [D, B*S]
__device__ float          g_sc[(size_t)B_ * S_ * S_];
__device__ unsigned short g_p [(size_t)B_ * S_ * S_];
__device__ unsigned short g_y [NT_ * D_];
__device__ float          g_x1[NT_ * D_];
__device__ unsigned short g_h2[NT_ * D_];
__device__ unsigned short g_m [(size_t)NT_ * H_];
// transposed weights [N,K] fp16
__device__ unsigned short g_wqt[D_ * D_];
__device__ unsigned short g_wkt[D_ * D_];
__device__ unsigned short g_wvt[D_ * D_];
__device__ unsigned short g_wot[D_ * D_];
__device__ unsigned short g_wfct[H_ * D_];
__device__ unsigned short g_wprojt[D_ * H_];

// ---------------------------------------------------------------------------
// PTX helpers
// ---------------------------------------------------------------------------
__device__ __forceinline__ void cp16(uint32_t dst, const void* src) {
    asm volatile("cp.async.cg.shared.global [%0], [%1], 16;" :: "r"(dst), "l"(src));
}
__device__ __forceinline__ void cp_commit() { asm volatile("cp.async.commit_group;" ::: "memory"); }
__device__ __forceinline__ void cp_wait0()  { asm volatile("cp.async.wait_group 0;"  ::: "memory"); }
__device__ __forceinline__ void cp_wait1()  { asm volatile("cp.async.wait_group 1;"  ::: "memory"); }
__device__ __forceinline__ void cp_wait2()  { asm volatile("cp.async.wait_group 2;"  ::: "memory"); }

__device__ __forceinline__ void ldm4(uint32_t (&r)[4], uint32_t addr) {
    asm volatile("ldmatrix.sync.aligned.m8n8.x4.shared.b16 {%0,%1,%2,%3}, [%4];"
                 : "=r"(r[0]), "=r"(r[1]), "=r"(r[2]), "=r"(r[3]) : "r"(addr));
}
__device__ __forceinline__ void ldm2(uint32_t (&r)[2], uint32_t addr) {
    asm volatile("ldmatrix.sync.aligned.m8n8.x2.shared.b16 {%0,%1}, [%2];"
                 : "=r"(r[0]), "=r"(r[1]) : "r"(addr));
}
__device__ __forceinline__ void mma16816(float (&c)[4], const uint32_t (&a)[4],
                                         const uint32_t (&b)[2]) {
    asm volatile("mma.sync.aligned.m16n8k16.row.col.f32.f16.f16.f32 "
                 "{%0,%1,%2,%3}, {%4,%5,%6,%7}, {%8,%9}, {%0,%1,%2,%3};"
                 : "+f"(c[0]), "+f"(c[1]), "+f"(c[2]), "+f"(c[3])
                 : "r"(a[0]), "r"(a[1]), "r"(a[2]), "r"(a[3]), "r"(b[0]), "r"(b[1]));
}
__device__ __forceinline__ uint32_t pack2h(__half a, __half b) {
    return ((uint32_t)__half_as_ushort(b) << 16) | __half_as_ushort(a);
}

// ---------------------------------------------------------------------------
// Tensor-core GEMM: C[M,N] = sum_k A[M,K]*B[N,K], plain fp16 operands
// tile 256x128, BK=32, 512 threads (16 warps 4x4), warp tile 64x32
// 4-stage cp.async pipeline.  PITCH=80 -> ldmatrix conflict-free.
// BIASM: 0 none, 1 col, 2 row.  OUTK: 0 fp32, 1 fp16
// ---------------------------------------------------------------------------
#define PITCH   80
#define ATILEB  (256 * PITCH)                 // 20480
#define BTILEB  (128 * PITCH)                 // 10240
#define STAGEB  (ATILEB + BTILEB)             // 30720
#define NSTAGE  4
#define SMEM_GEMM (NSTAGE * STAGEB)           // 122880

__device__ __forceinline__ void load_stage(uint32_t so, const __half* gA,
                                           long ldA, const __half* gB,
                                           long ldB, int k0) {
    int tid = threadIdx.x;
#pragma unroll
    for (int i = 0; i < 2; i++) {            // A: 256 rows x 32 cols
        int idx = tid + i * 512;
        int row = idx >> 2, ch = idx & 3;
        cp16(so + row * PITCH + ch * 16, gA + (long)row * ldA + k0 + ch * 8);
    }
    {                                        // B: 128 rows x 32 cols
        int row = tid >> 2, ch = tid & 3;
        cp16(so + ATILEB + row * PITCH + ch * 16, gB + (long)row * ldB + k0 + ch * 8);
    }
}

template <int BIASM, int DOGELU, int DORES, int OUTK>
__global__ void __launch_bounds__(512, 1)
gemm_mma(const __half* __restrict__ A, long ldA, long sA,
         const __half* __restrict__ Bm, long ldB, long sB,
         float* __restrict__ Cf, __half* __restrict__ Ch,
         long ldC, long sC,
         const float* __restrict__ bias, const float* __restrict__ res, int K)
{
    extern __shared__ char smem[];
    uint32_t sb = (uint32_t)__cvta_generic_to_shared(smem);
    int tid = threadIdx.x, lane = tid & 31, wid = tid >> 5;
    int wm = wid & 3, wn = wid >> 2;
    long row0 = (long)blockIdx.y * 256, col0 = (long)blockIdx.x * 128;
    int bz = blockIdx.z;

    const __half* gA = A  + (long)bz * sA + row0 * ldA;
    const __half* gB = Bm + (long)bz * sB + col0 * ldB;

    float acc[4][4][4];
#pragma unroll
    for (int t = 0; t < 4; t++)
#pragma unroll
        for (int j = 0; j < 4; j++)
#pragma unroll
            for (int e = 0; e < 4; e++) acc[t][j][e] = 0.f;

    int a_row = wm * 64 + (lane & 15);
    int a_ch  = (lane >> 4) * 8;
    int b_row = wn * 32 + (lane & 7);
    int b_ch  = ((lane >> 3) & 1) * 8;

    int NC = K >> 5;
    // prologue: stages 0..2
#pragma unroll
    for (int s = 0; s < NSTAGE - 1; s++) {
        if (s < NC) {
            load_stage(sb + s * STAGEB, gA, ldA, gB, ldB, s * 32);
            cp_commit();
        }
    }

    for (int c = 0; c < NC; c++) {
        int rem = NC - 1 - c;
        if (rem >= 2) cp_wait2();
        else if (rem == 1) cp_wait1();
        else cp_wait0();
        __syncthreads();

        if (c + NSTAGE - 1 < NC) {
            load_stage(sb + ((c + NSTAGE - 1) % NSTAGE) * STAGEB,
                       gA, ldA, gB, ldB, (c + NSTAGE - 1) * 32);
            cp_commit();
        }

        uint32_t s0 = sb + (c % NSTAGE) * STAGEB;
#pragma unroll
        for (int kk = 0; kk < 32; kk += 16) {
            uint32_t ar[4][4];
#pragma unroll
            for (int t = 0; t < 4; t++)
                ldm4(ar[t], s0 + (a_row + t * 16) * PITCH + (a_ch + kk) * 2);
            uint32_t br[4][2];
#pragma unroll
            for (int j = 0; j < 4; j++)
                ldm2(br[j], s0 + ATILEB + (b_row + j * 8) * PITCH + (b_ch + kk) * 2);
#pragma unroll
            for (int t = 0; t < 4; t++)
#pragma unroll
                for (int j = 0; j < 4; j++)
                    mma16816(acc[t][j], ar[t], br[j]);
        }
    }

    // epilogue from registers, fused ops
#pragma unroll
    for (int t = 0; t < 4; t++)
#pragma unroll
        for (int j = 0; j < 4; j++) {
#pragma unroll
            for (int half = 0; half < 2; half++) {
                long r  = row0 + wm * 64 + t * 16 + (lane >> 2) + half * 8;
                long cc = col0 + wn * 32 + j * 8 + (lane & 3) * 2;
                float v0 = acc[t][j][half * 2 + 0];
                float v1 = acc[t][j][half * 2 + 1];
                if (BIASM == 1) { v0 += bias[cc]; v1 += bias[cc + 1]; }
                if (BIASM == 2) { float bb = bias[r]; v0 += bb; v1 += bb; }
                if (DOGELU) {
                    v0 = 0.5f * v0 * (1.f + erff(v0 * 0.70710678118654752f));
                    v1 = 0.5f * v1 * (1.f + erff(v1 * 0.70710678118654752f));
                }
                long off = (long)bz * sC + r * ldC + cc;
                if (DORES) {
                    float2 rv = *reinterpret_cast<const float2*>(res + off);
                    v0 += rv.x; v1 += rv.y;
                }
                if (OUTK == 0) {
                    *reinterpret_cast<float2*>(Cf + off) = make_float2(v0, v1);
                } else {
                    *reinterpret_cast<uint32_t*>(Ch + off) =
                        pack2h(__float2half(v0), __float2half(v1));
                }
            }
        }
}

// ---------------------------------------------------------------------------
// Transpose + convert:  W[K,N] fp32 -> out[N,K] fp16
// ---------------------------------------------------------------------------
__global__ void __launch_bounds__(256)
tconv_kernel(const float* __restrict__ W, __half* __restrict__ o, int K, int N)
{
    __shared__ float t[32][33];
    int n0 = blockIdx.x * 32, k0 = blockIdx.y * 32;
    int tx = threadIdx.x & 31, ty = threadIdx.x >> 5;
#pragma unroll
    for (int i = 0; i < 32; i += 8)
        t[ty + i][tx] = W[(long)(k0 + ty + i) * N + n0 + tx];
    __syncthreads();
#pragma unroll
    for (int i = 0; i < 32; i += 8)
        o[(long)(n0 + ty + i) * K + k0 + tx] = __float2half(t[tx][ty + i]);
}

// ---------------------------------------------------------------------------
// LayerNorm -> fp16
// ---------------------------------------------------------------------------
__global__ void __launch_bounds__(256)
ln_kernel(const float* __restrict__ x, const float* __restrict__ g,
          const float* __restrict__ b, __half* __restrict__ o)
{
    long row = blockIdx.x;
    const float* xr = x + row * D_;
    int t = threadIdx.x;
    float vals[3];
    float s = 0.f, s2 = 0.f;
#pragma unroll
    for (int i = 0; i < 3; i++) {
        float v = xr[t + i * 256];
        vals[i] = v; s += v; s2 += v * v;
    }
#pragma unroll
    for (int o2 = 16; o2 > 0; o2 >>= 1) {
        s  += __shfl_xor_sync(0xffffffffu, s,  o2);
        s2 += __shfl_xor_sync(0xffffffffu, s2, o2);
    }
    __shared__ float sm[8], sm2[8], stat[2];
    int w = t >> 5, l = t & 31;
    if (l == 0) { sm[w] = s; sm2[w] = s2; }
    __syncthreads();
    if (t == 0) {
        float a = 0.f, c = 0.f;
#pragma unroll
        for (int i = 0; i < 8; i++) { a += sm[i]; c += sm2[i]; }
        float mu = a / (float)D_;
        stat[0] = mu;
        stat[1] = rsqrtf(c / (float)D_ - mu * mu + EPS_);
    }
    __syncthreads();
    float mu = stat[0], rstd = stat[1];
#pragma unroll
    for (int i = 0; i < 3; i++) {
        int idx = t + i * 256;
        o[row * D_ + idx] = __float2half((vals[i] - mu) * rstd * g[idx] + b[idx]);
    }
}

// ---------------------------------------------------------------------------
// Softmax (with scale) -> fp16 probs
// ---------------------------------------------------------------------------
__global__ void __launch_bounds__(256)
softmax_kernel(const float* __restrict__ sc, __half* __restrict__ ph, float scale)
{
    long row = blockIdx.x;
    const float* p = sc + row * (long)S_;
    int t = threadIdx.x;
    float vals[8];
    float mx = -1e30f;
#pragma unroll
    for (int i = 0; i < 8; i++) {
        float v = p[t + i * 256];
        vals[i] = v; mx = fmaxf(mx, v);
    }
#pragma unroll
    for (int o = 16; o > 0; o >>= 1)
        mx = fmaxf(mx, __shfl_xor_sync(0xffffffffu, mx, o));
    __shared__ float sm[8], stat[1];
    int w = t >> 5, l = t & 31;
    if (l == 0) sm[w] = mx;
    __syncthreads();
    if (t == 0) {
        float m2 = sm[0];
#pragma unroll
        for (int i = 1; i < 8; i++) m2 = fmaxf(m2, sm[i]);
        stat[0] = m2;
    }
    __syncthreads();
    float rowmax = stat[0];
    float sum = 0.f;
#pragma unroll
    for (int i = 0; i < 8; i++) {
        float e = __expf((vals[i] - rowmax) * scale);
        vals[i] = e; sum += e;
    }
#pragma unroll
    for (int o = 16; o > 0; o >>= 1)
        sum += __shfl_xor_sync(0xffffffffu, sum, o);
    if (l == 0) sm[w] = sum;
    __syncthreads();
    if (t == 0) {
        float a = 0.f;
#pragma unroll
        for (int i = 0; i < 8; i++) a += sm[i];
        stat[0] = 1.f / a;
    }
    __syncthreads();
    float inv = stat[0];
#pragma unroll
    for (int i = 0; i < 8; i++)
        ph[row * (long)S_ + t + i * 256] = __float2half(vals[i] * inv);
}

// ---------------------------------------------------------------------------
// Launch
// ---------------------------------------------------------------------------
extern "C" void kernel_launch(void* const* d_in, const int* in_sizes, int n_in,
                              void* d_out, int out_size)
{
    const float* x     = (const float*)d_in[0];
    const float* ln1g  = (const float*)d_in[1];
    const float* ln1b  = (const float*)d_in[2];
    const float* ln2g  = (const float*)d_in[3];
    const float* ln2b  = (const float*)d_in[4];
    const float* Wq    = (const float*)d_in[5];
    const float* bq    = (const float*)d_in[6];
    const float* Wk    = (const float*)d_in[7];
    const float* bk    = (const float*)d_in[8];
    const float* Wv    = (const float*)d_in[9];
    const float* bv    = (const float*)d_in[10];
    const float* Wo    = (const float*)d_in[11];
    const float* bo    = (const float*)d_in[12];
    const float* Wfc   = (const float*)d_in[13];
    const float* bfc   = (const float*)d_in[14];
    const float* Wproj = (const float*)d_in[15];
    const float* bproj = (const float*)d_in[16];
    float* out = (float*)d_out;

    auto ga = [](const void* sym) { void* p; cudaGetSymbolAddress(&p, sym); return p; };
    __half *h  = (__half*)ga(g_h);
    __half *q  = (__half*)ga(g_q);
    __half *k  = (__half*)ga(g_k);
    __half *vt = (__half*)ga(g_vt);
    float  *sc = (float*)ga(g_sc);
    __half *p  = (__half*)ga(g_p);
    __half *y  = (__half*)ga(g_y);
    float  *x1 = (float*)ga(g_x1);
    __half *h2 = (__half*)ga(g_h2);
    __half *m  = (__half*)ga(g_m);
    __half *wqt = (__half*)ga(g_wqt);
    __half *wkt = (__half*)ga(g_wkt);
    __half *wvt = (__half*)ga(g_wvt);
    __half *wot = (__half*)ga(g_wot);
    __half *wfct = (__half*)ga(g_wfct);
    __half *wpt = (__half*)ga(g_wprojt);

    cudaFuncSetAttribute(gemm_mma<1,0,0,1>, cudaFuncAttributeMaxDynamicSharedMemorySize, SMEM_GEMM);
    cudaFuncSetAttribute(gemm_mma<2,0,0,1>, cudaFuncAttributeMaxDynamicSharedMemorySize, SMEM_GEMM);
    cudaFuncSetAttribute(gemm_mma<0,0,0,0>, cudaFuncAttributeMaxDynamicSharedMemorySize, SMEM_GEMM);
    cudaFuncSetAttribute(gemm_mma<0,0,0,1>, cudaFuncAttributeMaxDynamicSharedMemorySize, SMEM_GEMM);
    cudaFuncSetAttribute(gemm_mma<1,0,1,0>, cudaFuncAttributeMaxDynamicSharedMemorySize, SMEM_GEMM);
    cudaFuncSetAttribute(gemm_mma<1,1,0,1>, cudaFuncAttributeMaxDynamicSharedMemorySize, SMEM_GEMM);

    const long sQ = (long)S_ * D_;
    const long sS = (long)S_ * S_;

    // LN1
    ln_kernel<<<NT_, 256>>>(x, ln1g, ln1b, h);

    // weight transpose+convert q/k/v
    tconv_kernel<<<dim3(24, 24), 256>>>(Wq, wqt, D_, D_);
    tconv_kernel<<<dim3(24, 24), 256>>>(Wk, wkt, D_, D_);
    tconv_kernel<<<dim3(24, 24), 256>>>(Wv, wvt, D_, D_);

    // q, k
    gemm_mma<1,0,0,1><<<dim3(6, 64, 1), 512, SMEM_GEMM>>>(
        h, D_, 0, wqt, D_, 0, nullptr, q, D_, 0, bq, nullptr, D_);
    gemm_mma<1,0,0,1><<<dim3(6, 64, 1), 512, SMEM_GEMM>>>(
        h, D_, 0, wkt, D_, 0, nullptr, k, D_, 0, bk, nullptr, D_);

    // v^T = Wv^T . h^T  ([768, 16384], row bias)
    gemm_mma<2,0,0,1><<<dim3(128, 3, 1), 512, SMEM_GEMM>>>(
        wvt, D_, 0, h, D_, 0, nullptr, vt, NT_, 0, bv, nullptr, D_);

    // scores = q . k^T (batched, fp32)
    gemm_mma<0,0,0,0><<<dim3(16, 8, B_), 512, SMEM_GEMM>>>(
        q, D_, sQ, k, D_, sQ, sc, nullptr, S_, sS, nullptr, nullptr, D_);

    // softmax -> probs fp16
    softmax_kernel<<<B_ * S_, 256>>>(sc, p, 1.0f / sqrtf((float)D_));

    // y = probs . v
    gemm_mma<0,0,0,1><<<dim3(6, 8, B_), 512, SMEM_GEMM>>>(
        p, S_, sS, vt, NT_, S_, nullptr, y, D_, sQ, nullptr, nullptr, S_);

    // x1 = x + y . Wo + bo
    tconv_kernel<<<dim3(24, 24), 256>>>(Wo, wot, D_, D_);
    gemm_mma<1,0,1,0><<<dim3(6, 64, 1), 512, SMEM_GEMM>>>(
        y, D_, 0, wot, D_, 0, x1, nullptr, D_, 0, bo, x, D_);

    // LN2
    ln_kernel<<<NT_, 256>>>(x1, ln2g, ln2b, h2);

    // m = GELU(h2 . Wfc + bfc)
    tconv_kernel<<<dim3(96, 24), 256>>>(Wfc, wfct, D_, H_);
    gemm_mma<1,1,0,1><<<dim3(24, 64, 1), 512, SMEM_GEMM>>>(
        h2, D_, 0, wfct, H_ == 0 ? 0 : D_, 0, nullptr, m, H_, 0, bfc, nullptr, D_);

    // out = x1 + m . Wproj + bproj
    tconv_kernel<<<dim3(24, 96), 256>>>(Wproj, wpt, H_, D_);
    gemm_mma<1,0,1,0><<<dim3(6, 64, 1), 512, SMEM_GEMM>>>(
        m, H_, 0, wpt, H_, 0, out, nullptr, D_, 0, bproj, x1, H_);
}

// round 9
// speedup vs baseline: 6.1042x; 1.0408x over previous
#include <cuda_runtime.h>
#include <cuda_fp16.h>
#include <math.h>
#include <stdint.h>

// Problem dims
#define B_   8
#define S_   2048
#define D_   768
#define H_   3072
#define NT_  (B_ * S_)         // 16384 tokens
#define EPS_ 1e-5f

// ---------------------------------------------------------------------------
// Scratch (device globals) — activations fp16
// ---------------------------------------------------------------------------
__device__ unsigned short g_h  [NT_ * D_];                // LN1 out
__device__ unsigned short g_qk [NT_ * 2 * D_];            // [NT, 1536]: q | k
__device__ unsigned short g_vt [NT_ * D_];                // [D, B*S]
__device__ unsigned short g_sch[(size_t)B_ * S_ * S_];    // fp16 scores -> probs (in-place)
__device__ unsigned short g_y  [NT_ * D_];
__device__ float          g_x1 [NT_ * D_];
__device__ unsigned short g_h2 [NT_ * D_];
__device__ unsigned short g_m  [(size_t)NT_ * H_];
// transposed weights [N,K] fp16
__device__ unsigned short g_wqkt[2 * D_ * D_];            // [1536, 768]
__device__ unsigned short g_wvt [D_ * D_];
__device__ unsigned short g_wot [D_ * D_];
__device__ unsigned short g_wfct[H_ * D_];
__device__ unsigned short g_wprojt[D_ * H_];
__device__ float          g_bqk[2 * D_];

// ---------------------------------------------------------------------------
// PTX helpers
// ---------------------------------------------------------------------------
__device__ __forceinline__ void cp16(uint32_t dst, const void* src) {
    asm volatile("cp.async.cg.shared.global [%0], [%1], 16;" :: "r"(dst), "l"(src));
}
__device__ __forceinline__ void cp_commit() { asm volatile("cp.async.commit_group;" ::: "memory"); }
__device__ __forceinline__ void cp_wait0()  { asm volatile("cp.async.wait_group 0;"  ::: "memory"); }
__device__ __forceinline__ void cp_wait1()  { asm volatile("cp.async.wait_group 1;"  ::: "memory"); }
__device__ __forceinline__ void cp_wait2()  { asm volatile("cp.async.wait_group 2;"  ::: "memory"); }

__device__ __forceinline__ void ldm4(uint32_t (&r)[4], uint32_t addr) {
    asm volatile("ldmatrix.sync.aligned.m8n8.x4.shared.b16 {%0,%1,%2,%3}, [%4];"
                 : "=r"(r[0]), "=r"(r[1]), "=r"(r[2]), "=r"(r[3]) : "r"(addr));
}
__device__ __forceinline__ void mma16816(float (&c)[4], const uint32_t (&a)[4],
                                         const uint32_t (&b)[2]) {
    asm volatile("mma.sync.aligned.m16n8k16.row.col.f32.f16.f16.f32 "
                 "{%0,%1,%2,%3}, {%4,%5,%6,%7}, {%8,%9}, {%0,%1,%2,%3};"
                 : "+f"(c[0]), "+f"(c[1]), "+f"(c[2]), "+f"(c[3])
                 : "r"(a[0]), "r"(a[1]), "r"(a[2]), "r"(a[3]), "r"(b[0]), "r"(b[1]));
}
__device__ __forceinline__ uint32_t pack2h(__half a, __half b) {
    return ((uint32_t)__half_as_ushort(b) << 16) | __half_as_ushort(a);
}

// ---------------------------------------------------------------------------
// Tensor-core GEMM: C[M,N] = alpha * (sum_k A[M,K]*B[N,K]) (+bias)(+gelu)(+res)
// tile 256x128, BK=32, 512 threads (16 warps 4x4), warp tile 64x32
// 4-stage cp.async.  PITCH=80 -> ldmatrix conflict-free.
// BIASM: 0 none, 1 col, 2 row.  OUTK: 0 fp32, 1 fp16
// ---------------------------------------------------------------------------
#define PITCH   80
#define ATILEB  (256 * PITCH)
#define BTILEB  (128 * PITCH)
#define STAGEB  (ATILEB + BTILEB)             // 30720
#define NSTAGE  4
#define SMEM_GEMM (NSTAGE * STAGEB)           // 122880

__device__ __forceinline__ void load_stage(uint32_t so, const __half* gA,
                                           long ldA, const __half* gB,
                                           long ldB, int k0) {
    int tid = threadIdx.x;
#pragma unroll
    for (int i = 0; i < 2; i++) {
        int idx = tid + i * 512;
        int row = idx >> 2, ch = idx & 3;
        cp16(so + row * PITCH + ch * 16, gA + (long)row * ldA + k0 + ch * 8);
    }
    {
        int row = tid >> 2, ch = tid & 3;
        cp16(so + ATILEB + row * PITCH + ch * 16, gB + (long)row * ldB + k0 + ch * 8);
    }
}

template <int BIASM, int DOGELU, int DORES, int OUTK>
__global__ void __launch_bounds__(512, 1)
gemm_mma(const __half* __restrict__ A, long ldA, long sA,
         const __half* __restrict__ Bm, long ldB, long sB,
         float* __restrict__ Cf, __half* __restrict__ Ch,
         long ldC, long sC,
         const float* __restrict__ bias, const float* __restrict__ res,
         float alpha, int K)
{
    extern __shared__ char smem[];
    uint32_t sb = (uint32_t)__cvta_generic_to_shared(smem);
    int tid = threadIdx.x, lane = tid & 31, wid = tid >> 5;
    int wm = wid & 3, wn = wid >> 2;
    long row0 = (long)blockIdx.y * 256, col0 = (long)blockIdx.x * 128;
    int bz = blockIdx.z;

    const __half* gA = A  + (long)bz * sA + row0 * ldA;
    const __half* gB = Bm + (long)bz * sB + col0 * ldB;

    float acc[4][4][4];
#pragma unroll
    for (int t = 0; t < 4; t++)
#pragma unroll
        for (int j = 0; j < 4; j++)
#pragma unroll
            for (int e = 0; e < 4; e++) acc[t][j][e] = 0.f;

    int a_row  = wm * 64 + (lane & 15);
    int a_ch   = (lane >> 4) * 8;
    int b_row4 = wn * 32 + (lane & 7) + ((lane >> 4) << 3);  // ldm4 covers 2 j's
    int b_ch4  = ((lane >> 3) & 1) * 8;

    int NC = K >> 5;
#pragma unroll
    for (int s = 0; s < NSTAGE - 1; s++) {
        if (s < NC) {
            load_stage(sb + s * STAGEB, gA, ldA, gB, ldB, s * 32);
            cp_commit();
        }
    }

    for (int c = 0; c < NC; c++) {
        int rem = NC - 1 - c;
        if (rem >= 2) cp_wait2();
        else if (rem == 1) cp_wait1();
        else cp_wait0();
        __syncthreads();

        if (c + NSTAGE - 1 < NC) {
            load_stage(sb + ((c + NSTAGE - 1) % NSTAGE) * STAGEB,
                       gA, ldA, gB, ldB, (c + NSTAGE - 1) * 32);
            cp_commit();
        }

        uint32_t s0 = sb + (c % NSTAGE) * STAGEB;
#pragma unroll
        for (int kk = 0; kk < 32; kk += 16) {
            uint32_t ar[4][4];
#pragma unroll
            for (int t = 0; t < 4; t++)
                ldm4(ar[t], s0 + (a_row + t * 16) * PITCH + (a_ch + kk) * 2);
            uint32_t br[4][2];
#pragma unroll
            for (int j2 = 0; j2 < 2; j2++) {
                uint32_t r4[4];
                ldm4(r4, s0 + ATILEB + (b_row4 + j2 * 16) * PITCH + (b_ch4 + kk) * 2);
                br[j2 * 2 + 0][0] = r4[0]; br[j2 * 2 + 0][1] = r4[1];
                br[j2 * 2 + 1][0] = r4[2]; br[j2 * 2 + 1][1] = r4[3];
            }
#pragma unroll
            for (int t = 0; t < 4; t++)
#pragma unroll
                for (int j = 0; j < 4; j++)
                    mma16816(acc[t][j], ar[t], br[j]);
        }
    }

    // epilogue from registers, fused ops
#pragma unroll
    for (int t = 0; t < 4; t++)
#pragma unroll
        for (int j = 0; j < 4; j++) {
#pragma unroll
            for (int half = 0; half < 2; half++) {
                long r  = row0 + wm * 64 + t * 16 + (lane >> 2) + half * 8;
                long cc = col0 + wn * 32 + j * 8 + (lane & 3) * 2;
                float v0 = acc[t][j][half * 2 + 0] * alpha;
                float v1 = acc[t][j][half * 2 + 1] * alpha;
                if (BIASM == 1) { v0 += bias[cc]; v1 += bias[cc + 1]; }
                if (BIASM == 2) { float bb = bias[r]; v0 += bb; v1 += bb; }
                if (DOGELU) {
                    v0 = 0.5f * v0 * (1.f + erff(v0 * 0.70710678118654752f));
                    v1 = 0.5f * v1 * (1.f + erff(v1 * 0.70710678118654752f));
                }
                long off = (long)bz * sC + r * ldC + cc;
                if (DORES) {
                    float2 rv = *reinterpret_cast<const float2*>(res + off);
                    v0 += rv.x; v1 += rv.y;
                }
                if (OUTK == 0) {
                    *reinterpret_cast<float2*>(Cf + off) = make_float2(v0, v1);
                } else {
                    *reinterpret_cast<uint32_t*>(Ch + off) =
                        pack2h(__float2half(v0), __float2half(v1));
                }
            }
        }
}

// ---------------------------------------------------------------------------
// Transpose + convert, 4 weights (768x768 each) in one launch via blockIdx.z
// ---------------------------------------------------------------------------
__global__ void __launch_bounds__(256)
tconv4_kernel(const float* __restrict__ s0, const float* __restrict__ s1,
              const float* __restrict__ s2, const float* __restrict__ s3,
              __half* __restrict__ d0, __half* __restrict__ d1,
              __half* __restrict__ d2, __half* __restrict__ d3)
{
    int z = blockIdx.z;
    const float* W = (z == 0) ? s0 : (z == 1) ? s1 : (z == 2) ? s2 : s3;
    __half* o      = (z == 0) ? d0 : (z == 1) ? d1 : (z == 2) ? d2 : d3;
    __shared__ float t[32][33];
    int n0 = blockIdx.x * 32, k0 = blockIdx.y * 32;
    int tx = threadIdx.x & 31, ty = threadIdx.x >> 5;
#pragma unroll
    for (int i = 0; i < 32; i += 8)
        t[ty + i][tx] = W[(long)(k0 + ty + i) * D_ + n0 + tx];
    __syncthreads();
#pragma unroll
    for (int i = 0; i < 32; i += 8)
        o[(long)(n0 + ty + i) * D_ + k0 + tx] = __float2half(t[tx][ty + i]);
}

// Generic single transpose+convert: W[K,N] fp32 -> out[N,K] fp16
__global__ void __launch_bounds__(256)
tconv_kernel(const float* __restrict__ W, __half* __restrict__ o, int K, int N)
{
    __shared__ float t[32][33];
    int n0 = blockIdx.x * 32, k0 = blockIdx.y * 32;
    int tx = threadIdx.x & 31, ty = threadIdx.x >> 5;
#pragma unroll
    for (int i = 0; i < 32; i += 8)
        t[ty + i][tx] = W[(long)(k0 + ty + i) * N + n0 + tx];
    __syncthreads();
#pragma unroll
    for (int i = 0; i < 32; i += 8)
        o[(long)(n0 + ty + i) * K + k0 + tx] = __float2half(t[tx][ty + i]);
}

// concat bq|bk -> bqk[1536]
__global__ void __launch_bounds__(256)
concat2_kernel(const float* __restrict__ a, const float* __restrict__ b,
               float* __restrict__ o)
{
    int i = blockIdx.x * 256 + threadIdx.x;
    if (i < D_) o[i] = a[i];
    else if (i < 2 * D_) o[i] = b[i - D_];
}

// ---------------------------------------------------------------------------
// LayerNorm -> fp16
// ---------------------------------------------------------------------------
__global__ void __launch_bounds__(256)
ln_kernel(const float* __restrict__ x, const float* __restrict__ g,
          const float* __restrict__ b, __half* __restrict__ o)
{
    long row = blockIdx.x;
    const float* xr = x + row * D_;
    int t = threadIdx.x;
    float vals[3];
    float s = 0.f, s2 = 0.f;
#pragma unroll
    for (int i = 0; i < 3; i++) {
        float v = xr[t + i * 256];
        vals[i] = v; s += v; s2 += v * v;
    }
#pragma unroll
    for (int o2 = 16; o2 > 0; o2 >>= 1) {
        s  += __shfl_xor_sync(0xffffffffu, s,  o2);
        s2 += __shfl_xor_sync(0xffffffffu, s2, o2);
    }
    __shared__ float sm[8], sm2[8], stat[2];
    int w = t >> 5, l = t & 31;
    if (l == 0) { sm[w] = s; sm2[w] = s2; }
    __syncthreads();
    if (t == 0) {
        float a = 0.f, c = 0.f;
#pragma unroll
        for (int i = 0; i < 8; i++) { a += sm[i]; c += sm2[i]; }
        float mu = a / (float)D_;
        stat[0] = mu;
        stat[1] = rsqrtf(c / (float)D_ - mu * mu + EPS_);
    }
    __syncthreads();
    float mu = stat[0], rstd = stat[1];
#pragma unroll
    for (int i = 0; i < 3; i++) {
        int idx = t + i * 256;
        o[row * D_ + idx] = __float2half((vals[i] - mu) * rstd * g[idx] + b[idx]);
    }
}

// ---------------------------------------------------------------------------
// Softmax over fp16 scores, in place (scale pre-applied in GEMM epilogue)
// ---------------------------------------------------------------------------
__global__ void __launch_bounds__(256)
softmax_kernel(__half* __restrict__ sc)
{
    long row = blockIdx.x;
    __half* p = sc + row * (long)S_;
    int t = threadIdx.x;
    float vals[8];
    float mx = -1e30f;
#pragma unroll
    for (int i = 0; i < 8; i++) {
        float v = __half2float(p[t + i * 256]);
        vals[i] = v; mx = fmaxf(mx, v);
    }
#pragma unroll
    for (int o = 16; o > 0; o >>= 1)
        mx = fmaxf(mx, __shfl_xor_sync(0xffffffffu, mx, o));
    __shared__ float sm[8], stat[1];
    int w = t >> 5, l = t & 31;
    if (l == 0) sm[w] = mx;
    __syncthreads();
    if (t == 0) {
        float m2 = sm[0];
#pragma unroll
        for (int i = 1; i < 8; i++) m2 = fmaxf(m2, sm[i]);
        stat[0] = m2;
    }
    __syncthreads();
    float rowmax = stat[0];
    float sum = 0.f;
#pragma unroll
    for (int i = 0; i < 8; i++) {
        float e = __expf(vals[i] - rowmax);
        vals[i] = e; sum += e;
    }
#pragma unroll
    for (int o = 16; o > 0; o >>= 1)
        sum += __shfl_xor_sync(0xffffffffu, sum, o);
    if (l == 0) sm[w] = sum;
    __syncthreads();
    if (t == 0) {
        float a = 0.f;
#pragma unroll
        for (int i = 0; i < 8; i++) a += sm[i];
        stat[0] = 1.f / a;
    }
    __syncthreads();
    float inv = stat[0];
#pragma unroll
    for (int i = 0; i < 8; i++)
        p[t + i * 256] = __float2half(vals[i] * inv);
}

// ---------------------------------------------------------------------------
// Launch
// ---------------------------------------------------------------------------
extern "C" void kernel_launch(void* const* d_in, const int* in_sizes, int n_in,
                              void* d_out, int out_size)
{
    const float* x     = (const float*)d_in[0];
    const float* ln1g  = (const float*)d_in[1];
    const float* ln1b  = (const float*)d_in[2];
    const float* ln2g  = (const float*)d_in[3];
    const float* ln2b  = (const float*)d_in[4];
    const float* Wq    = (const float*)d_in[5];
    const float* bq    = (const float*)d_in[6];
    const float* Wk    = (const float*)d_in[7];
    const float* bk    = (const float*)d_in[8];
    const float* Wv    = (const float*)d_in[9];
    const float* bv    = (const float*)d_in[10];
    const float* Wo    = (const float*)d_in[11];
    const float* bo    = (const float*)d_in[12];
    const float* Wfc   = (const float*)d_in[13];
    const float* bfc   = (const float*)d_in[14];
    const float* Wproj = (const float*)d_in[15];
    const float* bproj = (const float*)d_in[16];
    float* out = (float*)d_out;

    auto ga = [](const void* sym) { void* p; cudaGetSymbolAddress(&p, sym); return p; };
    __half *h   = (__half*)ga(g_h);
    __half *qk  = (__half*)ga(g_qk);
    __half *vt  = (__half*)ga(g_vt);
    __half *sch = (__half*)ga(g_sch);
    __half *y   = (__half*)ga(g_y);
    float  *x1  = (float*)ga(g_x1);
    __half *h2  = (__half*)ga(g_h2);
    __half *m   = (__half*)ga(g_m);
    __half *wqkt = (__half*)ga(g_wqkt);
    __half *wvt  = (__half*)ga(g_wvt);
    __half *wot  = (__half*)ga(g_wot);
    __half *wfct = (__half*)ga(g_wfct);
    __half *wpt  = (__half*)ga(g_wprojt);
    float  *bqk  = (float*)ga(g_bqk);

    cudaFuncSetAttribute(gemm_mma<1,0,0,1>, cudaFuncAttributeMaxDynamicSharedMemorySize, SMEM_GEMM);
    cudaFuncSetAttribute(gemm_mma<2,0,0,1>, cudaFuncAttributeMaxDynamicSharedMemorySize, SMEM_GEMM);
    cudaFuncSetAttribute(gemm_mma<0,0,0,1>, cudaFuncAttributeMaxDynamicSharedMemorySize, SMEM_GEMM);
    cudaFuncSetAttribute(gemm_mma<1,0,1,0>, cudaFuncAttributeMaxDynamicSharedMemorySize, SMEM_GEMM);
    cudaFuncSetAttribute(gemm_mma<1,1,0,1>, cudaFuncAttributeMaxDynamicSharedMemorySize, SMEM_GEMM);

    const long sQ  = (long)S_ * D_;
    const long sQK = (long)S_ * 2 * D_;
    const long sS  = (long)S_ * S_;

    // LN1
    ln_kernel<<<NT_, 256>>>(x, ln1g, ln1b, h);

    // transpose+convert Wq,Wk,Wv,Wo (one launch) + concat bias
    tconv4_kernel<<<dim3(24, 24, 4), 256>>>(Wq, Wk, Wv, Wo,
                                            wqkt, wqkt + D_ * D_, wvt, wot);
    concat2_kernel<<<6, 256>>>(bq, bk, bqk);

    // fused qk = h . [Wq|Wk]  -> g_qk [NT, 1536]
    gemm_mma<1,0,0,1><<<dim3(12, 64, 1), 512, SMEM_GEMM>>>(
        h, D_, 0, wqkt, D_, 0, nullptr, qk, 2 * D_, 0, bqk, nullptr, 1.f, D_);

    // v^T = Wv^T . h^T  ([768, 16384], row bias)
    gemm_mma<2,0,0,1><<<dim3(128, 3, 1), 512, SMEM_GEMM>>>(
        wvt, D_, 0, h, D_, 0, nullptr, vt, NT_, 0, bv, nullptr, 1.f, D_);

    // scores = (q . k^T) * 1/sqrt(D)  (batched, fp16 out, scale fused)
    gemm_mma<0,0,0,1><<<dim3(16, 8, B_), 512, SMEM_GEMM>>>(
        qk, 2 * D_, sQK, qk + D_, 2 * D_, sQK,
        nullptr, sch, S_, sS, nullptr, nullptr, 1.0f / sqrtf((float)D_), D_);

    // softmax in-place (fp16)
    softmax_kernel<<<B_ * S_, 256>>>(sch);

    // y = probs . v
    gemm_mma<0,0,0,1><<<dim3(6, 8, B_), 512, SMEM_GEMM>>>(
        sch, S_, sS, vt, NT_, S_, nullptr, y, D_, sQ, nullptr, nullptr, 1.f, S_);

    // x1 = x + y . Wo + bo
    gemm_mma<1,0,1,0><<<dim3(6, 64, 1), 512, SMEM_GEMM>>>(
        y, D_, 0, wot, D_, 0, x1, nullptr, D_, 0, bo, x, 1.f, D_);

    // LN2
    ln_kernel<<<NT_, 256>>>(x1, ln2g, ln2b, h2);

    // m = GELU(h2 . Wfc + bfc)
    tconv_kernel<<<dim3(96, 24), 256>>>(Wfc, wfct, D_, H_);
    gemm_mma<1,1,0,1><<<dim3(24, 64, 1), 512, SMEM_GEMM>>>(
        h2, D_, 0, wfct, D_, 0, nullptr, m, H_, 0, bfc, nullptr, 1.f, D_);

    // out = x1 + m . Wproj + bproj
    tconv_kernel<<<dim3(24, 96), 256>>>(Wproj, wpt, H_, D_);
    gemm_mma<1,0,1,0><<<dim3(6, 64, 1), 512, SMEM_GEMM>>>(
        m, H_, 0, wpt, H_, 0, out, nullptr, D_, 0, bproj, x1, 1.f, H_);
}

// round 10
// speedup vs baseline: 6.9574x; 1.1398x over previous
#include <cuda_runtime.h>
#include <cuda_fp16.h>
#include <math.h>
#include <stdint.h>

// Problem dims
#define B_   8
#define S_   2048
#define D_   768
#define H_   3072
#define NT_  (B_ * S_)         // 16384 tokens
#define EPS_ 1e-5f

// ---------------------------------------------------------------------------
// Scratch (device globals) — activations fp16
// ---------------------------------------------------------------------------
__device__ unsigned short g_h  [NT_ * D_];                // LN1 out
__device__ unsigned short g_qk [NT_ * 2 * D_];            // [NT, 1536]: q | k
__device__ unsigned short g_vt [NT_ * D_];                // [D, B*S]
__device__ unsigned short g_sch[(size_t)B_ * S_ * S_];    // fp16 scores -> probs (in-place)
__device__ unsigned short g_y  [NT_ * D_];
__device__ float          g_x1 [NT_ * D_];
__device__ unsigned short g_h2 [NT_ * D_];
__device__ unsigned short g_m  [(size_t)NT_ * H_];
// transposed weights [N,K] fp16
__device__ unsigned short g_wqkt[2 * D_ * D_];            // [1536, 768]
__device__ unsigned short g_wvt [D_ * D_];
__device__ unsigned short g_wot [D_ * D_];
__device__ unsigned short g_wfct[H_ * D_];
__device__ unsigned short g_wprojt[D_ * H_];
__device__ float          g_bqk[2 * D_];

// ---------------------------------------------------------------------------
// PTX helpers
// ---------------------------------------------------------------------------
__device__ __forceinline__ void cp16(uint32_t dst, const void* src) {
    asm volatile("cp.async.cg.shared.global [%0], [%1], 16;" :: "r"(dst), "l"(src));
}
__device__ __forceinline__ void cp_commit() { asm volatile("cp.async.commit_group;" ::: "memory"); }
__device__ __forceinline__ void cp_wait0()  { asm volatile("cp.async.wait_group 0;"  ::: "memory"); }
__device__ __forceinline__ void cp_wait1()  { asm volatile("cp.async.wait_group 1;"  ::: "memory"); }

__device__ __forceinline__ void ldm4(uint32_t (&r)[4], uint32_t addr) {
    asm volatile("ldmatrix.sync.aligned.m8n8.x4.shared.b16 {%0,%1,%2,%3}, [%4];"
                 : "=r"(r[0]), "=r"(r[1]), "=r"(r[2]), "=r"(r[3]) : "r"(addr));
}
__device__ __forceinline__ void mma16816(float (&c)[4], const uint32_t (&a)[4],
                                         const uint32_t (&b)[2]) {
    asm volatile("mma.sync.aligned.m16n8k16.row.col.f32.f16.f16.f32 "
                 "{%0,%1,%2,%3}, {%4,%5,%6,%7}, {%8,%9}, {%0,%1,%2,%3};"
                 : "+f"(c[0]), "+f"(c[1]), "+f"(c[2]), "+f"(c[3])
                 : "r"(a[0]), "r"(a[1]), "r"(a[2]), "r"(a[3]), "r"(b[0]), "r"(b[1]));
}
__device__ __forceinline__ uint32_t pack2h(__half a, __half b) {
    return ((uint32_t)__half_as_ushort(b) << 16) | __half_as_ushort(a);
}

// ---------------------------------------------------------------------------
// Tensor-core GEMM: C[M,N] = alpha * (sum_k A[M,K]*B[N,K]) (+bias)(+gelu)(+res)
// tile 256x128, BK=64, 512 threads (16 warps 4x4), warp tile 64x32
// 3-stage cp.async, one __syncthreads per 4 k16-steps.
// PITCH=144 (stride 9 x 16B) -> ldmatrix conflict-free for 64-elem rows.
// BIASM: 0 none, 1 col, 2 row.  OUTK: 0 fp32, 1 fp16
// ---------------------------------------------------------------------------
#define PITCH   144
#define ATILEB  (256 * PITCH)                 // 36864
#define BTILEB  (128 * PITCH)                 // 18432
#define STAGEB  (ATILEB + BTILEB)             // 55296
#define NSTAGE  3
#define SMEM_GEMM (NSTAGE * STAGEB)           // 165888

__device__ __forceinline__ void load_stage(uint32_t so, const __half* gA,
                                           long ldA, const __half* gB,
                                           long ldB, int k0) {
    int tid = threadIdx.x;
#pragma unroll
    for (int i = 0; i < 4; i++) {            // A: 256 rows x 64 cols
        int idx = tid + i * 512;
        int row = idx >> 3, ch = idx & 7;
        cp16(so + row * PITCH + ch * 16, gA + (long)row * ldA + k0 + ch * 8);
    }
#pragma unroll
    for (int i = 0; i < 2; i++) {            // B: 128 rows x 64 cols
        int idx = tid + i * 512;
        int row = idx >> 3, ch = idx & 7;
        cp16(so + ATILEB + row * PITCH + ch * 16, gB + (long)row * ldB + k0 + ch * 8);
    }
}

template <int BIASM, int DOGELU, int DORES, int OUTK>
__global__ void __launch_bounds__(512, 1)
gemm_mma(const __half* __restrict__ A, long ldA, long sA,
         const __half* __restrict__ Bm, long ldB, long sB,
         float* __restrict__ Cf, __half* __restrict__ Ch,
         long ldC, long sC,
         const float* __restrict__ bias, const float* __restrict__ res,
         float alpha, int K)
{
    extern __shared__ char smem[];
    uint32_t sb = (uint32_t)__cvta_generic_to_shared(smem);
    int tid = threadIdx.x, lane = tid & 31, wid = tid >> 5;
    int wm = wid & 3, wn = wid >> 2;
    long row0 = (long)blockIdx.y * 256, col0 = (long)blockIdx.x * 128;
    int bz = blockIdx.z;

    const __half* gA = A  + (long)bz * sA + row0 * ldA;
    const __half* gB = Bm + (long)bz * sB + col0 * ldB;

    float acc[4][4][4];
#pragma unroll
    for (int t = 0; t < 4; t++)
#pragma unroll
        for (int j = 0; j < 4; j++)
#pragma unroll
            for (int e = 0; e < 4; e++) acc[t][j][e] = 0.f;

    int a_row  = wm * 64 + (lane & 15);
    int a_ch   = (lane >> 4) * 8;
    int b_row4 = wn * 32 + (lane & 7) + ((lane >> 4) << 3);  // ldm4 covers 2 j's
    int b_ch4  = ((lane >> 3) & 1) * 8;

    int NC = K >> 6;                          // BK = 64
    // prologue: stages 0,1
#pragma unroll
    for (int s = 0; s < NSTAGE - 1; s++) {
        if (s < NC) {
            load_stage(sb + s * STAGEB, gA, ldA, gB, ldB, s * 64);
            cp_commit();
        }
    }

    for (int c = 0; c < NC; c++) {
        if (c + 1 < NC) cp_wait1(); else cp_wait0();
        __syncthreads();
        if (c + 2 < NC) {
            load_stage(sb + ((c + 2) % NSTAGE) * STAGEB,
                       gA, ldA, gB, ldB, (c + 2) * 64);
            cp_commit();
        }

        uint32_t s0 = sb + (c % NSTAGE) * STAGEB;
#pragma unroll
        for (int kk = 0; kk < 64; kk += 16) {
            uint32_t ar[4][4];
#pragma unroll
            for (int t = 0; t < 4; t++)
                ldm4(ar[t], s0 + (a_row + t * 16) * PITCH + (a_ch + kk) * 2);
            uint32_t br[4][2];
#pragma unroll
            for (int j2 = 0; j2 < 2; j2++) {
                uint32_t r4[4];
                ldm4(r4, s0 + ATILEB + (b_row4 + j2 * 16) * PITCH + (b_ch4 + kk) * 2);
                br[j2 * 2 + 0][0] = r4[0]; br[j2 * 2 + 0][1] = r4[1];
                br[j2 * 2 + 1][0] = r4[2]; br[j2 * 2 + 1][1] = r4[3];
            }
#pragma unroll
            for (int t = 0; t < 4; t++)
#pragma unroll
                for (int j = 0; j < 4; j++)
                    mma16816(acc[t][j], ar[t], br[j]);
        }
    }

    // epilogue from registers, fused ops
#pragma unroll
    for (int t = 0; t < 4; t++)
#pragma unroll
        for (int j = 0; j < 4; j++) {
#pragma unroll
            for (int half = 0; half < 2; half++) {
                long r  = row0 + wm * 64 + t * 16 + (lane >> 2) + half * 8;
                long cc = col0 + wn * 32 + j * 8 + (lane & 3) * 2;
                float v0 = acc[t][j][half * 2 + 0] * alpha;
                float v1 = acc[t][j][half * 2 + 1] * alpha;
                if (BIASM == 1) { v0 += bias[cc]; v1 += bias[cc + 1]; }
                if (BIASM == 2) { float bb = bias[r]; v0 += bb; v1 += bb; }
                if (DOGELU) {
                    v0 = 0.5f * v0 * (1.f + erff(v0 * 0.70710678118654752f));
                    v1 = 0.5f * v1 * (1.f + erff(v1 * 0.70710678118654752f));
                }
                long off = (long)bz * sC + r * ldC + cc;
                if (DORES) {
                    float2 rv = *reinterpret_cast<const float2*>(res + off);
                    v0 += rv.x; v1 += rv.y;
                }
                if (OUTK == 0) {
                    *reinterpret_cast<float2*>(Cf + off) = make_float2(v0, v1);
                } else {
                    *reinterpret_cast<uint32_t*>(Ch + off) =
                        pack2h(__float2half(v0), __float2half(v1));
                }
            }
        }
}

// ---------------------------------------------------------------------------
// Transpose + convert, 4 weights (768x768 each) in one launch via blockIdx.z
// ---------------------------------------------------------------------------
__global__ void __launch_bounds__(256)
tconv4_kernel(const float* __restrict__ s0, const float* __restrict__ s1,
              const float* __restrict__ s2, const float* __restrict__ s3,
              __half* __restrict__ d0, __half* __restrict__ d1,
              __half* __restrict__ d2, __half* __restrict__ d3)
{
    int z = blockIdx.z;
    const float* W = (z == 0) ? s0 : (z == 1) ? s1 : (z == 2) ? s2 : s3;
    __half* o      = (z == 0) ? d0 : (z == 1) ? d1 : (z == 2) ? d2 : d3;
    __shared__ float t[32][33];
    int n0 = blockIdx.x * 32, k0 = blockIdx.y * 32;
    int tx = threadIdx.x & 31, ty = threadIdx.x >> 5;
#pragma unroll
    for (int i = 0; i < 32; i += 8)
        t[ty + i][tx] = W[(long)(k0 + ty + i) * D_ + n0 + tx];
    __syncthreads();
#pragma unroll
    for (int i = 0; i < 32; i += 8)
        o[(long)(n0 + ty + i) * D_ + k0 + tx] = __float2half(t[tx][ty + i]);
}

// Generic single transpose+convert: W[K,N] fp32 -> out[N,K] fp16
__global__ void __launch_bounds__(256)
tconv_kernel(const float* __restrict__ W, __half* __restrict__ o, int K, int N)
{
    __shared__ float t[32][33];
    int n0 = blockIdx.x * 32, k0 = blockIdx.y * 32;
    int tx = threadIdx.x & 31, ty = threadIdx.x >> 5;
#pragma unroll
    for (int i = 0; i < 32; i += 8)
        t[ty + i][tx] = W[(long)(k0 + ty + i) * N + n0 + tx];
    __syncthreads();
#pragma unroll
    for (int i = 0; i < 32; i += 8)
        o[(long)(n0 + ty + i) * K + k0 + tx] = __float2half(t[tx][ty + i]);
}

// concat bq|bk -> bqk[1536]
__global__ void __launch_bounds__(256)
concat2_kernel(const float* __restrict__ a, const float* __restrict__ b,
               float* __restrict__ o)
{
    int i = blockIdx.x * 256 + threadIdx.x;
    if (i < D_) o[i] = a[i];
    else if (i < 2 * D_) o[i] = b[i - D_];
}

// ---------------------------------------------------------------------------
// LayerNorm -> fp16
// ---------------------------------------------------------------------------
__global__ void __launch_bounds__(256)
ln_kernel(const float* __restrict__ x, const float* __restrict__ g,
          const float* __restrict__ b, __half* __restrict__ o)
{
    long row = blockIdx.x;
    const float* xr = x + row * D_;
    int t = threadIdx.x;
    float vals[3];
    float s = 0.f, s2 = 0.f;
#pragma unroll
    for (int i = 0; i < 3; i++) {
        float v = xr[t + i * 256];
        vals[i] = v; s += v; s2 += v * v;
    }
#pragma unroll
    for (int o2 = 16; o2 > 0; o2 >>= 1) {
        s  += __shfl_xor_sync(0xffffffffu, s,  o2);
        s2 += __shfl_xor_sync(0xffffffffu, s2, o2);
    }
    __shared__ float sm[8], sm2[8], stat[2];
    int w = t >> 5, l = t & 31;
    if (l == 0) { sm[w] = s; sm2[w] = s2; }
    __syncthreads();
    if (t == 0) {
        float a = 0.f, c = 0.f;
#pragma unroll
        for (int i = 0; i < 8; i++) { a += sm[i]; c += sm2[i]; }
        float mu = a / (float)D_;
        stat[0] = mu;
        stat[1] = rsqrtf(c / (float)D_ - mu * mu + EPS_);
    }
    __syncthreads();
    float mu = stat[0], rstd = stat[1];
#pragma unroll
    for (int i = 0; i < 3; i++) {
        int idx = t + i * 256;
        o[row * D_ + idx] = __float2half((vals[i] - mu) * rstd * g[idx] + b[idx]);
    }
}

// ---------------------------------------------------------------------------
// Softmax over fp16 scores, in place (scale pre-applied in GEMM epilogue)
// ---------------------------------------------------------------------------
__global__ void __launch_bounds__(256)
softmax_kernel(__half* __restrict__ sc)
{
    long row = blockIdx.x;
    __half* p = sc + row * (long)S_;
    int t = threadIdx.x;
    float vals[8];
    float mx = -1e30f;
#pragma unroll
    for (int i = 0; i < 8; i++) {
        float v = __half2float(p[t + i * 256]);
        vals[i] = v; mx = fmaxf(mx, v);
    }
#pragma unroll
    for (int o = 16; o > 0; o >>= 1)
        mx = fmaxf(mx, __shfl_xor_sync(0xffffffffu, mx, o));
    __shared__ float sm[8], stat[1];
    int w = t >> 5, l = t & 31;
    if (l == 0) sm[w] = mx;
    __syncthreads();
    if (t == 0) {
        float m2 = sm[0];
#pragma unroll
        for (int i = 1; i < 8; i++) m2 = fmaxf(m2, sm[i]);
        stat[0] = m2;
    }
    __syncthreads();
    float rowmax = stat[0];
    float sum = 0.f;
#pragma unroll
    for (int i = 0; i < 8; i++) {
        float e = __expf(vals[i] - rowmax);
        vals[i] = e; sum += e;
    }
#pragma unroll
    for (int o = 16; o > 0; o >>= 1)
        sum += __shfl_xor_sync(0xffffffffu, sum, o);
    if (l == 0) sm[w] = sum;
    __syncthreads();
    if (t == 0) {
        float a = 0.f;
#pragma unroll
        for (int i = 0; i < 8; i++) a += sm[i];
        stat[0] = 1.f / a;
    }
    __syncthreads();
    float inv = stat[0];
#pragma unroll
    for (int i = 0; i < 8; i++)
        p[t + i * 256] = __float2half(vals[i] * inv);
}

// ---------------------------------------------------------------------------
// Launch
// ---------------------------------------------------------------------------
extern "C" void kernel_launch(void* const* d_in, const int* in_sizes, int n_in,
                              void* d_out, int out_size)
{
    const float* x     = (const float*)d_in[0];
    const float* ln1g  = (const float*)d_in[1];
    const float* ln1b  = (const float*)d_in[2];
    const float* ln2g  = (const float*)d_in[3];
    const float* ln2b  = (const float*)d_in[4];
    const float* Wq    = (const float*)d_in[5];
    const float* bq    = (const float*)d_in[6];
    const float* Wk    = (const float*)d_in[7];
    const float* bk    = (const float*)d_in[8];
    const float* Wv    = (const float*)d_in[9];
    const float* bv    = (const float*)d_in[10];
    const float* Wo    = (const float*)d_in[11];
    const float* bo    = (const float*)d_in[12];
    const float* Wfc   = (const float*)d_in[13];
    const float* bfc   = (const float*)d_in[14];
    const float* Wproj = (const float*)d_in[15];
    const float* bproj = (const float*)d_in[16];
    float* out = (float*)d_out;

    auto ga = [](const void* sym) { void* p; cudaGetSymbolAddress(&p, sym); return p; };
    __half *h   = (__half*)ga(g_h);
    __half *qk  = (__half*)ga(g_qk);
    __half *vt  = (__half*)ga(g_vt);
    __half *sch = (__half*)ga(g_sch);
    __half *y   = (__half*)ga(g_y);
    float  *x1  = (float*)ga(g_x1);
    __half *h2  = (__half*)ga(g_h2);
    __half *m   = (__half*)ga(g_m);
    __half *wqkt = (__half*)ga(g_wqkt);
    __half *wvt  = (__half*)ga(g_wvt);
    __half *wot  = (__half*)ga(g_wot);
    __half *wfct = (__half*)ga(g_wfct);
    __half *wpt  = (__half*)ga(g_wprojt);
    float  *bqk  = (float*)ga(g_bqk);

    cudaFuncSetAttribute(gemm_mma<1,0,0,1>, cudaFuncAttributeMaxDynamicSharedMemorySize, SMEM_GEMM);
    cudaFuncSetAttribute(gemm_mma<2,0,0,1>, cudaFuncAttributeMaxDynamicSharedMemorySize, SMEM_GEMM);
    cudaFuncSetAttribute(gemm_mma<0,0,0,1>, cudaFuncAttributeMaxDynamicSharedMemorySize, SMEM_GEMM);
    cudaFuncSetAttribute(gemm_mma<1,0,1,0>, cudaFuncAttributeMaxDynamicSharedMemorySize, SMEM_GEMM);
    cudaFuncSetAttribute(gemm_mma<1,1,0,1>, cudaFuncAttributeMaxDynamicSharedMemorySize, SMEM_GEMM);

    const long sQ  = (long)S_ * D_;
    const long sQK = (long)S_ * 2 * D_;
    const long sS  = (long)S_ * S_;

    // LN1
    ln_kernel<<<NT_, 256>>>(x, ln1g, ln1b, h);

    // transpose+convert Wq,Wk,Wv,Wo (one launch) + concat bias
    tconv4_kernel<<<dim3(24, 24, 4), 256>>>(Wq, Wk, Wv, Wo,
                                            wqkt, wqkt + D_ * D_, wvt, wot);
    concat2_kernel<<<6, 256>>>(bq, bk, bqk);

    // fused qk = h . [Wq|Wk]  -> g_qk [NT, 1536]
    gemm_mma<1,0,0,1><<<dim3(12, 64, 1), 512, SMEM_GEMM>>>(
        h, D_, 0, wqkt, D_, 0, nullptr, qk, 2 * D_, 0, bqk, nullptr, 1.f, D_);

    // v^T = Wv^T . h^T  ([768, 16384], row bias)
    gemm_mma<2,0,0,1><<<dim3(128, 3, 1), 512, SMEM_GEMM>>>(
        wvt, D_, 0, h, D_, 0, nullptr, vt, NT_, 0, bv, nullptr, 1.f, D_);

    // scores = (q . k^T) * 1/sqrt(D)  (batched, fp16 out, scale fused)
    gemm_mma<0,0,0,1><<<dim3(16, 8, B_), 512, SMEM_GEMM>>>(
        qk, 2 * D_, sQK, qk + D_, 2 * D_, sQK,
        nullptr, sch, S_, sS, nullptr, nullptr, 1.0f / sqrtf((float)D_), D_);

    // softmax in-place (fp16)
    softmax_kernel<<<B_ * S_, 256>>>(sch);

    // y = probs . v
    gemm_mma<0,0,0,1><<<dim3(6, 8, B_), 512, SMEM_GEMM>>>(
        sch, S_, sS, vt, NT_, S_, nullptr, y, D_, sQ, nullptr, nullptr, 1.f, S_);

    // x1 = x + y . Wo + bo
    gemm_mma<1,0,1,0><<<dim3(6, 64, 1), 512, SMEM_GEMM>>>(
        y, D_, 0, wot, D_, 0, x1, nullptr, D_, 0, bo, x, 1.f, D_);

    // LN2
    ln_kernel<<<NT_, 256>>>(x1, ln2g, ln2b, h2);

    // m = GELU(h2 . Wfc + bfc)
    tconv_kernel<<<dim3(96, 24), 256>>>(Wfc, wfct, D_, H_);
    gemm_mma<1,1,0,1><<<dim3(24, 64, 1), 512, SMEM_GEMM>>>(
        h2, D_, 0, wfct, D_, 0, nullptr, m, H_, 0, bfc, nullptr, 1.f, D_);

    // out = x1 + m . Wproj + bproj
    tconv_kernel<<<dim3(24, 96), 256>>>(Wproj, wpt, H_, D_);
    gemm_mma<1,0,1,0><<<dim3(6, 64, 1), 512, SMEM_GEMM>>>(
        m, H_, 0, wpt, H_, 0, out, nullptr, D_, 0, bproj, x1, 1.f, H_);
}

// round 11
// speedup vs baseline: 7.4839x; 1.0757x over previous
#include <cuda_runtime.h>
#include <cuda_fp16.h>
#include <math.h>
#include <stdint.h>

// Problem dims
#define B_   8
#define S_   2048
#define D_   768
#define H_   3072
#define NT_  (B_ * S_)         // 16384 tokens
#define EPS_ 1e-5f

// ---------------------------------------------------------------------------
// Scratch (device globals) — activations fp16
// ---------------------------------------------------------------------------
__device__ unsigned short g_h  [NT_ * D_];                // LN1 out
__device__ unsigned short g_qk [NT_ * 2 * D_];            // [NT, 1536]: q | k
__device__ unsigned short g_vt [NT_ * D_];                // [D, B*S]
__device__ unsigned short g_sch[(size_t)B_ * S_ * S_];    // fp16 scores -> probs (in-place)
__device__ unsigned short g_y  [NT_ * D_];
__device__ float          g_x1 [NT_ * D_];
__device__ unsigned short g_h2 [NT_ * D_];
__device__ unsigned short g_m  [(size_t)NT_ * H_];
// transposed weights [N,K] fp16
__device__ unsigned short g_wqkt[2 * D_ * D_];            // [1536, 768]
__device__ unsigned short g_wvt [D_ * D_];
__device__ unsigned short g_wot [D_ * D_];
__device__ unsigned short g_wfct[H_ * D_];
__device__ unsigned short g_wprojt[D_ * H_];
__device__ float          g_bqk[2 * D_];

// ---------------------------------------------------------------------------
// PTX helpers
// ---------------------------------------------------------------------------
__device__ __forceinline__ void cp16(uint32_t dst, const void* src) {
    asm volatile("cp.async.cg.shared.global [%0], [%1], 16;" :: "r"(dst), "l"(src));
}
__device__ __forceinline__ void cp_commit() { asm volatile("cp.async.commit_group;" ::: "memory"); }
__device__ __forceinline__ void cp_wait0()  { asm volatile("cp.async.wait_group 0;"  ::: "memory"); }
__device__ __forceinline__ void cp_wait1()  { asm volatile("cp.async.wait_group 1;"  ::: "memory"); }

__device__ __forceinline__ void ldm4(uint32_t (&r)[4], uint32_t addr) {
    asm volatile("ldmatrix.sync.aligned.m8n8.x4.shared.b16 {%0,%1,%2,%3}, [%4];"
                 : "=r"(r[0]), "=r"(r[1]), "=r"(r[2]), "=r"(r[3]) : "r"(addr));
}
__device__ __forceinline__ void mma16816(float (&c)[4], const uint32_t (&a)[4],
                                         const uint32_t (&b)[2]) {
    asm volatile("mma.sync.aligned.m16n8k16.row.col.f32.f16.f16.f32 "
                 "{%0,%1,%2,%3}, {%4,%5,%6,%7}, {%8,%9}, {%0,%1,%2,%3};"
                 : "+f"(c[0]), "+f"(c[1]), "+f"(c[2]), "+f"(c[3])
                 : "r"(a[0]), "r"(a[1]), "r"(a[2]), "r"(a[3]), "r"(b[0]), "r"(b[1]));
}
__device__ __forceinline__ uint32_t pack2h(__half a, __half b) {
    return ((uint32_t)__half_as_ushort(b) << 16) | __half_as_ushort(a);
}

// ---------------------------------------------------------------------------
// Tensor-core GEMM: C[M,N] = alpha * (sum_k A[M,K]*B[N,K]) (+bias)(+gelu)(+res)
// tile 128x128, BK=64, 256 threads (8 warps, 2x4), warp tile 64x32
// 2 CTAs per SM (occupancy covers barrier/latency stalls).
// 3-stage cp.async, one __syncthreads per 4 k16-steps.
// PITCH=144 (stride 9 x 16B) -> ldmatrix conflict-free for 64-elem rows.
// BIASM: 0 none, 1 col, 2 row.  OUTK: 0 fp32, 1 fp16
// ---------------------------------------------------------------------------
#define PITCH   144
#define ATILEB  (128 * PITCH)                 // 18432
#define BTILEB  (128 * PITCH)                 // 18432
#define STAGEB  (ATILEB + BTILEB)             // 36864
#define NSTAGE  3
#define SMEM_GEMM (NSTAGE * STAGEB)           // 110592  (x2 CTAs = 221184 <= 228KB)

__device__ __forceinline__ void load_stage(uint32_t so, const __half* gA,
                                           long ldA, const __half* gB,
                                           long ldB, int k0) {
    int tid = threadIdx.x;
#pragma unroll
    for (int i = 0; i < 4; i++) {            // A: 128 rows x 64 cols
        int idx = tid + i * 256;
        int row = idx >> 3, ch = idx & 7;
        cp16(so + row * PITCH + ch * 16, gA + (long)row * ldA + k0 + ch * 8);
    }
#pragma unroll
    for (int i = 0; i < 4; i++) {            // B: 128 rows x 64 cols
        int idx = tid + i * 256;
        int row = idx >> 3, ch = idx & 7;
        cp16(so + ATILEB + row * PITCH + ch * 16, gB + (long)row * ldB + k0 + ch * 8);
    }
}

template <int BIASM, int DOGELU, int DORES, int OUTK>
__global__ void __launch_bounds__(256, 2)
gemm_mma(const __half* __restrict__ A, long ldA, long sA,
         const __half* __restrict__ Bm, long ldB, long sB,
         float* __restrict__ Cf, __half* __restrict__ Ch,
         long ldC, long sC,
         const float* __restrict__ bias, const float* __restrict__ res,
         float alpha, int K)
{
    extern __shared__ char smem[];
    uint32_t sb = (uint32_t)__cvta_generic_to_shared(smem);
    int tid = threadIdx.x, lane = tid & 31, wid = tid >> 5;
    int wm = wid & 1, wn = wid >> 1;                 // 2 x 4 warp grid
    long row0 = (long)blockIdx.y * 128, col0 = (long)blockIdx.x * 128;
    int bz = blockIdx.z;

    const __half* gA = A  + (long)bz * sA + row0 * ldA;
    const __half* gB = Bm + (long)bz * sB + col0 * ldB;

    float acc[4][4][4];
#pragma unroll
    for (int t = 0; t < 4; t++)
#pragma unroll
        for (int j = 0; j < 4; j++)
#pragma unroll
            for (int e = 0; e < 4; e++) acc[t][j][e] = 0.f;

    int a_row  = wm * 64 + (lane & 15);
    int a_ch   = (lane >> 4) * 8;
    int b_row4 = wn * 32 + (lane & 7) + ((lane >> 4) << 3);  // ldm4 covers 2 j's
    int b_ch4  = ((lane >> 3) & 1) * 8;

    int NC = K >> 6;                          // BK = 64
#pragma unroll
    for (int s = 0; s < NSTAGE - 1; s++) {
        if (s < NC) {
            load_stage(sb + s * STAGEB, gA, ldA, gB, ldB, s * 64);
            cp_commit();
        }
    }

    for (int c = 0; c < NC; c++) {
        if (c + 1 < NC) cp_wait1(); else cp_wait0();
        __syncthreads();
        if (c + 2 < NC) {
            load_stage(sb + ((c + 2) % NSTAGE) * STAGEB,
                       gA, ldA, gB, ldB, (c + 2) * 64);
            cp_commit();
        }

        uint32_t s0 = sb + (c % NSTAGE) * STAGEB;
#pragma unroll
        for (int kk = 0; kk < 64; kk += 16) {
            uint32_t ar[4][4];
#pragma unroll
            for (int t = 0; t < 4; t++)
                ldm4(ar[t], s0 + (a_row + t * 16) * PITCH + (a_ch + kk) * 2);
            uint32_t br[4][2];
#pragma unroll
            for (int j2 = 0; j2 < 2; j2++) {
                uint32_t r4[4];
                ldm4(r4, s0 + ATILEB + (b_row4 + j2 * 16) * PITCH + (b_ch4 + kk) * 2);
                br[j2 * 2 + 0][0] = r4[0]; br[j2 * 2 + 0][1] = r4[1];
                br[j2 * 2 + 1][0] = r4[2]; br[j2 * 2 + 1][1] = r4[3];
            }
#pragma unroll
            for (int t = 0; t < 4; t++)
#pragma unroll
                for (int j = 0; j < 4; j++)
                    mma16816(acc[t][j], ar[t], br[j]);
        }
    }

    // epilogue from registers, fused ops
#pragma unroll
    for (int t = 0; t < 4; t++)
#pragma unroll
        for (int j = 0; j < 4; j++) {
#pragma unroll
            for (int half = 0; half < 2; half++) {
                long r  = row0 + wm * 64 + t * 16 + (lane >> 2) + half * 8;
                long cc = col0 + wn * 32 + j * 8 + (lane & 3) * 2;
                float v0 = acc[t][j][half * 2 + 0] * alpha;
                float v1 = acc[t][j][half * 2 + 1] * alpha;
                if (BIASM == 1) { v0 += bias[cc]; v1 += bias[cc + 1]; }
                if (BIASM == 2) { float bb = bias[r]; v0 += bb; v1 += bb; }
                if (DOGELU) {
                    v0 = 0.5f * v0 * (1.f + erff(v0 * 0.70710678118654752f));
                    v1 = 0.5f * v1 * (1.f + erff(v1 * 0.70710678118654752f));
                }
                long off = (long)bz * sC + r * ldC + cc;
                if (DORES) {
                    float2 rv = *reinterpret_cast<const float2*>(res + off);
                    v0 += rv.x; v1 += rv.y;
                }
                if (OUTK == 0) {
                    *reinterpret_cast<float2*>(Cf + off) = make_float2(v0, v1);
                } else {
                    *reinterpret_cast<uint32_t*>(Ch + off) =
                        pack2h(__float2half(v0), __float2half(v1));
                }
            }
        }
}

// ---------------------------------------------------------------------------
// Transpose + convert, 4 weights (768x768 each) in one launch via blockIdx.z
// ---------------------------------------------------------------------------
__global__ void __launch_bounds__(256)
tconv4_kernel(const float* __restrict__ s0, const float* __restrict__ s1,
              const float* __restrict__ s2, const float* __restrict__ s3,
              __half* __restrict__ d0, __half* __restrict__ d1,
              __half* __restrict__ d2, __half* __restrict__ d3)
{
    int z = blockIdx.z;
    const float* W = (z == 0) ? s0 : (z == 1) ? s1 : (z == 2) ? s2 : s3;
    __half* o      = (z == 0) ? d0 : (z == 1) ? d1 : (z == 2) ? d2 : d3;
    __shared__ float t[32][33];
    int n0 = blockIdx.x * 32, k0 = blockIdx.y * 32;
    int tx = threadIdx.x & 31, ty = threadIdx.x >> 5;
#pragma unroll
    for (int i = 0; i < 32; i += 8)
        t[ty + i][tx] = W[(long)(k0 + ty + i) * D_ + n0 + tx];
    __syncthreads();
#pragma unroll
    for (int i = 0; i < 32; i += 8)
        o[(long)(n0 + ty + i) * D_ + k0 + tx] = __float2half(t[tx][ty + i]);
}

// Generic single transpose+convert: W[K,N] fp32 -> out[N,K] fp16
__global__ void __launch_bounds__(256)
tconv_kernel(const float* __restrict__ W, __half* __restrict__ o, int K, int N)
{
    __shared__ float t[32][33];
    int n0 = blockIdx.x * 32, k0 = blockIdx.y * 32;
    int tx = threadIdx.x & 31, ty = threadIdx.x >> 5;
#pragma unroll
    for (int i = 0; i < 32; i += 8)
        t[ty + i][tx] = W[(long)(k0 + ty + i) * N + n0 + tx];
    __syncthreads();
#pragma unroll
    for (int i = 0; i < 32; i += 8)
        o[(long)(n0 + ty + i) * K + k0 + tx] = __float2half(t[tx][ty + i]);
}

// concat bq|bk -> bqk[1536]
__global__ void __launch_bounds__(256)
concat2_kernel(const float* __restrict__ a, const float* __restrict__ b,
               float* __restrict__ o)
{
    int i = blockIdx.x * 256 + threadIdx.x;
    if (i < D_) o[i] = a[i];
    else if (i < 2 * D_) o[i] = b[i - D_];
}

// ---------------------------------------------------------------------------
// LayerNorm -> fp16
// ---------------------------------------------------------------------------
__global__ void __launch_bounds__(256)
ln_kernel(const float* __restrict__ x, const float* __restrict__ g,
          const float* __restrict__ b, __half* __restrict__ o)
{
    long row = blockIdx.x;
    const float* xr = x + row * D_;
    int t = threadIdx.x;
    float vals[3];
    float s = 0.f, s2 = 0.f;
#pragma unroll
    for (int i = 0; i < 3; i++) {
        float v = xr[t + i * 256];
        vals[i] = v; s += v; s2 += v * v;
    }
#pragma unroll
    for (int o2 = 16; o2 > 0; o2 >>= 1) {
        s  += __shfl_xor_sync(0xffffffffu, s,  o2);
        s2 += __shfl_xor_sync(0xffffffffu, s2, o2);
    }
    __shared__ float sm[8], sm2[8], stat[2];
    int w = t >> 5, l = t & 31;
    if (l == 0) { sm[w] = s; sm2[w] = s2; }
    __syncthreads();
    if (t == 0) {
        float a = 0.f, c = 0.f;
#pragma unroll
        for (int i = 0; i < 8; i++) { a += sm[i]; c += sm2[i]; }
        float mu = a / (float)D_;
        stat[0] = mu;
        stat[1] = rsqrtf(c / (float)D_ - mu * mu + EPS_);
    }
    __syncthreads();
    float mu = stat[0], rstd = stat[1];
#pragma unroll
    for (int i = 0; i < 3; i++) {
        int idx = t + i * 256;
        o[row * D_ + idx] = __float2half((vals[i] - mu) * rstd * g[idx] + b[idx]);
    }
}

// ---------------------------------------------------------------------------
// Softmax over fp16 scores, in place (scale pre-applied in GEMM epilogue)
// ---------------------------------------------------------------------------
__global__ void __launch_bounds__(256)
softmax_kernel(__half* __restrict__ sc)
{
    long row = blockIdx.x;
    __half* p = sc + row * (long)S_;
    int t = threadIdx.x;
    float vals[8];
    float mx = -1e30f;
#pragma unroll
    for (int i = 0; i < 8; i++) {
        float v = __half2float(p[t + i * 256]);
        vals[i] = v; mx = fmaxf(mx, v);
    }
#pragma unroll
    for (int o = 16; o > 0; o >>= 1)
        mx = fmaxf(mx, __shfl_xor_sync(0xffffffffu, mx, o));
    __shared__ float sm[8], stat[1];
    int w = t >> 5, l = t & 31;
    if (l == 0) sm[w] = mx;
    __syncthreads();
    if (t == 0) {
        float m2 = sm[0];
#pragma unroll
        for (int i = 1; i < 8; i++) m2 = fmaxf(m2, sm[i]);
        stat[0] = m2;
    }
    __syncthreads();
    float rowmax = stat[0];
    float sum = 0.f;
#pragma unroll
    for (int i = 0; i < 8; i++) {
        float e = __expf(vals[i] - rowmax);
        vals[i] = e; sum += e;
    }
#pragma unroll
    for (int o = 16; o > 0; o >>= 1)
        sum += __shfl_xor_sync(0xffffffffu, sum, o);
    if (l == 0) sm[w] = sum;
    __syncthreads();
    if (t == 0) {
        float a = 0.f;
#pragma unroll
        for (int i = 0; i < 8; i++) a += sm[i];
        stat[0] = 1.f / a;
    }
    __syncthreads();
    float inv = stat[0];
#pragma unroll
    for (int i = 0; i < 8; i++)
        p[t + i * 256] = __float2half(vals[i] * inv);
}

// ---------------------------------------------------------------------------
// Launch
// ---------------------------------------------------------------------------
extern "C" void kernel_launch(void* const* d_in, const int* in_sizes, int n_in,
                              void* d_out, int out_size)
{
    const float* x     = (const float*)d_in[0];
    const float* ln1g  = (const float*)d_in[1];
    const float* ln1b  = (const float*)d_in[2];
    const float* ln2g  = (const float*)d_in[3];
    const float* ln2b  = (const float*)d_in[4];
    const float* Wq    = (const float*)d_in[5];
    const float* bq    = (const float*)d_in[6];
    const float* Wk    = (const float*)d_in[7];
    const float* bk    = (const float*)d_in[8];
    const float* Wv    = (const float*)d_in[9];
    const float* bv    = (const float*)d_in[10];
    const float* Wo    = (const float*)d_in[11];
    const float* bo    = (const float*)d_in[12];
    const float* Wfc   = (const float*)d_in[13];
    const float* bfc   = (const float*)d_in[14];
    const float* Wproj = (const float*)d_in[15];
    const float* bproj = (const float*)d_in[16];
    float* out = (float*)d_out;

    auto ga = [](const void* sym) { void* p; cudaGetSymbolAddress(&p, sym); return p; };
    __half *h   = (__half*)ga(g_h);
    __half *qk  = (__half*)ga(g_qk);
    __half *vt  = (__half*)ga(g_vt);
    __half *sch = (__half*)ga(g_sch);
    __half *y   = (__half*)ga(g_y);
    float  *x1  = (float*)ga(g_x1);
    __half *h2  = (__half*)ga(g_h2);
    __half *m   = (__half*)ga(g_m);
    __half *wqkt = (__half*)ga(g_wqkt);
    __half *wvt  = (__half*)ga(g_wvt);
    __half *wot  = (__half*)ga(g_wot);
    __half *wfct = (__half*)ga(g_wfct);
    __half *wpt  = (__half*)ga(g_wprojt);
    float  *bqk  = (float*)ga(g_bqk);

    cudaFuncSetAttribute(gemm_mma<1,0,0,1>, cudaFuncAttributeMaxDynamicSharedMemorySize, SMEM_GEMM);
    cudaFuncSetAttribute(gemm_mma<2,0,0,1>, cudaFuncAttributeMaxDynamicSharedMemorySize, SMEM_GEMM);
    cudaFuncSetAttribute(gemm_mma<0,0,0,1>, cudaFuncAttributeMaxDynamicSharedMemorySize, SMEM_GEMM);
    cudaFuncSetAttribute(gemm_mma<1,0,1,0>, cudaFuncAttributeMaxDynamicSharedMemorySize, SMEM_GEMM);
    cudaFuncSetAttribute(gemm_mma<1,1,0,1>, cudaFuncAttributeMaxDynamicSharedMemorySize, SMEM_GEMM);

    const long sQ  = (long)S_ * D_;
    const long sQK = (long)S_ * 2 * D_;
    const long sS  = (long)S_ * S_;

    // LN1
    ln_kernel<<<NT_, 256>>>(x, ln1g, ln1b, h);

    // transpose+convert Wq,Wk,Wv,Wo (one launch) + concat bias
    tconv4_kernel<<<dim3(24, 24, 4), 256>>>(Wq, Wk, Wv, Wo,
                                            wqkt, wqkt + D_ * D_, wvt, wot);
    concat2_kernel<<<6, 256>>>(bq, bk, bqk);

    // fused qk = h . [Wq|Wk]  -> g_qk [NT, 1536]
    gemm_mma<1,0,0,1><<<dim3(12, 128, 1), 256, SMEM_GEMM>>>(
        h, D_, 0, wqkt, D_, 0, nullptr, qk, 2 * D_, 0, bqk, nullptr, 1.f, D_);

    // v^T = Wv^T . h^T  ([768, 16384], row bias)
    gemm_mma<2,0,0,1><<<dim3(128, 6, 1), 256, SMEM_GEMM>>>(
        wvt, D_, 0, h, D_, 0, nullptr, vt, NT_, 0, bv, nullptr, 1.f, D_);

    // scores = (q . k^T) * 1/sqrt(D)  (batched, fp16 out, scale fused)
    gemm_mma<0,0,0,1><<<dim3(16, 16, B_), 256, SMEM_GEMM>>>(
        qk, 2 * D_, sQK, qk + D_, 2 * D_, sQK,
        nullptr, sch, S_, sS, nullptr, nullptr, 1.0f / sqrtf((float)D_), D_);

    // softmax in-place (fp16)
    softmax_kernel<<<B_ * S_, 256>>>(sch);

    // y = probs . v
    gemm_mma<0,0,0,1><<<dim3(6, 16, B_), 256, SMEM_GEMM>>>(
        sch, S_, sS, vt, NT_, S_, nullptr, y, D_, sQ, nullptr, nullptr, 1.f, S_);

    // x1 = x + y . Wo + bo
    gemm_mma<1,0,1,0><<<dim3(6, 128, 1), 256, SMEM_GEMM>>>(
        y, D_, 0, wot, D_, 0, x1, nullptr, D_, 0, bo, x, 1.f, D_);

    // LN2
    ln_kernel<<<NT_, 256>>>(x1, ln2g, ln2b, h2);

    // m = GELU(h2 . Wfc + bfc)
    tconv_kernel<<<dim3(96, 24), 256>>>(Wfc, wfct, D_, H_);
    gemm_mma<1,1,0,1><<<dim3(24, 128, 1), 256, SMEM_GEMM>>>(
        h2, D_, 0, wfct, D_, 0, nullptr, m, H_, 0, bfc, nullptr, 1.f, D_);

    // out = x1 + m . Wproj + bproj
    tconv_kernel<<<dim3(24, 96), 256>>>(Wproj, wpt, H_, D_);
    gemm_mma<1,0,1,0><<<dim3(6, 128, 1), 256, SMEM_GEMM>>>(
        m, H_, 0, wpt, H_, 0, out, nullptr, D_, 0, bproj, x1, 1.f, H_);
}

// round 12
// speedup vs baseline: 7.4915x; 1.0010x over previous
#include <cuda_runtime.h>
#include <cuda_fp16.h>
#include <math.h>
#include <stdint.h>

// Problem dims
#define B_   8
#define S_   2048
#define D_   768
#define H_   3072
#define NT_  (B_ * S_)         // 16384 tokens
#define EPS_ 1e-5f

// ---------------------------------------------------------------------------
// Scratch (device globals) — activations fp16
// ---------------------------------------------------------------------------
__device__ unsigned short g_h  [NT_ * D_];                // LN1 out
__device__ unsigned short g_qk [NT_ * 2 * D_];            // [NT, 1536]: q | k
__device__ unsigned short g_vt [NT_ * D_];                // [D, B*S]
__device__ unsigned short g_sch[(size_t)B_ * S_ * S_];    // fp16 scores -> probs (in-place)
__device__ unsigned short g_y  [NT_ * D_];
__device__ float          g_x1 [NT_ * D_];
__device__ unsigned short g_h2 [NT_ * D_];
__device__ unsigned short g_m  [(size_t)NT_ * H_];
// transposed weights [N,K] fp16
__device__ unsigned short g_wqkt[2 * D_ * D_];            // [1536, 768]
__device__ unsigned short g_wvt [D_ * D_];
__device__ unsigned short g_wot [D_ * D_];
__device__ unsigned short g_wfct[H_ * D_];
__device__ unsigned short g_wprojt[D_ * H_];
__device__ float          g_bqk[2 * D_];

// ---------------------------------------------------------------------------
// PTX helpers
// ---------------------------------------------------------------------------
__device__ __forceinline__ void cp16(uint32_t dst, const void* src) {
    asm volatile("cp.async.cg.shared.global [%0], [%1], 16;" :: "r"(dst), "l"(src));
}
__device__ __forceinline__ void cp_commit() { asm volatile("cp.async.commit_group;" ::: "memory"); }
__device__ __forceinline__ void cp_wait0()  { asm volatile("cp.async.wait_group 0;"  ::: "memory"); }
__device__ __forceinline__ void cp_wait1()  { asm volatile("cp.async.wait_group 1;"  ::: "memory"); }

__device__ __forceinline__ void ldm4(uint32_t (&r)[4], uint32_t addr) {
    asm volatile("ldmatrix.sync.aligned.m8n8.x4.shared.b16 {%0,%1,%2,%3}, [%4];"
                 : "=r"(r[0]), "=r"(r[1]), "=r"(r[2]), "=r"(r[3]) : "r"(addr));
}
__device__ __forceinline__ void mma16816(float (&c)[4], const uint32_t (&a)[4],
                                         const uint32_t (&b)[2]) {
    asm volatile("mma.sync.aligned.m16n8k16.row.col.f32.f16.f16.f32 "
                 "{%0,%1,%2,%3}, {%4,%5,%6,%7}, {%8,%9}, {%0,%1,%2,%3};"
                 : "+f"(c[0]), "+f"(c[1]), "+f"(c[2]), "+f"(c[3])
                 : "r"(a[0]), "r"(a[1]), "r"(a[2]), "r"(a[3]), "r"(b[0]), "r"(b[1]));
}
__device__ __forceinline__ uint32_t pack2h(__half a, __half b) {
    return ((uint32_t)__half_as_ushort(b) << 16) | __half_as_ushort(a);
}

// ---------------------------------------------------------------------------
// Tensor-core GEMM: C[M,N] = alpha * (sum_k A[M,K]*B[N,K]) (+bias)(+gelu)(+res)
// tile 128x128, BK=64, 256 threads (8 warps, 2x4), warp tile 64x32
// 2 CTAs per SM (occupancy covers barrier/latency stalls).
// 3-stage cp.async, one __syncthreads per 4 k16-steps.
// PITCH=144 (stride 9 x 16B) -> ldmatrix conflict-free for 64-elem rows.
// BIASM: 0 none, 1 col, 2 row.  OUTK: 0 fp32, 1 fp16
// ---------------------------------------------------------------------------
#define PITCH   144
#define ATILEB  (128 * PITCH)                 // 18432
#define BTILEB  (128 * PITCH)                 // 18432
#define STAGEB  (ATILEB + BTILEB)             // 36864
#define NSTAGE  3
#define SMEM_GEMM (NSTAGE * STAGEB)           // 110592  (x2 CTAs = 221184 <= 228KB)

__device__ __forceinline__ void load_stage(uint32_t so, const __half* gA,
                                           long ldA, const __half* gB,
                                           long ldB, int k0) {
    int tid = threadIdx.x;
#pragma unroll
    for (int i = 0; i < 4; i++) {            // A: 128 rows x 64 cols
        int idx = tid + i * 256;
        int row = idx >> 3, ch = idx & 7;
        cp16(so + row * PITCH + ch * 16, gA + (long)row * ldA + k0 + ch * 8);
    }
#pragma unroll
    for (int i = 0; i < 4; i++) {            // B: 128 rows x 64 cols
        int idx = tid + i * 256;
        int row = idx >> 3, ch = idx & 7;
        cp16(so + ATILEB + row * PITCH + ch * 16, gB + (long)row * ldB + k0 + ch * 8);
    }
}

template <int BIASM, int DOGELU, int DORES, int OUTK>
__global__ void __launch_bounds__(256, 2)
gemm_mma(const __half* __restrict__ A, long ldA, long sA,
         const __half* __restrict__ Bm, long ldB, long sB,
         float* __restrict__ Cf, __half* __restrict__ Ch,
         long ldC, long sC,
         const float* __restrict__ bias, const float* __restrict__ res,
         float alpha, int K)
{
    extern __shared__ char smem[];
    uint32_t sb = (uint32_t)__cvta_generic_to_shared(smem);
    int tid = threadIdx.x, lane = tid & 31, wid = tid >> 5;
    int wm = wid & 1, wn = wid >> 1;                 // 2 x 4 warp grid
    long row0 = (long)blockIdx.y * 128, col0 = (long)blockIdx.x * 128;
    int bz = blockIdx.z;

    const __half* gA = A  + (long)bz * sA + row0 * ldA;
    const __half* gB = Bm + (long)bz * sB + col0 * ldB;

    float acc[4][4][4];
#pragma unroll
    for (int t = 0; t < 4; t++)
#pragma unroll
        for (int j = 0; j < 4; j++)
#pragma unroll
            for (int e = 0; e < 4; e++) acc[t][j][e] = 0.f;

    int a_row  = wm * 64 + (lane & 15);
    int a_ch   = (lane >> 4) * 8;
    int b_row4 = wn * 32 + (lane & 7) + ((lane >> 4) << 3);  // ldm4 covers 2 j's
    int b_ch4  = ((lane >> 3) & 1) * 8;

    int NC = K >> 6;                          // BK = 64
#pragma unroll
    for (int s = 0; s < NSTAGE - 1; s++) {
        if (s < NC) {
            load_stage(sb + s * STAGEB, gA, ldA, gB, ldB, s * 64);
            cp_commit();
        }
    }

    for (int c = 0; c < NC; c++) {
        if (c + 1 < NC) cp_wait1(); else cp_wait0();
        __syncthreads();
        if (c + 2 < NC) {
            load_stage(sb + ((c + 2) % NSTAGE) * STAGEB,
                       gA, ldA, gB, ldB, (c + 2) * 64);
            cp_commit();
        }

        uint32_t s0 = sb + (c % NSTAGE) * STAGEB;
#pragma unroll
        for (int kk = 0; kk < 64; kk += 16) {
            uint32_t ar[4][4];
#pragma unroll
            for (int t = 0; t < 4; t++)
                ldm4(ar[t], s0 + (a_row + t * 16) * PITCH + (a_ch + kk) * 2);
            uint32_t br[4][2];
#pragma unroll
            for (int j2 = 0; j2 < 2; j2++) {
                uint32_t r4[4];
                ldm4(r4, s0 + ATILEB + (b_row4 + j2 * 16) * PITCH + (b_ch4 + kk) * 2);
                br[j2 * 2 + 0][0] = r4[0]; br[j2 * 2 + 0][1] = r4[1];
                br[j2 * 2 + 1][0] = r4[2]; br[j2 * 2 + 1][1] = r4[3];
            }
#pragma unroll
            for (int t = 0; t < 4; t++)
#pragma unroll
                for (int j = 0; j < 4; j++)
                    mma16816(acc[t][j], ar[t], br[j]);
        }
    }

    // epilogue from registers, fused ops
#pragma unroll
    for (int t = 0; t < 4; t++)
#pragma unroll
        for (int j = 0; j < 4; j++) {
#pragma unroll
            for (int half = 0; half < 2; half++) {
                long r  = row0 + wm * 64 + t * 16 + (lane >> 2) + half * 8;
                long cc = col0 + wn * 32 + j * 8 + (lane & 3) * 2;
                float v0 = acc[t][j][half * 2 + 0] * alpha;
                float v1 = acc[t][j][half * 2 + 1] * alpha;
                if (BIASM == 1) { v0 += bias[cc]; v1 += bias[cc + 1]; }
                if (BIASM == 2) { float bb = bias[r]; v0 += bb; v1 += bb; }
                if (DOGELU) {
                    v0 = 0.5f * v0 * (1.f + erff(v0 * 0.70710678118654752f));
                    v1 = 0.5f * v1 * (1.f + erff(v1 * 0.70710678118654752f));
                }
                long off = (long)bz * sC + r * ldC + cc;
                if (DORES) {
                    float2 rv = *reinterpret_cast<const float2*>(res + off);
                    v0 += rv.x; v1 += rv.y;
                }
                if (OUTK == 0) {
                    *reinterpret_cast<float2*>(Cf + off) = make_float2(v0, v1);
                } else {
                    *reinterpret_cast<uint32_t*>(Ch + off) =
                        pack2h(__float2half(v0), __float2half(v1));
                }
            }
        }
}

// ---------------------------------------------------------------------------
// Transpose + convert, 4 weights (768x768 each) in one launch via blockIdx.z
// ---------------------------------------------------------------------------
__global__ void __launch_bounds__(256)
tconv4_kernel(const float* __restrict__ s0, const float* __restrict__ s1,
              const float* __restrict__ s2, const float* __restrict__ s3,
              __half* __restrict__ d0, __half* __restrict__ d1,
              __half* __restrict__ d2, __half* __restrict__ d3)
{
    int z = blockIdx.z;
    const float* W = (z == 0) ? s0 : (z == 1) ? s1 : (z == 2) ? s2 : s3;
    __half* o      = (z == 0) ? d0 : (z == 1) ? d1 : (z == 2) ? d2 : d3;
    __shared__ float t[32][33];
    int n0 = blockIdx.x * 32, k0 = blockIdx.y * 32;
    int tx = threadIdx.x & 31, ty = threadIdx.x >> 5;
#pragma unroll
    for (int i = 0; i < 32; i += 8)
        t[ty + i][tx] = W[(long)(k0 + ty + i) * D_ + n0 + tx];
    __syncthreads();
#pragma unroll
    for (int i = 0; i < 32; i += 8)
        o[(long)(n0 + ty + i) * D_ + k0 + tx] = __float2half(t[tx][ty + i]);
}

// Generic single transpose+convert: W[K,N] fp32 -> out[N,K] fp16
__global__ void __launch_bounds__(256)
tconv_kernel(const float* __restrict__ W, __half* __restrict__ o, int K, int N)
{
    __shared__ float t[32][33];
    int n0 = blockIdx.x * 32, k0 = blockIdx.y * 32;
    int tx = threadIdx.x & 31, ty = threadIdx.x >> 5;
#pragma unroll
    for (int i = 0; i < 32; i += 8)
        t[ty + i][tx] = W[(long)(k0 + ty + i) * N + n0 + tx];
    __syncthreads();
#pragma unroll
    for (int i = 0; i < 32; i += 8)
        o[(long)(n0 + ty + i) * K + k0 + tx] = __float2half(t[tx][ty + i]);
}

// concat bq|bk -> bqk[1536]
__global__ void __launch_bounds__(256)
concat2_kernel(const float* __restrict__ a, const float* __restrict__ b,
               float* __restrict__ o)
{
    int i = blockIdx.x * 256 + threadIdx.x;
    if (i < D_) o[i] = a[i];
    else if (i < 2 * D_) o[i] = b[i - D_];
}

// ---------------------------------------------------------------------------
// LayerNorm -> fp16
// ---------------------------------------------------------------------------
__global__ void __launch_bounds__(256)
ln_kernel(const float* __restrict__ x, const float* __restrict__ g,
          const float* __restrict__ b, __half* __restrict__ o)
{
    long row = blockIdx.x;
    const float* xr = x + row * D_;
    int t = threadIdx.x;
    float vals[3];
    float s = 0.f, s2 = 0.f;
#pragma unroll
    for (int i = 0; i < 3; i++) {
        float v = xr[t + i * 256];
        vals[i] = v; s += v; s2 += v * v;
    }
#pragma unroll
    for (int o2 = 16; o2 > 0; o2 >>= 1) {
        s  += __shfl_xor_sync(0xffffffffu, s,  o2);
        s2 += __shfl_xor_sync(0xffffffffu, s2, o2);
    }
    __shared__ float sm[8], sm2[8], stat[2];
    int w = t >> 5, l = t & 31;
    if (l == 0) { sm[w] = s; sm2[w] = s2; }
    __syncthreads();
    if (t == 0) {
        float a = 0.f, c = 0.f;
#pragma unroll
        for (int i = 0; i < 8; i++) { a += sm[i]; c += sm2[i]; }
        float mu = a / (float)D_;
        stat[0] = mu;
        stat[1] = rsqrtf(c / (float)D_ - mu * mu + EPS_);
    }
    __syncthreads();
    float mu = stat[0], rstd = stat[1];
#pragma unroll
    for (int i = 0; i < 3; i++) {
        int idx = t + i * 256;
        o[row * D_ + idx] = __float2half((vals[i] - mu) * rstd * g[idx] + b[idx]);
    }
}

// ---------------------------------------------------------------------------
// Softmax over fp16 scores, in place (scale pre-applied in GEMM epilogue)
// ---------------------------------------------------------------------------
__global__ void __launch_bounds__(256)
softmax_kernel(__half* __restrict__ sc)
{
    long row = blockIdx.x;
    __half* p = sc + row * (long)S_;
    int t = threadIdx.x;
    float vals[8];
    float mx = -1e30f;
#pragma unroll
    for (int i = 0; i < 8; i++) {
        float v = __half2float(p[t + i * 256]);
        vals[i] = v; mx = fmaxf(mx, v);
    }
#pragma unroll
    for (int o = 16; o > 0; o >>= 1)
        mx = fmaxf(mx, __shfl_xor_sync(0xffffffffu, mx, o));
    __shared__ float sm[8], stat[1];
    int w = t >> 5, l = t & 31;
    if (l == 0) sm[w] = mx;
    __syncthreads();
    if (t == 0) {
        float m2 = sm[0];
#pragma unroll
        for (int i = 1; i < 8; i++) m2 = fmaxf(m2, sm[i]);
        stat[0] = m2;
    }
    __syncthreads();
    float rowmax = stat[0];
    float sum = 0.f;
#pragma unroll
    for (int i = 0; i < 8; i++) {
        float e = __expf(vals[i] - rowmax);
        vals[i] = e; sum += e;
    }
#pragma unroll
    for (int o = 16; o > 0; o >>= 1)
        sum += __shfl_xor_sync(0xffffffffu, sum, o);
    if (l == 0) sm[w] = sum;
    __syncthreads();
    if (t == 0) {
        float a = 0.f;
#pragma unroll
        for (int i = 0; i < 8; i++) a += sm[i];
        stat[0] = 1.f / a;
    }
    __syncthreads();
    float inv = stat[0];
#pragma unroll
    for (int i = 0; i < 8; i++)
        p[t + i * 256] = __float2half(vals[i] * inv);
}

// ---------------------------------------------------------------------------
// Launch
// ---------------------------------------------------------------------------
extern "C" void kernel_launch(void* const* d_in, const int* in_sizes, int n_in,
                              void* d_out, int out_size)
{
    const float* x     = (const float*)d_in[0];
    const float* ln1g  = (const float*)d_in[1];
    const float* ln1b  = (const float*)d_in[2];
    const float* ln2g  = (const float*)d_in[3];
    const float* ln2b  = (const float*)d_in[4];
    const float* Wq    = (const float*)d_in[5];
    const float* bq    = (const float*)d_in[6];
    const float* Wk    = (const float*)d_in[7];
    const float* bk    = (const float*)d_in[8];
    const float* Wv    = (const float*)d_in[9];
    const float* bv    = (const float*)d_in[10];
    const float* Wo    = (const float*)d_in[11];
    const float* bo    = (const float*)d_in[12];
    const float* Wfc   = (const float*)d_in[13];
    const float* bfc   = (const float*)d_in[14];
    const float* Wproj = (const float*)d_in[15];
    const float* bproj = (const float*)d_in[16];
    float* out = (float*)d_out;

    auto ga = [](const void* sym) { void* p; cudaGetSymbolAddress(&p, sym); return p; };
    __half *h   = (__half*)ga(g_h);
    __half *qk  = (__half*)ga(g_qk);
    __half *vt  = (__half*)ga(g_vt);
    __half *sch = (__half*)ga(g_sch);
    __half *y   = (__half*)ga(g_y);
    float  *x1  = (float*)ga(g_x1);
    __half *h2  = (__half*)ga(g_h2);
    __half *m   = (__half*)ga(g_m);
    __half *wqkt = (__half*)ga(g_wqkt);
    __half *wvt  = (__half*)ga(g_wvt);
    __half *wot  = (__half*)ga(g_wot);
    __half *wfct = (__half*)ga(g_wfct);
    __half *wpt  = (__half*)ga(g_wprojt);
    float  *bqk  = (float*)ga(g_bqk);

    cudaFuncSetAttribute(gemm_mma<1,0,0,1>, cudaFuncAttributeMaxDynamicSharedMemorySize, SMEM_GEMM);
    cudaFuncSetAttribute(gemm_mma<2,0,0,1>, cudaFuncAttributeMaxDynamicSharedMemorySize, SMEM_GEMM);
    cudaFuncSetAttribute(gemm_mma<0,0,0,1>, cudaFuncAttributeMaxDynamicSharedMemorySize, SMEM_GEMM);
    cudaFuncSetAttribute(gemm_mma<1,0,1,0>, cudaFuncAttributeMaxDynamicSharedMemorySize, SMEM_GEMM);
    cudaFuncSetAttribute(gemm_mma<1,1,0,1>, cudaFuncAttributeMaxDynamicSharedMemorySize, SMEM_GEMM);

    const long sQ  = (long)S_ * D_;
    const long sQK = (long)S_ * 2 * D_;
    const long sS  = (long)S_ * S_;

    // LN1
    ln_kernel<<<NT_, 256>>>(x, ln1g, ln1b, h);

    // transpose+convert Wq,Wk,Wv,Wo (one launch) + concat bias
    tconv4_kernel<<<dim3(24, 24, 4), 256>>>(Wq, Wk, Wv, Wo,
                                            wqkt, wqkt + D_ * D_, wvt, wot);
    concat2_kernel<<<6, 256>>>(bq, bk, bqk);

    // fused qk = h . [Wq|Wk]  -> g_qk [NT, 1536]
    gemm_mma<1,0,0,1><<<dim3(12, 128, 1), 256, SMEM_GEMM>>>(
        h, D_, 0, wqkt, D_, 0, nullptr, qk, 2 * D_, 0, bqk, nullptr, 1.f, D_);

    // v^T = Wv^T . h^T  ([768, 16384], row bias)
    gemm_mma<2,0,0,1><<<dim3(128, 6, 1), 256, SMEM_GEMM>>>(
        wvt, D_, 0, h, D_, 0, nullptr, vt, NT_, 0, bv, nullptr, 1.f, D_);

    // scores = (q . k^T) * 1/sqrt(D)  (batched, fp16 out, scale fused)
    gemm_mma<0,0,0,1><<<dim3(16, 16, B_), 256, SMEM_GEMM>>>(
        qk, 2 * D_, sQK, qk + D_, 2 * D_, sQK,
        nullptr, sch, S_, sS, nullptr, nullptr, 1.0f / sqrtf((float)D_), D_);

    // softmax in-place (fp16)
    softmax_kernel<<<B_ * S_, 256>>>(sch);

    // y = probs . v
    gemm_mma<0,0,0,1><<<dim3(6, 16, B_), 256, SMEM_GEMM>>>(
        sch, S_, sS, vt, NT_, S_, nullptr, y, D_, sQ, nullptr, nullptr, 1.f, S_);

    // x1 = x + y . Wo + bo
    gemm_mma<1,0,1,0><<<dim3(6, 128, 1), 256, SMEM_GEMM>>>(
        y, D_, 0, wot, D_, 0, x1, nullptr, D_, 0, bo, x, 1.f, D_);

    // LN2
    ln_kernel<<<NT_, 256>>>(x1, ln2g, ln2b, h2);

    // m = GELU(h2 . Wfc + bfc)
    tconv_kernel<<<dim3(96, 24), 256>>>(Wfc, wfct, D_, H_);
    gemm_mma<1,1,0,1><<<dim3(24, 128, 1), 256, SMEM_GEMM>>>(
        h2, D_, 0, wfct, D_, 0, nullptr, m, H_, 0, bfc, nullptr, 1.f, D_);

    // out = x1 + m . Wproj + bproj
    tconv_kernel<<<dim3(24, 96), 256>>>(Wproj, wpt, H_, D_);
    gemm_mma<1,0,1,0><<<dim3(6, 128, 1), 256, SMEM_GEMM>>>(
        m, H_, 0, wpt, H_, 0, out, nullptr, D_, 0, bproj, x1, 1.f, H_);
}

// round 13
// speedup vs baseline: 8.1108x; 1.0827x over previous
#include <cuda_runtime.h>
#include <cuda_fp16.h>
#include <math.h>
#include <stdint.h>

// Problem dims
#define B_   8
#define S_   2048
#define D_   768
#define H_   3072
#define NT_  (B_ * S_)         // 16384 tokens
#define EPS_ 1e-5f

// ---------------------------------------------------------------------------
// Scratch (device globals) — activations fp16
// ---------------------------------------------------------------------------
__device__ unsigned short g_h  [NT_ * D_];                // LN1 out
__device__ unsigned short g_qk [NT_ * 2 * D_];            // [NT, 1536]: q | k
__device__ unsigned short g_vt [NT_ * D_];                // [D, B*S]
__device__ unsigned short g_sch[(size_t)B_ * S_ * S_];    // fp16 scores -> probs (in-place)
__device__ unsigned short g_y  [NT_ * D_];
__device__ float          g_x1 [NT_ * D_];
__device__ unsigned short g_h2 [NT_ * D_];
__device__ unsigned short g_m  [(size_t)NT_ * H_];
// transposed weights [N,K] fp16
__device__ unsigned short g_wqkt[2 * D_ * D_];            // [1536, 768]
__device__ unsigned short g_wvt [D_ * D_];
__device__ unsigned short g_wot [D_ * D_];
__device__ unsigned short g_wfct[H_ * D_];
__device__ unsigned short g_wprojt[D_ * H_];
__device__ float          g_bqk[2 * D_];

// ---------------------------------------------------------------------------
// PTX helpers
// ---------------------------------------------------------------------------
__device__ __forceinline__ void cp16(uint32_t dst, const void* src) {
    asm volatile("cp.async.cg.shared.global [%0], [%1], 16;" :: "r"(dst), "l"(src));
}
__device__ __forceinline__ void cp_commit() { asm volatile("cp.async.commit_group;" ::: "memory"); }
__device__ __forceinline__ void cp_wait0()  { asm volatile("cp.async.wait_group 0;"  ::: "memory"); }
__device__ __forceinline__ void cp_wait1()  { asm volatile("cp.async.wait_group 1;"  ::: "memory"); }

__device__ __forceinline__ void ldm4(uint32_t (&r)[4], uint32_t addr) {
    asm volatile("ldmatrix.sync.aligned.m8n8.x4.shared.b16 {%0,%1,%2,%3}, [%4];"
                 : "=r"(r[0]), "=r"(r[1]), "=r"(r[2]), "=r"(r[3]) : "r"(addr));
}
__device__ __forceinline__ void mma16816(float (&c)[4], const uint32_t (&a)[4],
                                         const uint32_t (&b)[2]) {
    asm volatile("mma.sync.aligned.m16n8k16.row.col.f32.f16.f16.f32 "
                 "{%0,%1,%2,%3}, {%4,%5,%6,%7}, {%8,%9}, {%0,%1,%2,%3};"
                 : "+f"(c[0]), "+f"(c[1]), "+f"(c[2]), "+f"(c[3])
                 : "r"(a[0]), "r"(a[1]), "r"(a[2]), "r"(a[3]), "r"(b[0]), "r"(b[1]));
}
__device__ __forceinline__ uint32_t pack2h(__half a, __half b) {
    return ((uint32_t)__half_as_ushort(b) << 16) | __half_as_ushort(a);
}

// ---------------------------------------------------------------------------
// Tensor-core GEMM: C[M,N] = alpha * (sum_k A[M,K]*B[N,K]) (+bias)(+gelu)(+res)
// tile 128x128, BK=64, 256 threads (8 warps, 2x4), warp tile 64x32
// 2 CTAs per SM.  3-stage cp.async, one __syncthreads per 4 k16-steps.
// Prefetch issued after first k16-step so MMA stream starts right at barrier.
// PITCH=144 (stride 9 x 16B) -> ldmatrix conflict-free.
// BIASM: 0 none, 1 col, 2 row.  OUTK: 0 fp32, 1 fp16
// ---------------------------------------------------------------------------
#define PITCH   144
#define ATILEB  (128 * PITCH)                 // 18432
#define BTILEB  (128 * PITCH)                 // 18432
#define STAGEB  (ATILEB + BTILEB)             // 36864
#define NSTAGE  3
#define SMEM_GEMM (NSTAGE * STAGEB)           // 110592  (x2 CTAs = 221184 <= 228KB)

__device__ __forceinline__ void load_stage(uint32_t so, const __half* gA,
                                           long ldA, const __half* gB,
                                           long ldB, int k0) {
    int tid = threadIdx.x;
#pragma unroll
    for (int i = 0; i < 4; i++) {            // A: 128 rows x 64 cols
        int idx = tid + i * 256;
        int row = idx >> 3, ch = idx & 7;
        cp16(so + row * PITCH + ch * 16, gA + (long)row * ldA + k0 + ch * 8);
    }
#pragma unroll
    for (int i = 0; i < 4; i++) {            // B: 128 rows x 64 cols
        int idx = tid + i * 256;
        int row = idx >> 3, ch = idx & 7;
        cp16(so + ATILEB + row * PITCH + ch * 16, gB + (long)row * ldB + k0 + ch * 8);
    }
}

template <int BIASM, int DOGELU, int DORES, int OUTK>
__global__ void __launch_bounds__(256, 2)
gemm_mma(const __half* __restrict__ A, long ldA, long sA,
         const __half* __restrict__ Bm, long ldB, long sB,
         float* __restrict__ Cf, __half* __restrict__ Ch,
         long ldC, long sC,
         const float* __restrict__ bias, const float* __restrict__ res,
         float alpha, int K)
{
    extern __shared__ char smem[];
    uint32_t sb = (uint32_t)__cvta_generic_to_shared(smem);
    int tid = threadIdx.x, lane = tid & 31, wid = tid >> 5;
    int wm = wid & 1, wn = wid >> 1;                 // 2 x 4 warp grid
    long row0 = (long)blockIdx.y * 128, col0 = (long)blockIdx.x * 128;
    int bz = blockIdx.z;

    const __half* gA = A  + (long)bz * sA + row0 * ldA;
    const __half* gB = Bm + (long)bz * sB + col0 * ldB;

    float acc[4][4][4];
#pragma unroll
    for (int t = 0; t < 4; t++)
#pragma unroll
        for (int j = 0; j < 4; j++)
#pragma unroll
            for (int e = 0; e < 4; e++) acc[t][j][e] = 0.f;

    int a_row  = wm * 64 + (lane & 15);
    int a_ch   = (lane >> 4) * 8;
    int b_row4 = wn * 32 + (lane & 7) + ((lane >> 4) << 3);  // ldm4 covers 2 j's
    int b_ch4  = ((lane >> 3) & 1) * 8;

    int NC = K >> 6;                          // BK = 64
#pragma unroll
    for (int s = 0; s < NSTAGE - 1; s++) {
        if (s < NC) {
            load_stage(sb + s * STAGEB, gA, ldA, gB, ldB, s * 64);
            cp_commit();
        }
    }

    for (int c = 0; c < NC; c++) {
        if (c + 1 < NC) cp_wait1(); else cp_wait0();
        __syncthreads();

        uint32_t s0 = sb + (c % NSTAGE) * STAGEB;

        // ---- k16-step 0 immediately (tensor pipe starts now) ----
        {
            uint32_t ar[4][4];
#pragma unroll
            for (int t = 0; t < 4; t++)
                ldm4(ar[t], s0 + (a_row + t * 16) * PITCH + a_ch * 2);
            uint32_t br[4][2];
#pragma unroll
            for (int j2 = 0; j2 < 2; j2++) {
                uint32_t r4[4];
                ldm4(r4, s0 + ATILEB + (b_row4 + j2 * 16) * PITCH + b_ch4 * 2);
                br[j2 * 2 + 0][0] = r4[0]; br[j2 * 2 + 0][1] = r4[1];
                br[j2 * 2 + 1][0] = r4[2]; br[j2 * 2 + 1][1] = r4[3];
            }
#pragma unroll
            for (int t = 0; t < 4; t++)
#pragma unroll
                for (int j = 0; j < 4; j++)
                    mma16816(acc[t][j], ar[t], br[j]);
        }

        // ---- prefetch stage c+2 (overlaps with remaining MMAs) ----
        if (c + 2 < NC) {
            load_stage(sb + ((c + 2) % NSTAGE) * STAGEB,
                       gA, ldA, gB, ldB, (c + 2) * 64);
            cp_commit();
        }

        // ---- k16-steps 1..3 ----
#pragma unroll
        for (int kk = 16; kk < 64; kk += 16) {
            uint32_t ar[4][4];
#pragma unroll
            for (int t = 0; t < 4; t++)
                ldm4(ar[t], s0 + (a_row + t * 16) * PITCH + (a_ch + kk) * 2);
            uint32_t br[4][2];
#pragma unroll
            for (int j2 = 0; j2 < 2; j2++) {
                uint32_t r4[4];
                ldm4(r4, s0 + ATILEB + (b_row4 + j2 * 16) * PITCH + (b_ch4 + kk) * 2);
                br[j2 * 2 + 0][0] = r4[0]; br[j2 * 2 + 0][1] = r4[1];
                br[j2 * 2 + 1][0] = r4[2]; br[j2 * 2 + 1][1] = r4[3];
            }
#pragma unroll
            for (int t = 0; t < 4; t++)
#pragma unroll
                for (int j = 0; j < 4; j++)
                    mma16816(acc[t][j], ar[t], br[j]);
        }
    }

    // epilogue from registers, fused ops
#pragma unroll
    for (int t = 0; t < 4; t++)
#pragma unroll
        for (int j = 0; j < 4; j++) {
#pragma unroll
            for (int half = 0; half < 2; half++) {
                long r  = row0 + wm * 64 + t * 16 + (lane >> 2) + half * 8;
                long cc = col0 + wn * 32 + j * 8 + (lane & 3) * 2;
                float v0 = acc[t][j][half * 2 + 0] * alpha;
                float v1 = acc[t][j][half * 2 + 1] * alpha;
                if (BIASM == 1) { v0 += bias[cc]; v1 += bias[cc + 1]; }
                if (BIASM == 2) { float bb = bias[r]; v0 += bb; v1 += bb; }
                if (DOGELU) {
                    v0 = 0.5f * v0 * (1.f + erff(v0 * 0.70710678118654752f));
                    v1 = 0.5f * v1 * (1.f + erff(v1 * 0.70710678118654752f));
                }
                long off = (long)bz * sC + r * ldC + cc;
                if (DORES) {
                    float2 rv = *reinterpret_cast<const float2*>(res + off);
                    v0 += rv.x; v1 += rv.y;
                }
                if (OUTK == 0) {
                    *reinterpret_cast<float2*>(Cf + off) = make_float2(v0, v1);
                } else {
                    *reinterpret_cast<uint32_t*>(Ch + off) =
                        pack2h(__float2half(v0), __float2half(v1));
                }
            }
        }
}

// ---------------------------------------------------------------------------
// Transpose + convert, 4 weights (768x768 each) in one launch via blockIdx.z
// ---------------------------------------------------------------------------
__global__ void __launch_bounds__(256)
tconv4_kernel(const float* __restrict__ s0, const float* __restrict__ s1,
              const float* __restrict__ s2, const float* __restrict__ s3,
              __half* __restrict__ d0, __half* __restrict__ d1,
              __half* __restrict__ d2, __half* __restrict__ d3)
{
    int z = blockIdx.z;
    const float* W = (z == 0) ? s0 : (z == 1) ? s1 : (z == 2) ? s2 : s3;
    __half* o      = (z == 0) ? d0 : (z == 1) ? d1 : (z == 2) ? d2 : d3;
    __shared__ float t[32][33];
    int n0 = blockIdx.x * 32, k0 = blockIdx.y * 32;
    int tx = threadIdx.x & 31, ty = threadIdx.x >> 5;
#pragma unroll
    for (int i = 0; i < 32; i += 8)
        t[ty + i][tx] = W[(long)(k0 + ty + i) * D_ + n0 + tx];
    __syncthreads();
#pragma unroll
    for (int i = 0; i < 32; i += 8)
        o[(long)(n0 + ty + i) * D_ + k0 + tx] = __float2half(t[tx][ty + i]);
}

// Generic single transpose+convert: W[K,N] fp32 -> out[N,K] fp16
__global__ void __launch_bounds__(256)
tconv_kernel(const float* __restrict__ W, __half* __restrict__ o, int K, int N)
{
    __shared__ float t[32][33];
    int n0 = blockIdx.x * 32, k0 = blockIdx.y * 32;
    int tx = threadIdx.x & 31, ty = threadIdx.x >> 5;
#pragma unroll
    for (int i = 0; i < 32; i += 8)
        t[ty + i][tx] = W[(long)(k0 + ty + i) * N + n0 + tx];
    __syncthreads();
#pragma unroll
    for (int i = 0; i < 32; i += 8)
        o[(long)(n0 + ty + i) * K + k0 + tx] = __float2half(t[tx][ty + i]);
}

// concat bq|bk -> bqk[1536]
__global__ void __launch_bounds__(256)
concat2_kernel(const float* __restrict__ a, const float* __restrict__ b,
               float* __restrict__ o)
{
    int i = blockIdx.x * 256 + threadIdx.x;
    if (i < D_) o[i] = a[i];
    else if (i < 2 * D_) o[i] = b[i - D_];
}

// ---------------------------------------------------------------------------
// LayerNorm -> fp16, vectorized: 192 threads/row, float4 loads, uint2 stores
// ---------------------------------------------------------------------------
__global__ void __launch_bounds__(192)
ln_kernel(const float* __restrict__ x, const float* __restrict__ g,
          const float* __restrict__ b, __half* __restrict__ o)
{
    long row = blockIdx.x;
    int t = threadIdx.x;
    float4 v4 = reinterpret_cast<const float4*>(x + row * D_)[t];
    float s  = v4.x + v4.y + v4.z + v4.w;
    float s2 = v4.x * v4.x + v4.y * v4.y + v4.z * v4.z + v4.w * v4.w;
#pragma unroll
    for (int o2 = 16; o2 > 0; o2 >>= 1) {
        s  += __shfl_xor_sync(0xffffffffu, s,  o2);
        s2 += __shfl_xor_sync(0xffffffffu, s2, o2);
    }
    __shared__ float sm[6], sm2[6], stat[2];
    int w = t >> 5, l = t & 31;
    if (l == 0) { sm[w] = s; sm2[w] = s2; }
    __syncthreads();
    if (t == 0) {
        float a = 0.f, c = 0.f;
#pragma unroll
        for (int i = 0; i < 6; i++) { a += sm[i]; c += sm2[i]; }
        float mu = a / (float)D_;
        stat[0] = mu;
        stat[1] = rsqrtf(c / (float)D_ - mu * mu + EPS_);
    }
    __syncthreads();
    float mu = stat[0], rstd = stat[1];
    float4 g4 = reinterpret_cast<const float4*>(g)[t];
    float4 b4 = reinterpret_cast<const float4*>(b)[t];
    uint2 outv;
    outv.x = pack2h(__float2half((v4.x - mu) * rstd * g4.x + b4.x),
                    __float2half((v4.y - mu) * rstd * g4.y + b4.y));
    outv.y = pack2h(__float2half((v4.z - mu) * rstd * g4.z + b4.z),
                    __float2half((v4.w - mu) * rstd * g4.w + b4.w));
    reinterpret_cast<uint2*>(o + row * D_)[t] = outv;
}

// ---------------------------------------------------------------------------
// Softmax over fp16 scores, in place, vectorized: 256 thr x uint4 (8 halves)
// ---------------------------------------------------------------------------
__global__ void __launch_bounds__(256)
softmax_kernel(__half* __restrict__ sc)
{
    long row = blockIdx.x;
    uint4* p4 = reinterpret_cast<uint4*>(sc + row * (long)S_);
    int t = threadIdx.x;
    uint4 pk = p4[t];
    __half2 hh[4];
    hh[0] = *reinterpret_cast<__half2*>(&pk.x);
    hh[1] = *reinterpret_cast<__half2*>(&pk.y);
    hh[2] = *reinterpret_cast<__half2*>(&pk.z);
    hh[3] = *reinterpret_cast<__half2*>(&pk.w);
    float vals[8];
    float mx = -1e30f;
#pragma unroll
    for (int i = 0; i < 4; i++) {
        float2 f2 = __half22float2(hh[i]);
        vals[i * 2 + 0] = f2.x; vals[i * 2 + 1] = f2.y;
        mx = fmaxf(mx, fmaxf(f2.x, f2.y));
    }
#pragma unroll
    for (int o = 16; o > 0; o >>= 1)
        mx = fmaxf(mx, __shfl_xor_sync(0xffffffffu, mx, o));
    __shared__ float sm[8], stat[1];
    int w = t >> 5, l = t & 31;
    if (l == 0) sm[w] = mx;
    __syncthreads();
    if (t == 0) {
        float m2 = sm[0];
#pragma unroll
        for (int i = 1; i < 8; i++) m2 = fmaxf(m2, sm[i]);
        stat[0] = m2;
    }
    __syncthreads();
    float rowmax = stat[0];
    float sum = 0.f;
#pragma unroll
    for (int i = 0; i < 8; i++) {
        float e = __expf(vals[i] - rowmax);
        vals[i] = e; sum += e;
    }
#pragma unroll
    for (int o = 16; o > 0; o >>= 1)
        sum += __shfl_xor_sync(0xffffffffu, sum, o);
    if (l == 0) sm[w] = sum;
    __syncthreads();
    if (t == 0) {
        float a = 0.f;
#pragma unroll
        for (int i = 0; i < 8; i++) a += sm[i];
        stat[0] = 1.f / a;
    }
    __syncthreads();
    float inv = stat[0];
    uint4 outp;
    outp.x = pack2h(__float2half(vals[0] * inv), __float2half(vals[1] * inv));
    outp.y = pack2h(__float2half(vals[2] * inv), __float2half(vals[3] * inv));
    outp.z = pack2h(__float2half(vals[4] * inv), __float2half(vals[5] * inv));
    outp.w = pack2h(__float2half(vals[6] * inv), __float2half(vals[7] * inv));
    p4[t] = outp;
}

// ---------------------------------------------------------------------------
// Launch
// ---------------------------------------------------------------------------
extern "C" void kernel_launch(void* const* d_in, const int* in_sizes, int n_in,
                              void* d_out, int out_size)
{
    const float* x     = (const float*)d_in[0];
    const float* ln1g  = (const float*)d_in[1];
    const float* ln1b  = (const float*)d_in[2];
    const float* ln2g  = (const float*)d_in[3];
    const float* ln2b  = (const float*)d_in[4];
    const float* Wq    = (const float*)d_in[5];
    const float* bq    = (const float*)d_in[6];
    const float* Wk    = (const float*)d_in[7];
    const float* bk    = (const float*)d_in[8];
    const float* Wv    = (const float*)d_in[9];
    const float* bv    = (const float*)d_in[10];
    const float* Wo    = (const float*)d_in[11];
    const float* bo    = (const float*)d_in[12];
    const float* Wfc   = (const float*)d_in[13];
    const float* bfc   = (const float*)d_in[14];
    const float* Wproj = (const float*)d_in[15];
    const float* bproj = (const float*)d_in[16];
    float* out = (float*)d_out;

    auto ga = [](const void* sym) { void* p; cudaGetSymbolAddress(&p, sym); return p; };
    __half *h   = (__half*)ga(g_h);
    __half *qk  = (__half*)ga(g_qk);
    __half *vt  = (__half*)ga(g_vt);
    __half *sch = (__half*)ga(g_sch);
    __half *y   = (__half*)ga(g_y);
    float  *x1  = (float*)ga(g_x1);
    __half *h2  = (__half*)ga(g_h2);
    __half *m   = (__half*)ga(g_m);
    __half *wqkt = (__half*)ga(g_wqkt);
    __half *wvt  = (__half*)ga(g_wvt);
    __half *wot  = (__half*)ga(g_wot);
    __half *wfct = (__half*)ga(g_wfct);
    __half *wpt  = (__half*)ga(g_wprojt);
    float  *bqk  = (float*)ga(g_bqk);

    cudaFuncSetAttribute(gemm_mma<1,0,0,1>, cudaFuncAttributeMaxDynamicSharedMemorySize, SMEM_GEMM);
    cudaFuncSetAttribute(gemm_mma<2,0,0,1>, cudaFuncAttributeMaxDynamicSharedMemorySize, SMEM_GEMM);
    cudaFuncSetAttribute(gemm_mma<0,0,0,1>, cudaFuncAttributeMaxDynamicSharedMemorySize, SMEM_GEMM);
    cudaFuncSetAttribute(gemm_mma<1,0,1,0>, cudaFuncAttributeMaxDynamicSharedMemorySize, SMEM_GEMM);
    cudaFuncSetAttribute(gemm_mma<1,1,0,1>, cudaFuncAttributeMaxDynamicSharedMemorySize, SMEM_GEMM);

    const long sQ  = (long)S_ * D_;
    const long sQK = (long)S_ * 2 * D_;
    const long sS  = (long)S_ * S_;

    // LN1
    ln_kernel<<<NT_, 192>>>(x, ln1g, ln1b, h);

    // transpose+convert Wq,Wk,Wv,Wo (one launch) + concat bias
    tconv4_kernel<<<dim3(24, 24, 4), 256>>>(Wq, Wk, Wv, Wo,
                                            wqkt, wqkt + D_ * D_, wvt, wot);
    concat2_kernel<<<6, 256>>>(bq, bk, bqk);

    // fused qk = h . [Wq|Wk]  -> g_qk [NT, 1536]
    gemm_mma<1,0,0,1><<<dim3(12, 128, 1), 256, SMEM_GEMM>>>(
        h, D_, 0, wqkt, D_, 0, nullptr, qk, 2 * D_, 0, bqk, nullptr, 1.f, D_);

    // v^T = Wv^T . h^T  ([768, 16384], row bias)
    gemm_mma<2,0,0,1><<<dim3(128, 6, 1), 256, SMEM_GEMM>>>(
        wvt, D_, 0, h, D_, 0, nullptr, vt, NT_, 0, bv, nullptr, 1.f, D_);

    // scores = (q . k^T) * 1/sqrt(D)  (batched, fp16 out, scale fused)
    gemm_mma<0,0,0,1><<<dim3(16, 16, B_), 256, SMEM_GEMM>>>(
        qk, 2 * D_, sQK, qk + D_, 2 * D_, sQK,
        nullptr, sch, S_, sS, nullptr, nullptr, 1.0f / sqrtf((float)D_), D_);

    // softmax in-place (fp16, vectorized)
    softmax_kernel<<<B_ * S_, 256>>>(sch);

    // y = probs . v
    gemm_mma<0,0,0,1><<<dim3(6, 16, B_), 256, SMEM_GEMM>>>(
        sch, S_, sS, vt, NT_, S_, nullptr, y, D_, sQ, nullptr, nullptr, 1.f, S_);

    // x1 = x + y . Wo + bo
    gemm_mma<1,0,1,0><<<dim3(6, 128, 1), 256, SMEM_GEMM>>>(
        y, D_, 0, wot, D_, 0, x1, nullptr, D_, 0, bo, x, 1.f, D_);

    // LN2
    ln_kernel<<<NT_, 192>>>(x1, ln2g, ln2b, h2);

    // m = GELU(h2 . Wfc + bfc)
    tconv_kernel<<<dim3(96, 24), 256>>>(Wfc, wfct, D_, H_);
    gemm_mma<1,1,0,1><<<dim3(24, 128, 1), 256, SMEM_GEMM>>>(
        h2, D_, 0, wfct, D_, 0, nullptr, m, H_, 0, bfc, nullptr, 1.f, D_);

    // out = x1 + m . Wproj + bproj
    tconv_kernel<<<dim3(24, 96), 256>>>(Wproj, wpt, H_, D_);
    gemm_mma<1,0,1,0><<<dim3(6, 128, 1), 256, SMEM_GEMM>>>(
        m, H_, 0, wpt, H_, 0, out, nullptr, D_, 0, bproj, x1, 1.f, H_);
}